// round 6
// baseline (speedup 1.0000x reference)
#include <cuda_runtime.h>
#include <cstdint>

#define BB 2
#define SS 2048
#define DD 1024
#define HH 16
#define DK 64
#define MM (BB*SS)

// ---------------- global scratch (device globals: allocation-free) ----------
__device__ uint32_t g_qin_hi[(size_t)MM*DD], g_qin_lo[(size_t)MM*DD];
__device__ uint32_t g_kin_hi[(size_t)MM*DD], g_kin_lo[(size_t)MM*DD];
__device__ uint32_t g_vin_hi[(size_t)MM*DD], g_vin_lo[(size_t)MM*DD];
__device__ uint32_t g_wq_hi[(size_t)DD*DD],  g_wq_lo[(size_t)DD*DD];
__device__ uint32_t g_wk_hi[(size_t)DD*DD],  g_wk_lo[(size_t)DD*DD];
__device__ uint32_t g_wv_hi[(size_t)DD*DD],  g_wv_lo[(size_t)DD*DD];
__device__ uint32_t g_wo_hi[(size_t)DD*DD],  g_wo_lo[(size_t)DD*DD];
__device__ uint32_t g_qh_hi[(size_t)MM*DD],  g_qh_lo[(size_t)MM*DD];
__device__ uint32_t g_kh_hi[(size_t)MM*DD],  g_kh_lo[(size_t)MM*DD];
__device__ uint32_t g_vh_hi[(size_t)MM*DD],  g_vh_lo[(size_t)MM*DD];
__device__ uint32_t g_oh_hi[(size_t)MM*DD],  g_oh_lo[(size_t)MM*DD];

// ---------------- tf32 helpers ----------------------------------------------
__device__ __forceinline__ uint32_t f2tf(float x){
    uint32_t r; asm("cvt.rna.tf32.f32 %0, %1;" : "=r"(r) : "f"(x)); return r;
}
__device__ __forceinline__ void split_tf(float x, uint32_t& hi, uint32_t& lo){
    hi = f2tf(x);
    lo = f2tf(x - __uint_as_float(hi));
}
__device__ __forceinline__ void mma8(float* d, const uint32_t* a, const uint32_t* b){
    asm volatile("mma.sync.aligned.m16n8k8.row.col.f32.tf32.tf32.f32 "
        "{%0,%1,%2,%3},{%4,%5,%6,%7},{%8,%9},{%0,%1,%2,%3};"
        : "+f"(d[0]),"+f"(d[1]),"+f"(d[2]),"+f"(d[3])
        : "r"(a[0]),"r"(a[1]),"r"(a[2]),"r"(a[3]),"r"(b[0]),"r"(b[1]));
}

// ---------------- pre-split kernel ------------------------------------------
__global__ void ksplit(const float* __restrict__ x, uint32_t* __restrict__ hi,
                       uint32_t* __restrict__ lo, int n)
{
    int i = (blockIdx.x*blockDim.x + threadIdx.x)*4;
    if (i >= n) return;
    float4 v = *(const float4*)(x + i);
    uint4 h4, l4;
    h4.x = f2tf(v.x); l4.x = f2tf(v.x - __uint_as_float(h4.x));
    h4.y = f2tf(v.y); l4.y = f2tf(v.y - __uint_as_float(h4.y));
    h4.z = f2tf(v.z); l4.z = f2tf(v.z - __uint_as_float(h4.z));
    h4.w = f2tf(v.w); l4.w = f2tf(v.w - __uint_as_float(h4.w));
    *(uint4*)(hi + i) = h4;
    *(uint4*)(lo + i) = l4;
}

// ---------------- projection GEMM (pre-split operands, pure LDS+MMA core) ---
// C[M,N] = A[M,K] * W[N,K]^T + bias.  Tile 128x64, BK=32, 256 thr, 8 warps.
// MODE 0: float row-major store.  MODE 1: split + scatter to (B,H,S,Dk).
#define PSTR 36
#define PROJ_SMEM ((2*128*PSTR + 2*64*PSTR) * 4)
template<int MODE>
__global__ __launch_bounds__(256)
void proj_tc(const uint32_t* __restrict__ Ahi_g, const uint32_t* __restrict__ Alo_g,
             const uint32_t* __restrict__ Whi_g, const uint32_t* __restrict__ Wlo_g,
             const float* __restrict__ bias, float* __restrict__ Cf,
             uint32_t* __restrict__ Chi, uint32_t* __restrict__ Clo)
{
    extern __shared__ uint32_t ps[];
    uint32_t* Ash = ps;                  // 128*PSTR
    uint32_t* Asl = Ash + 128*PSTR;
    uint32_t* Wsh = Asl + 128*PSTR;      // 64*PSTR
    uint32_t* Wsl = Wsh + 64*PSTR;

    const int bm = blockIdx.y*128, bn = blockIdx.x*64;
    const int t = threadIdx.x, wid = t>>5, lane = t&31;
    const int qr = lane>>2, qc = lane&3;
    const int wm = (wid&3)*32, wn = (wid>>2)*32;
    const int lr = t>>3, lc = (t&7)*4;

    float acc[2][4][4] = {};

    for (int kc = 0; kc < DD; kc += 32) {
        __syncthreads();
        #pragma unroll
        for (int p = 0; p < 4; p++) {
            int row = lr + 32*p;
            *(uint4*)(Ash + row*PSTR + lc) = *(const uint4*)(Ahi_g + (size_t)(bm+row)*DD + kc + lc);
            *(uint4*)(Asl + row*PSTR + lc) = *(const uint4*)(Alo_g + (size_t)(bm+row)*DD + kc + lc);
        }
        #pragma unroll
        for (int p = 0; p < 2; p++) {
            int row = lr + 32*p;
            *(uint4*)(Wsh + row*PSTR + lc) = *(const uint4*)(Whi_g + (size_t)(bn+row)*DD + kc + lc);
            *(uint4*)(Wsl + row*PSTR + lc) = *(const uint4*)(Wlo_g + (size_t)(bn+row)*DD + kc + lc);
        }
        __syncthreads();
        #pragma unroll
        for (int ks = 0; ks < 4; ks++) {
            int k0 = ks*8;
            uint32_t ah[2][4], al[2][4], bh[4][2], bl[4][2];
            #pragma unroll
            for (int mi = 0; mi < 2; mi++) {
                int r0 = wm + 16*mi + qr;
                ah[mi][0] = Ash[ r0   *PSTR + k0+qc  ];
                ah[mi][1] = Ash[(r0+8)*PSTR + k0+qc  ];
                ah[mi][2] = Ash[ r0   *PSTR + k0+qc+4];
                ah[mi][3] = Ash[(r0+8)*PSTR + k0+qc+4];
                al[mi][0] = Asl[ r0   *PSTR + k0+qc  ];
                al[mi][1] = Asl[(r0+8)*PSTR + k0+qc  ];
                al[mi][2] = Asl[ r0   *PSTR + k0+qc+4];
                al[mi][3] = Asl[(r0+8)*PSTR + k0+qc+4];
            }
            #pragma unroll
            for (int ni = 0; ni < 4; ni++) {
                int rn = wn + 8*ni + qr;
                bh[ni][0] = Wsh[rn*PSTR + k0+qc  ];
                bh[ni][1] = Wsh[rn*PSTR + k0+qc+4];
                bl[ni][0] = Wsl[rn*PSTR + k0+qc  ];
                bl[ni][1] = Wsl[rn*PSTR + k0+qc+4];
            }
            #pragma unroll
            for (int mi = 0; mi < 2; mi++)
                #pragma unroll
                for (int ni = 0; ni < 4; ni++) {
                    mma8(acc[mi][ni], ah[mi], bh[ni]);
                    mma8(acc[mi][ni], ah[mi], bl[ni]);
                    mma8(acc[mi][ni], al[mi], bh[ni]);
                }
        }
    }
    #pragma unroll
    for (int mi = 0; mi < 2; mi++) {
        int r0 = bm + wm + 16*mi + qr;
        #pragma unroll
        for (int ni = 0; ni < 4; ni++) {
            int c0 = bn + wn + 8*ni + 2*qc;
            #pragma unroll
            for (int e = 0; e < 4; e++) {
                int m = r0 + ((e>=2) ? 8 : 0);
                int n = c0 + (e&1);
                float val = acc[mi][ni][e] + bias[n];
                if (MODE == 0) {
                    Cf[(size_t)m*DD + n] = val;
                } else {
                    int b = m/SS, s = m%SS, h = n/DK, dk = n%DK;
                    size_t idx = (((size_t)b*HH+h)*SS+s)*DK+dk;
                    uint32_t h2, l2; split_tf(val, h2, l2);
                    Chi[idx] = h2; Clo[idx] = l2;
                }
            }
        }
    }
}

// ---------------- attention kernel (512 threads, pre-split K/V/Q) -----------
// Block = (b, h, 16 q rows). Full 16x2048 score row in smem -> exact softmax.
// Phase1: warp w (0..15) computes score cols [8w, 8w+8) of each 128-col chunk.
// Phase3: warp w handles dk cols [8*(w&7),+8), contraction half (w>>3); 2-way
//         partial reduce through smem.
#define SCP  2052
#define QSP  68
#define KVP2 68
#define ATTN_SMEM ((16*SCP + 2*16*QSP + 2*128*KVP2) * (int)sizeof(float))

__global__ __launch_bounds__(512)
void attn_tc(const uint32_t* __restrict__ qh_hi, const uint32_t* __restrict__ qh_lo,
             const uint32_t* __restrict__ kh_hi, const uint32_t* __restrict__ kh_lo,
             const uint32_t* __restrict__ vh_hi, const uint32_t* __restrict__ vh_lo,
             const int* __restrict__ mask, float* __restrict__ attn,
             uint32_t* __restrict__ o_hi, uint32_t* __restrict__ o_lo, int write_attn)
{
    extern __shared__ float smem[];
    float*    sc   = smem;                         // [16][SCP]
    uint32_t* Qhi  = (uint32_t*)(smem + 16*SCP);   // [16][QSP]
    uint32_t* Qlo  = Qhi + 16*QSP;                 // [16][QSP]
    uint32_t* KVhi = Qlo + 16*QSP;                 // [128][KVP2]
    uint32_t* KVlo = KVhi + 128*KVP2;              // [128][KVP2]

    const int qt = blockIdx.x, h = blockIdx.y, b = blockIdx.z;
    const int t = threadIdx.x, w = t>>5, lane = t&31;
    const int qr = lane>>2, qc = lane&3;

    const size_t hdbase = ((size_t)b*HH + h)*SS*DK;
    const uint32_t* khi_b = kh_hi + hdbase;
    const uint32_t* klo_b = kh_lo + hdbase;
    const uint32_t* vhi_b = vh_hi + hdbase;
    const uint32_t* vlo_b = vh_lo + hdbase;

    // ---- load Q tile (16x64) hi/lo ----
    {
        int tt = t & 255;
        int row = tt>>4, col = (tt&15)*4;
        const uint32_t* src = (t < 256) ? qh_hi : qh_lo;
        uint32_t*       dst = (t < 256) ? Qhi   : Qlo;
        uint4 v4 = *(const uint4*)(src + hdbase + (size_t)(qt*16 + row)*DK + col);
        *(uint4*)(dst + row*QSP + col) = v4;
    }
    __syncthreads();

    // Q fragments hoisted for whole phase 1
    uint32_t qhf[8][4], qlf[8][4];
    #pragma unroll
    for (int ks = 0; ks < 8; ks++) {
        int k0 = ks*8;
        qhf[ks][0] = Qhi[ qr   *QSP + k0+qc  ];
        qhf[ks][1] = Qhi[(qr+8)*QSP + k0+qc  ];
        qhf[ks][2] = Qhi[ qr   *QSP + k0+qc+4];
        qhf[ks][3] = Qhi[(qr+8)*QSP + k0+qc+4];
        qlf[ks][0] = Qlo[ qr   *QSP + k0+qc  ];
        qlf[ks][1] = Qlo[(qr+8)*QSP + k0+qc  ];
        qlf[ks][2] = Qlo[ qr   *QSP + k0+qc+4];
        qlf[ks][3] = Qlo[(qr+8)*QSP + k0+qc+4];
    }

    // ---- Phase 1: scores ----
    for (int kb = 0; kb < SS/128; kb++) {
        __syncthreads();
        #pragma unroll
        for (int p = 0; p < 4; p++) {
            int i = t + 512*p;               // 0..2047
            int row = i>>4, col = (i&15)*4;
            *(uint4*)(KVhi + row*KVP2 + col) = *(const uint4*)(khi_b + (size_t)(kb*128+row)*DK + col);
            *(uint4*)(KVlo + row*KVP2 + col) = *(const uint4*)(klo_b + (size_t)(kb*128+row)*DK + col);
        }
        __syncthreads();

        float acc[4] = {};
        #pragma unroll
        for (int ks = 0; ks < 8; ks++) {
            int k0 = ks*8;
            int rn = w*8 + qr;
            uint32_t bh[2], bl[2];
            bh[0] = KVhi[rn*KVP2 + k0+qc  ];
            bh[1] = KVhi[rn*KVP2 + k0+qc+4];
            bl[0] = KVlo[rn*KVP2 + k0+qc  ];
            bl[1] = KVlo[rn*KVP2 + k0+qc+4];
            mma8(acc, qhf[ks], bh);
            mma8(acc, qhf[ks], bl);
            mma8(acc, qlf[ks], bh);
        }
        int gc = kb*128 + w*8 + 2*qc;
        int m0 = mask[(size_t)b*SS + gc];
        int m1 = mask[(size_t)b*SS + gc + 1];
        sc[ qr   *SCP + gc  ] = m0 ? acc[0]*0.125f : -1e9f;
        sc[ qr   *SCP + gc+1] = m1 ? acc[1]*0.125f : -1e9f;
        sc[(qr+8)*SCP + gc  ] = m0 ? acc[2]*0.125f : -1e9f;
        sc[(qr+8)*SCP + gc+1] = m1 ? acc[3]*0.125f : -1e9f;
    }
    __syncthreads();

    // ---- Phase 2: exact softmax, one row per warp ----
    {
        float* row = sc + (size_t)w*SCP;
        float mx = -1e30f;
        #pragma unroll 8
        for (int i = 0; i < SS/32; i++) mx = fmaxf(mx, row[lane + 32*i]);
        #pragma unroll
        for (int off = 16; off > 0; off >>= 1)
            mx = fmaxf(mx, __shfl_xor_sync(0xffffffffu, mx, off));
        float sum = 0.f;
        #pragma unroll 8
        for (int i = 0; i < SS/32; i++) {
            float e = __expf(row[lane + 32*i] - mx);
            row[lane + 32*i] = e;
            sum += e;
        }
        #pragma unroll
        for (int off = 16; off > 0; off >>= 1)
            sum += __shfl_xor_sync(0xffffffffu, sum, off);
        float inv = 1.f / sum;
        size_t abase = (((size_t)b*HH + h)*SS + (size_t)(qt*16 + w)) * SS;
        if (write_attn) {
            #pragma unroll 8
            for (int i = 0; i < SS/32; i++) {
                float p = row[lane + 32*i] * inv;
                row[lane + 32*i] = p;
                attn[abase + lane + 32*i] = p;
            }
        } else {
            #pragma unroll 8
            for (int i = 0; i < SS/32; i++)
                row[lane + 32*i] *= inv;
        }
    }

    // ---- Phase 3: O = P @ V (split contraction between warp halves) ----
    const int p3 = w>>3, wn = w&7;
    float oacc[4] = {};
    for (int vb = 0; vb < SS/128; vb++) {
        __syncthreads();
        #pragma unroll
        for (int p = 0; p < 4; p++) {
            int i = t + 512*p;
            int row = i>>4, col = (i&15)*4;
            *(uint4*)(KVhi + row*KVP2 + col) = *(const uint4*)(vhi_b + (size_t)(vb*128+row)*DK + col);
            *(uint4*)(KVlo + row*KVP2 + col) = *(const uint4*)(vlo_b + (size_t)(vb*128+row)*DK + col);
        }
        __syncthreads();
        #pragma unroll
        for (int ks2 = 0; ks2 < 8; ks2++) {
            int ks = p3*8 + ks2;
            int gj = vb*128 + ks*8;
            uint32_t ph[4], pl[4], vh2[2], vl2[2];
            split_tf(sc[ qr   *SCP + gj+qc  ], ph[0], pl[0]);
            split_tf(sc[(qr+8)*SCP + gj+qc  ], ph[1], pl[1]);
            split_tf(sc[ qr   *SCP + gj+qc+4], ph[2], pl[2]);
            split_tf(sc[(qr+8)*SCP + gj+qc+4], ph[3], pl[3]);
            vh2[0] = KVhi[(ks*8+qc  )*KVP2 + 8*wn + qr];
            vh2[1] = KVhi[(ks*8+qc+4)*KVP2 + 8*wn + qr];
            vl2[0] = KVlo[(ks*8+qc  )*KVP2 + 8*wn + qr];
            vl2[1] = KVlo[(ks*8+qc+4)*KVP2 + 8*wn + qr];
            mma8(oacc, ph, vh2);
            mma8(oacc, ph, vl2);
            mma8(oacc, pl, vh2);
        }
    }

    // 2-way partial reduction through smem (reuse Q region, dead since phase 1)
    float* red = (float*)Qhi;            // [2][16][66] = 8448 B <= 8704 B
    red[p3*1056 +  qr   *66 + 8*wn + 2*qc    ] = oacc[0];
    red[p3*1056 +  qr   *66 + 8*wn + 2*qc + 1] = oacc[1];
    red[p3*1056 + (qr+8)*66 + 8*wn + 2*qc    ] = oacc[2];
    red[p3*1056 + (qr+8)*66 + 8*wn + 2*qc + 1] = oacc[3];
    __syncthreads();
    if (t < 256) {
        int row = t>>4, col = (t&15)*4;
        size_t orow = (size_t)b*SS + qt*16 + row;
        #pragma unroll
        for (int j = 0; j < 4; j++) {
            float v = red[row*66 + col + j] + red[1056 + row*66 + col + j];
            uint32_t h2, l2; split_tf(v, h2, l2);
            o_hi[orow*DD + h*DK + col + j] = h2;
            o_lo[orow*DD + h*DK + col + j] = l2;
        }
    }
}

// ---------------------------------------------------------------------------
extern "C" void kernel_launch(void* const* d_in, const int* in_sizes, int n_in,
                              void* d_out, int out_size)
{
    const float* q    = (const float*)d_in[0];
    const float* k    = (const float*)d_in[1];
    const float* v    = (const float*)d_in[2];
    const int*   mask = (const int*)  d_in[3];
    const float* wq_b = (const float*)d_in[5];
    const float* wk_b = (const float*)d_in[7];
    const float* wv_b = (const float*)d_in[9];
    const float* wo_b = (const float*)d_in[11];

    uint32_t *qin_hi,*qin_lo,*kin_hi,*kin_lo,*vin_hi,*vin_lo;
    uint32_t *wqh,*wql,*wkh,*wkl,*wvh,*wvl,*woh,*wol;
    uint32_t *qhh,*qhl,*khh,*khl,*vhh,*vhl,*ohh,*ohl;
    cudaGetSymbolAddress((void**)&qin_hi, g_qin_hi); cudaGetSymbolAddress((void**)&qin_lo, g_qin_lo);
    cudaGetSymbolAddress((void**)&kin_hi, g_kin_hi); cudaGetSymbolAddress((void**)&kin_lo, g_kin_lo);
    cudaGetSymbolAddress((void**)&vin_hi, g_vin_hi); cudaGetSymbolAddress((void**)&vin_lo, g_vin_lo);
    cudaGetSymbolAddress((void**)&wqh, g_wq_hi); cudaGetSymbolAddress((void**)&wql, g_wq_lo);
    cudaGetSymbolAddress((void**)&wkh, g_wk_hi); cudaGetSymbolAddress((void**)&wkl, g_wk_lo);
    cudaGetSymbolAddress((void**)&wvh, g_wv_hi); cudaGetSymbolAddress((void**)&wvl, g_wv_lo);
    cudaGetSymbolAddress((void**)&woh, g_wo_hi); cudaGetSymbolAddress((void**)&wol, g_wo_lo);
    cudaGetSymbolAddress((void**)&qhh, g_qh_hi); cudaGetSymbolAddress((void**)&qhl, g_qh_lo);
    cudaGetSymbolAddress((void**)&khh, g_kh_hi); cudaGetSymbolAddress((void**)&khl, g_kh_lo);
    cudaGetSymbolAddress((void**)&vhh, g_vh_hi); cudaGetSymbolAddress((void**)&vhl, g_vh_lo);
    cudaGetSymbolAddress((void**)&ohh, g_oh_hi); cudaGetSymbolAddress((void**)&ohl, g_oh_lo);

    const long OUT_E  = (long)BB*SS*DD;              // 4,194,304
    const long ATTN_E = (long)BB*HH*SS*(long)SS;     // 134,217,728
    float* out_ptr  = nullptr;
    float* attn_ptr = nullptr;
    if ((long)out_size >= OUT_E + ATTN_E) {
        out_ptr  = (float*)d_out;
        attn_ptr = (float*)d_out + OUT_E;
    } else if ((long)out_size >= ATTN_E) {
        attn_ptr = (float*)d_out;
    } else {
        out_ptr  = (float*)d_out;
    }

    // ---- pre-split inputs + weights ----
    const int NA = MM*DD, NW = DD*DD;
    ksplit<<<NA/1024, 256>>>(q, qin_hi, qin_lo, NA);
    ksplit<<<NA/1024, 256>>>(k, kin_hi, kin_lo, NA);
    ksplit<<<NA/1024, 256>>>(v, vin_hi, vin_lo, NA);
    ksplit<<<NW/1024, 256>>>((const float*)d_in[4],  wqh, wql, NW);
    ksplit<<<NW/1024, 256>>>((const float*)d_in[6],  wkh, wkl, NW);
    ksplit<<<NW/1024, 256>>>((const float*)d_in[8],  wvh, wvl, NW);
    ksplit<<<NW/1024, 256>>>((const float*)d_in[10], woh, wol, NW);

    // ---- projections ----
    cudaFuncSetAttribute(proj_tc<1>, cudaFuncAttributeMaxDynamicSharedMemorySize, PROJ_SMEM);
    cudaFuncSetAttribute(proj_tc<0>, cudaFuncAttributeMaxDynamicSharedMemorySize, PROJ_SMEM);
    dim3 pgrid(DD/64, MM/128);   // 16 x 32
    proj_tc<1><<<pgrid, 256, PROJ_SMEM>>>(qin_hi, qin_lo, wqh, wql, wq_b, nullptr, qhh, qhl);
    proj_tc<1><<<pgrid, 256, PROJ_SMEM>>>(kin_hi, kin_lo, wkh, wkl, wk_b, nullptr, khh, khl);
    proj_tc<1><<<pgrid, 256, PROJ_SMEM>>>(vin_hi, vin_lo, wvh, wvl, wv_b, nullptr, vhh, vhl);

    // ---- attention ----
    cudaFuncSetAttribute(attn_tc, cudaFuncAttributeMaxDynamicSharedMemorySize, ATTN_SMEM);
    attn_tc<<<dim3(SS/16, HH, BB), 512, ATTN_SMEM>>>(
        qhh, qhl, khh, khl, vhh, vhl, mask, attn_ptr, ohh, ohl,
        attn_ptr != nullptr ? 1 : 0);

    // ---- output projection ----
    if (out_ptr)
        proj_tc<0><<<pgrid, 256, PROJ_SMEM>>>(ohh, ohl, woh, wol, wo_b, out_ptr, nullptr, nullptr);
}

// round 8
// speedup vs baseline: 1.1815x; 1.1815x over previous
#include <cuda_runtime.h>
#include <cstdint>

#define BB 2
#define SS 2048
#define DD 1024
#define HH 16
#define DK 64
#define MM (BB*SS)

// Scratch (device globals: allocation-free per harness rules)
__device__ float g_qh[(size_t)BB*HH*SS*DK];
__device__ float g_kh[(size_t)BB*HH*SS*DK];
__device__ float g_vh[(size_t)BB*HH*SS*DK];
__device__ float g_o [(size_t)BB*SS*DD];

// ---------------------------------------------------------------------------
// tf32 helpers
// ---------------------------------------------------------------------------
__device__ __forceinline__ uint32_t f2tf(float x){
    uint32_t r; asm("cvt.rna.tf32.f32 %0, %1;" : "=r"(r) : "f"(x)); return r;
}
__device__ __forceinline__ void split_tf(float x, uint32_t& hi, uint32_t& lo){
    hi = f2tf(x);
    lo = f2tf(x - __uint_as_float(hi));
}
__device__ __forceinline__ void mma8(float* d, const uint32_t* a, const uint32_t* b){
    asm volatile("mma.sync.aligned.m16n8k8.row.col.f32.tf32.tf32.f32 "
        "{%0,%1,%2,%3},{%4,%5,%6,%7},{%8,%9},{%0,%1,%2,%3};"
        : "+f"(d[0]),"+f"(d[1]),"+f"(d[2]),"+f"(d[3])
        : "r"(a[0]),"r"(a[1]),"r"(a[2]),"r"(a[3]),"r"(b[0]),"r"(b[1]));
}

// FFMA-pipe exp: e^x via 2^(x*log2e), degree-5 poly, magic-constant round.
// Valid for x in [-80, 80]; rel err ~5e-7.
__device__ __forceinline__ float exp_poly(float x){
    float y = x * 1.4426950408889634f;
    float t = y + 12582912.0f;                       // round-to-nearest via magic
    int   n = __float_as_int(t) - 0x4B400000;        // integer part
    float f = y - (t - 12582912.0f);                 // frac in [-0.5, 0.5]
    float p =              1.33335581e-3f;
    p = fmaf(p, f, 9.61812910e-3f);
    p = fmaf(p, f, 5.55041087e-2f);
    p = fmaf(p, f, 2.40226507e-1f);
    p = fmaf(p, f, 6.93147180e-1f);
    p = fmaf(p, f, 1.0f);
    return __int_as_float(__float_as_int(p) + (n << 23));
}

// ---------------------------------------------------------------------------
// Projection GEMM: C[M,N] = A[M,K] * W[N,K]^T + bias
// Split-at-smem-store: loader converts float -> tf32 hi/lo once per element;
// inner loop is pure LDS + MMA (no cvt).
// Tile 128x64, BK=32, 256 threads (8 warps as 4(M) x 2(N)).
// MODE 0: float row-major store.  MODE 1: scatter float to (B,H,S,Dk).
// ---------------------------------------------------------------------------
#define PSTR 36
#define PROJ_SMEM ((2*128*PSTR + 2*64*PSTR) * 4)
template<int MODE>
__global__ __launch_bounds__(256)
void proj_tc(const float* __restrict__ A, const float* __restrict__ W,
             const float* __restrict__ bias, float* __restrict__ C)
{
    extern __shared__ uint32_t ps[];
    uint32_t* Ash = ps;                  // [128][PSTR]
    uint32_t* Asl = Ash + 128*PSTR;
    uint32_t* Wsh = Asl + 128*PSTR;      // [64][PSTR]
    uint32_t* Wsl = Wsh + 64*PSTR;

    const int bm = blockIdx.y*128, bn = blockIdx.x*64;
    const int t = threadIdx.x, wid = t>>5, lane = t&31;
    const int qr = lane>>2, qc = lane&3;
    const int wm = (wid&3)*32, wn = (wid>>2)*32;
    const int lr = t>>3, lc = (t&7)*4;

    float acc[2][4][4] = {};

    for (int kc = 0; kc < DD; kc += 32) {
        __syncthreads();
        #pragma unroll
        for (int p = 0; p < 4; p++) {
            int row = lr + 32*p;
            float4 v4 = *(const float4*)(A + (size_t)(bm+row)*DD + kc + lc);
            uint4 h4, l4;
            split_tf(v4.x, h4.x, l4.x); split_tf(v4.y, h4.y, l4.y);
            split_tf(v4.z, h4.z, l4.z); split_tf(v4.w, h4.w, l4.w);
            *(uint4*)(Ash + row*PSTR + lc) = h4;
            *(uint4*)(Asl + row*PSTR + lc) = l4;
        }
        #pragma unroll
        for (int p = 0; p < 2; p++) {
            int row = lr + 32*p;
            float4 v4 = *(const float4*)(W + (size_t)(bn+row)*DD + kc + lc);
            uint4 h4, l4;
            split_tf(v4.x, h4.x, l4.x); split_tf(v4.y, h4.y, l4.y);
            split_tf(v4.z, h4.z, l4.z); split_tf(v4.w, h4.w, l4.w);
            *(uint4*)(Wsh + row*PSTR + lc) = h4;
            *(uint4*)(Wsl + row*PSTR + lc) = l4;
        }
        __syncthreads();
        #pragma unroll
        for (int ks = 0; ks < 4; ks++) {
            int k0 = ks*8;
            uint32_t ah[2][4], al[2][4], bh[4][2], bl[4][2];
            #pragma unroll
            for (int mi = 0; mi < 2; mi++) {
                int r0 = wm + 16*mi + qr;
                ah[mi][0] = Ash[ r0   *PSTR + k0+qc  ];
                ah[mi][1] = Ash[(r0+8)*PSTR + k0+qc  ];
                ah[mi][2] = Ash[ r0   *PSTR + k0+qc+4];
                ah[mi][3] = Ash[(r0+8)*PSTR + k0+qc+4];
                al[mi][0] = Asl[ r0   *PSTR + k0+qc  ];
                al[mi][1] = Asl[(r0+8)*PSTR + k0+qc  ];
                al[mi][2] = Asl[ r0   *PSTR + k0+qc+4];
                al[mi][3] = Asl[(r0+8)*PSTR + k0+qc+4];
            }
            #pragma unroll
            for (int ni = 0; ni < 4; ni++) {
                int rn = wn + 8*ni + qr;
                bh[ni][0] = Wsh[rn*PSTR + k0+qc  ];
                bh[ni][1] = Wsh[rn*PSTR + k0+qc+4];
                bl[ni][0] = Wsl[rn*PSTR + k0+qc  ];
                bl[ni][1] = Wsl[rn*PSTR + k0+qc+4];
            }
            #pragma unroll
            for (int mi = 0; mi < 2; mi++)
                #pragma unroll
                for (int ni = 0; ni < 4; ni++) {
                    mma8(acc[mi][ni], ah[mi], bh[ni]);
                    mma8(acc[mi][ni], ah[mi], bl[ni]);
                    mma8(acc[mi][ni], al[mi], bh[ni]);
                }
        }
    }
    #pragma unroll
    for (int mi = 0; mi < 2; mi++) {
        int r0 = bm + wm + 16*mi + qr;
        #pragma unroll
        for (int ni = 0; ni < 4; ni++) {
            int c0 = bn + wn + 8*ni + 2*qc;
            #pragma unroll
            for (int e = 0; e < 4; e++) {
                int m = r0 + ((e>=2) ? 8 : 0);
                int n = c0 + (e&1);
                float val = acc[mi][ni][e] + bias[n];
                if (MODE == 0) {
                    C[(size_t)m*DD + n] = val;
                } else {
                    int b = m/SS, s = m%SS, h = n/DK, dk = n%DK;
                    C[(((size_t)b*HH+h)*SS+s)*DK+dk] = val;
                }
            }
        }
    }
}

// ---------------------------------------------------------------------------
// Attention (tensor cores, 3xTF32). Block = (b, h, 16 q rows), 256 threads.
// Full 16x2048 score row in smem -> exact softmax (clamped, no max pass).
// Softmax exp is hybrid: alternate MUFU __expf / FFMA exp_poly.
// ---------------------------------------------------------------------------
#define SCP  2052
#define QSP  68
#define KVP2 68
#define ATTN_SMEM ((16*SCP + 16*QSP + 128*KVP2) * (int)sizeof(float))

__global__ __launch_bounds__(256)
void attn_tc(const float* __restrict__ qh, const float* __restrict__ kh,
             const float* __restrict__ vh, const int* __restrict__ mask,
             float* __restrict__ attn, float* __restrict__ o, int write_attn)
{
    extern __shared__ float smem[];
    float* sc  = smem;                 // [16][SCP]
    float* Qs  = smem + 16*SCP;        // [16][QSP]
    float* KVs = Qs  + 16*QSP;         // [128][KVP2]

    const int qt = blockIdx.x, h = blockIdx.y, b = blockIdx.z;
    const int t = threadIdx.x, w = t>>5, lane = t&31;
    const int qr = lane>>2, qc = lane&3;

    const float* qbase = qh + (((size_t)b*HH+h)*SS + (size_t)qt*16)*DK;
    const float* kbase = kh + ((size_t)b*HH+h)*SS*DK;
    const float* vbase = vh + ((size_t)b*HH+h)*SS*DK;

    // load Q tile (16x64)
    {
        int row = t>>4, col = (t&15)*4;
        float4 v4 = *(const float4*)(qbase + (size_t)row*DK + col);
        *(float4*)&Qs[row*QSP + col] = v4;
    }
    __syncthreads();

    // Q fragments (8 k-steps), hoisted for whole phase 1
    uint32_t qhi_f[8][4], qlo_f[8][4];
    #pragma unroll
    for (int ks = 0; ks < 8; ks++) {
        int k0 = ks*8;
        split_tf(Qs[ qr   *QSP + k0+qc  ], qhi_f[ks][0], qlo_f[ks][0]);
        split_tf(Qs[(qr+8)*QSP + k0+qc  ], qhi_f[ks][1], qlo_f[ks][1]);
        split_tf(Qs[ qr   *QSP + k0+qc+4], qhi_f[ks][2], qlo_f[ks][2]);
        split_tf(Qs[(qr+8)*QSP + k0+qc+4], qhi_f[ks][3], qlo_f[ks][3]);
    }

    // ---- Phase 1: scores ----
    for (int kb = 0; kb < SS/128; kb++) {
        __syncthreads();
        {
            int j = t>>4, col = (t&15)*4;
            #pragma unroll
            for (int p = 0; p < 8; p++) {
                float4 v4 = *(const float4*)(kbase + (size_t)(kb*128 + j + 16*p)*DK + col);
                *(float4*)&KVs[(j+16*p)*KVP2 + col] = v4;
            }
        }
        __syncthreads();
        float acc[2][4] = {};
        #pragma unroll
        for (int ks = 0; ks < 8; ks++) {
            int k0 = ks*8;
            uint32_t bhf[2][2], blf[2][2];
            #pragma unroll
            for (int ni = 0; ni < 2; ni++) {
                int rn = w*16 + 8*ni + qr;
                split_tf(KVs[rn*KVP2 + k0+qc  ], bhf[ni][0], blf[ni][0]);
                split_tf(KVs[rn*KVP2 + k0+qc+4], bhf[ni][1], blf[ni][1]);
            }
            #pragma unroll
            for (int ni = 0; ni < 2; ni++) {
                mma8(acc[ni], qhi_f[ks], bhf[ni]);
                mma8(acc[ni], qhi_f[ks], blf[ni]);
                mma8(acc[ni], qlo_f[ks], bhf[ni]);
            }
        }
        #pragma unroll
        for (int ni = 0; ni < 2; ni++) {
            int gc = kb*128 + w*16 + 8*ni + 2*qc;
            int m0 = mask[(size_t)b*SS + gc];
            int m1 = mask[(size_t)b*SS + gc + 1];
            sc[ qr   *SCP + gc  ] = m0 ? acc[ni][0]*0.125f : -1e9f;
            sc[ qr   *SCP + gc+1] = m1 ? acc[ni][1]*0.125f : -1e9f;
            sc[(qr+8)*SCP + gc  ] = m0 ? acc[ni][2]*0.125f : -1e9f;
            sc[(qr+8)*SCP + gc+1] = m1 ? acc[ni][3]*0.125f : -1e9f;
        }
    }
    __syncthreads();

    // ---- Phase 2: softmax (clamped exp, hybrid MUFU/poly, 2 passes) ----
    for (int r = w*2; r < w*2 + 2; r++) {
        float* row = sc + (size_t)r*SCP;
        float sum = 0.f;
        #pragma unroll 4
        for (int i = 0; i < SS/32; i += 2) {
            float a = row[lane + 32*i];
            float c = row[lane + 32*(i+1)];
            a = fminf(fmaxf(a, -80.f), 80.f);
            c = fminf(fmaxf(c, -80.f), 80.f);
            float ea = __expf(a);     // MUFU pipe
            float ec = exp_poly(c);   // FMA/ALU pipes
            row[lane + 32*i]     = ea;
            row[lane + 32*(i+1)] = ec;
            sum += ea + ec;
        }
        #pragma unroll
        for (int off = 16; off > 0; off >>= 1)
            sum += __shfl_xor_sync(0xffffffffu, sum, off);
        float inv = 1.f / sum;
        size_t abase = (((size_t)b*HH + h)*SS + (size_t)(qt*16 + r)) * SS;
        if (write_attn) {
            #pragma unroll 8
            for (int i = 0; i < SS/32; i++) {
                float p = row[lane + 32*i] * inv;
                row[lane + 32*i] = p;
                attn[abase + lane + 32*i] = p;
            }
        } else {
            #pragma unroll 8
            for (int i = 0; i < SS/32; i++)
                row[lane + 32*i] *= inv;
        }
    }

    // ---- Phase 3: O = P @ V ----
    float oacc[4] = {};
    for (int vb = 0; vb < SS/128; vb++) {
        __syncthreads();
        {
            int j = t>>4, col = (t&15)*4;
            #pragma unroll
            for (int p = 0; p < 8; p++) {
                float4 v4 = *(const float4*)(vbase + (size_t)(vb*128 + j + 16*p)*DK + col);
                *(float4*)&KVs[(j+16*p)*KVP2 + col] = v4;
            }
        }
        __syncthreads();
        #pragma unroll
        for (int ks = 0; ks < 16; ks++) {
            int gj = vb*128 + ks*8;
            uint32_t ph[4], pl[4], vh2[2], vl2[2];
            split_tf(sc[ qr   *SCP + gj+qc  ], ph[0], pl[0]);
            split_tf(sc[(qr+8)*SCP + gj+qc  ], ph[1], pl[1]);
            split_tf(sc[ qr   *SCP + gj+qc+4], ph[2], pl[2]);
            split_tf(sc[(qr+8)*SCP + gj+qc+4], ph[3], pl[3]);
            split_tf(KVs[(ks*8+qc  )*KVP2 + 8*w + qr], vh2[0], vl2[0]);
            split_tf(KVs[(ks*8+qc+4)*KVP2 + 8*w + qr], vh2[1], vl2[1]);
            mma8(oacc, ph, vh2);
            mma8(oacc, ph, vl2);
            mma8(oacc, pl, vh2);
        }
    }
    {
        size_t r0 = (size_t)b*SS + qt*16 + qr;
        int c0 = h*DK + 8*w + 2*qc;
        o[ r0   *DD + c0  ] = oacc[0];
        o[ r0   *DD + c0+1] = oacc[1];
        o[(r0+8)*DD + c0  ] = oacc[2];
        o[(r0+8)*DD + c0+1] = oacc[3];
    }
}

// ---------------------------------------------------------------------------
extern "C" void kernel_launch(void* const* d_in, const int* in_sizes, int n_in,
                              void* d_out, int out_size)
{
    const float* q    = (const float*)d_in[0];
    const float* k    = (const float*)d_in[1];
    const float* v    = (const float*)d_in[2];
    const int*   mask = (const int*)  d_in[3];
    const float* wq_w = (const float*)d_in[4];
    const float* wq_b = (const float*)d_in[5];
    const float* wk_w = (const float*)d_in[6];
    const float* wk_b = (const float*)d_in[7];
    const float* wv_w = (const float*)d_in[8];
    const float* wv_b = (const float*)d_in[9];
    const float* wo_w = (const float*)d_in[10];
    const float* wo_b = (const float*)d_in[11];

    float *qh_p, *kh_p, *vh_p, *o_p;
    cudaGetSymbolAddress((void**)&qh_p, g_qh);
    cudaGetSymbolAddress((void**)&kh_p, g_kh);
    cudaGetSymbolAddress((void**)&vh_p, g_vh);
    cudaGetSymbolAddress((void**)&o_p,  g_o);

    const long OUT_E  = (long)BB*SS*DD;              // 4,194,304
    const long ATTN_E = (long)BB*HH*SS*(long)SS;     // 134,217,728
    float* out_ptr  = nullptr;
    float* attn_ptr = nullptr;
    if ((long)out_size >= OUT_E + ATTN_E) {
        out_ptr  = (float*)d_out;
        attn_ptr = (float*)d_out + OUT_E;
    } else if ((long)out_size >= ATTN_E) {
        attn_ptr = (float*)d_out;
    } else {
        out_ptr  = (float*)d_out;
    }

    cudaFuncSetAttribute(proj_tc<1>, cudaFuncAttributeMaxDynamicSharedMemorySize, PROJ_SMEM);
    cudaFuncSetAttribute(proj_tc<0>, cudaFuncAttributeMaxDynamicSharedMemorySize, PROJ_SMEM);
    dim3 pgrid(DD/64, MM/128);   // 16 x 32
    proj_tc<1><<<pgrid, 256, PROJ_SMEM>>>(q, wq_w, wq_b, qh_p);
    proj_tc<1><<<pgrid, 256, PROJ_SMEM>>>(k, wk_w, wk_b, kh_p);
    proj_tc<1><<<pgrid, 256, PROJ_SMEM>>>(v, wv_w, wv_b, vh_p);

    cudaFuncSetAttribute(attn_tc,
                         cudaFuncAttributeMaxDynamicSharedMemorySize, ATTN_SMEM);
    attn_tc<<<dim3(SS/16, HH, BB), 256, ATTN_SMEM>>>(
        qh_p, kh_p, vh_p, mask, attn_ptr, o_p, attn_ptr != nullptr ? 1 : 0);

    if (out_ptr)
        proj_tc<0><<<pgrid, 256, PROJ_SMEM>>>(o_p, wo_w, wo_b, out_ptr);
}

// round 9
// speedup vs baseline: 1.3313x; 1.1268x over previous
#include <cuda_runtime.h>
#include <cstdint>

#define BB 2
#define SS 2048
#define DD 1024
#define HH 16
#define DK 64
#define MM (BB*SS)

// Scratch (device globals: allocation-free per harness rules)
__device__ float g_qh [(size_t)BB*HH*SS*DK];
__device__ float g_kh [(size_t)BB*HH*SS*DK];
__device__ float g_vh [(size_t)BB*HH*SS*DK];
__device__ float g_o  [(size_t)BB*SS*DD];
__device__ float g_inv[(size_t)BB*HH*SS];

// ---------------------------------------------------------------------------
// tf32 helpers
// ---------------------------------------------------------------------------
__device__ __forceinline__ uint32_t f2tf(float x){
    uint32_t r; asm("cvt.rna.tf32.f32 %0, %1;" : "=r"(r) : "f"(x)); return r;
}
__device__ __forceinline__ void split_tf(float x, uint32_t& hi, uint32_t& lo){
    hi = f2tf(x);
    lo = f2tf(x - __uint_as_float(hi));
}
__device__ __forceinline__ void mma8(float* d, const uint32_t* a, const uint32_t* b){
    asm volatile("mma.sync.aligned.m16n8k8.row.col.f32.tf32.tf32.f32 "
        "{%0,%1,%2,%3},{%4,%5,%6,%7},{%8,%9},{%0,%1,%2,%3};"
        : "+f"(d[0]),"+f"(d[1]),"+f"(d[2]),"+f"(d[3])
        : "r"(a[0]),"r"(a[1]),"r"(a[2]),"r"(a[3]),"r"(b[0]),"r"(b[1]));
}

// FFMA-pipe exp: e^x via 2^(x*log2e), degree-5 poly. Valid |x|<=80, rel ~5e-7.
__device__ __forceinline__ float exp_poly(float x){
    float y = x * 1.4426950408889634f;
    float t = y + 12582912.0f;
    int   n = __float_as_int(t) - 0x4B400000;
    float f = y - (t - 12582912.0f);
    float p =              1.33335581e-3f;
    p = fmaf(p, f, 9.61812910e-3f);
    p = fmaf(p, f, 5.55041087e-2f);
    p = fmaf(p, f, 2.40226507e-1f);
    p = fmaf(p, f, 6.93147180e-1f);
    p = fmaf(p, f, 1.0f);
    return __int_as_float(__float_as_int(p) + (n << 23));
}

// ---------------------------------------------------------------------------
// Projection GEMM (unchanged from R7/R8 — split-at-smem-store, pure LDS+MMA).
// ---------------------------------------------------------------------------
#define PSTR 36
#define PROJ_SMEM ((2*128*PSTR + 2*64*PSTR) * 4)
template<int MODE>
__global__ __launch_bounds__(256)
void proj_tc(const float* __restrict__ A, const float* __restrict__ W,
             const float* __restrict__ bias, float* __restrict__ C)
{
    extern __shared__ uint32_t ps[];
    uint32_t* Ash = ps;
    uint32_t* Asl = Ash + 128*PSTR;
    uint32_t* Wsh = Asl + 128*PSTR;
    uint32_t* Wsl = Wsh + 64*PSTR;

    const int bm = blockIdx.y*128, bn = blockIdx.x*64;
    const int t = threadIdx.x, wid = t>>5, lane = t&31;
    const int qr = lane>>2, qc = lane&3;
    const int wm = (wid&3)*32, wn = (wid>>2)*32;
    const int lr = t>>3, lc = (t&7)*4;

    float acc[2][4][4] = {};

    for (int kc = 0; kc < DD; kc += 32) {
        __syncthreads();
        #pragma unroll
        for (int p = 0; p < 4; p++) {
            int row = lr + 32*p;
            float4 v4 = *(const float4*)(A + (size_t)(bm+row)*DD + kc + lc);
            uint4 h4, l4;
            split_tf(v4.x, h4.x, l4.x); split_tf(v4.y, h4.y, l4.y);
            split_tf(v4.z, h4.z, l4.z); split_tf(v4.w, h4.w, l4.w);
            *(uint4*)(Ash + row*PSTR + lc) = h4;
            *(uint4*)(Asl + row*PSTR + lc) = l4;
        }
        #pragma unroll
        for (int p = 0; p < 2; p++) {
            int row = lr + 32*p;
            float4 v4 = *(const float4*)(W + (size_t)(bn+row)*DD + kc + lc);
            uint4 h4, l4;
            split_tf(v4.x, h4.x, l4.x); split_tf(v4.y, h4.y, l4.y);
            split_tf(v4.z, h4.z, l4.z); split_tf(v4.w, h4.w, l4.w);
            *(uint4*)(Wsh + row*PSTR + lc) = h4;
            *(uint4*)(Wsl + row*PSTR + lc) = l4;
        }
        __syncthreads();
        #pragma unroll
        for (int ks = 0; ks < 4; ks++) {
            int k0 = ks*8;
            uint32_t ah[2][4], al[2][4], bh[4][2], bl[4][2];
            #pragma unroll
            for (int mi = 0; mi < 2; mi++) {
                int r0 = wm + 16*mi + qr;
                ah[mi][0] = Ash[ r0   *PSTR + k0+qc  ];
                ah[mi][1] = Ash[(r0+8)*PSTR + k0+qc  ];
                ah[mi][2] = Ash[ r0   *PSTR + k0+qc+4];
                ah[mi][3] = Ash[(r0+8)*PSTR + k0+qc+4];
                al[mi][0] = Asl[ r0   *PSTR + k0+qc  ];
                al[mi][1] = Asl[(r0+8)*PSTR + k0+qc  ];
                al[mi][2] = Asl[ r0   *PSTR + k0+qc+4];
                al[mi][3] = Asl[(r0+8)*PSTR + k0+qc+4];
            }
            #pragma unroll
            for (int ni = 0; ni < 4; ni++) {
                int rn = wn + 8*ni + qr;
                bh[ni][0] = Wsh[rn*PSTR + k0+qc  ];
                bh[ni][1] = Wsh[rn*PSTR + k0+qc+4];
                bl[ni][0] = Wsl[rn*PSTR + k0+qc  ];
                bl[ni][1] = Wsl[rn*PSTR + k0+qc+4];
            }
            #pragma unroll
            for (int mi = 0; mi < 2; mi++)
                #pragma unroll
                for (int ni = 0; ni < 4; ni++) {
                    mma8(acc[mi][ni], ah[mi], bh[ni]);
                    mma8(acc[mi][ni], ah[mi], bl[ni]);
                    mma8(acc[mi][ni], al[mi], bh[ni]);
                }
        }
    }
    #pragma unroll
    for (int mi = 0; mi < 2; mi++) {
        int r0 = bm + wm + 16*mi + qr;
        #pragma unroll
        for (int ni = 0; ni < 4; ni++) {
            int c0 = bn + wn + 8*ni + 2*qc;
            #pragma unroll
            for (int e = 0; e < 4; e++) {
                int m = r0 + ((e>=2) ? 8 : 0);
                int n = c0 + (e&1);
                float val = acc[mi][ni][e] + bias[n];
                if (MODE == 0) {
                    C[(size_t)m*DD + n] = val;
                } else {
                    int b = m/SS, s = m%SS, h = n/DK, dk = n%DK;
                    C[(((size_t)b*HH+h)*SS+s)*DK+dk] = val;
                }
            }
        }
    }
}

// ---------------------------------------------------------------------------
// Fused attention: per-chunk scores -> exp -> (dump unnormalized exp) -> P@V.
// Block = (b,h,16 q rows), 256 threads, 8 warps.
// Warp w: score cols [w*16,w*16+16) of chunk; PV dk cols [8w,8w+8).
// O normalized in-kernel; attn probs normalized by attn_scale kernel.
// smem ~61KB -> 3 CTAs/SM.
// ---------------------------------------------------------------------------
#define KVP2 68
#define PCH  132
#define QSP  68
#define ATTN_SMEM ((128*KVP2 + 2*16*PCH + 2*16*QSP + 16*8 + 16) * (int)sizeof(float))

__global__ __launch_bounds__(256, 3)
void attn_fused(const float* __restrict__ qh, const float* __restrict__ kh,
                const float* __restrict__ vh, const int* __restrict__ mask,
                float* __restrict__ attn, float* __restrict__ o,
                float* __restrict__ inv_g, int write_attn)
{
    extern __shared__ float smem[];
    float*    KVs  = smem;                           // [128][KVP2]
    uint32_t* Phi  = (uint32_t*)(smem + 128*KVP2);   // [16][PCH]
    uint32_t* Plo  = Phi + 16*PCH;                   // [16][PCH]
    uint32_t* Qhi  = Plo + 16*PCH;                   // [16][QSP]
    uint32_t* Qlo  = Qhi + 16*QSP;                   // [16][QSP]
    float*    red  = (float*)(Qlo + 16*QSP);         // [16][8]
    float*    invs = red + 16*8;                     // [16]

    const int qt = blockIdx.x, h = blockIdx.y, b = blockIdx.z;
    const int t = threadIdx.x, w = t>>5, lane = t&31;
    const int qr = lane>>2, qc = lane&3;

    const float* qbase = qh + (((size_t)b*HH+h)*SS + (size_t)qt*16)*DK;
    const float* kbase = kh + ((size_t)b*HH+h)*SS*DK;
    const float* vbase = vh + ((size_t)b*HH+h)*SS*DK;

    // load + split Q tile (16x64)
    {
        int row = t>>4, col = (t&15)*4;
        float4 v4 = *(const float4*)(qbase + (size_t)row*DK + col);
        uint4 h4, l4;
        split_tf(v4.x, h4.x, l4.x); split_tf(v4.y, h4.y, l4.y);
        split_tf(v4.z, h4.z, l4.z); split_tf(v4.w, h4.w, l4.w);
        *(uint4*)(Qhi + row*QSP + col) = h4;
        *(uint4*)(Qlo + row*QSP + col) = l4;
    }

    float sum0 = 0.f, sum1 = 0.f;
    float oacc[4] = {};

    const int ldr = t>>4, ldc = (t&15)*4;   // K/V tile loader coords

    for (int kb = 0; kb < SS/128; kb++) {
        __syncthreads();   // prev chunk's KVs/P fully consumed (also covers Q init)
        #pragma unroll
        for (int p = 0; p < 8; p++) {
            float4 v4 = *(const float4*)(kbase + (size_t)(kb*128 + ldr + 16*p)*DK + ldc);
            *(float4*)&KVs[(ldr+16*p)*KVP2 + ldc] = v4;
        }
        __syncthreads();

        // ---- scores for this chunk ----
        float acc[2][4] = {};
        #pragma unroll
        for (int ks = 0; ks < 8; ks++) {
            int k0 = ks*8;
            uint32_t qh4[4], ql4[4];
            qh4[0] = Qhi[ qr   *QSP + k0+qc  ];
            qh4[1] = Qhi[(qr+8)*QSP + k0+qc  ];
            qh4[2] = Qhi[ qr   *QSP + k0+qc+4];
            qh4[3] = Qhi[(qr+8)*QSP + k0+qc+4];
            ql4[0] = Qlo[ qr   *QSP + k0+qc  ];
            ql4[1] = Qlo[(qr+8)*QSP + k0+qc  ];
            ql4[2] = Qlo[ qr   *QSP + k0+qc+4];
            ql4[3] = Qlo[(qr+8)*QSP + k0+qc+4];
            #pragma unroll
            for (int ni = 0; ni < 2; ni++) {
                int rn = w*16 + 8*ni + qr;
                uint32_t bh[2], bl[2];
                split_tf(KVs[rn*KVP2 + k0+qc  ], bh[0], bl[0]);
                split_tf(KVs[rn*KVP2 + k0+qc+4], bh[1], bl[1]);
                mma8(acc[ni], qh4, bh);
                mma8(acc[ni], qh4, bl);
                mma8(acc[ni], ql4, bh);
            }
        }

        // ---- mask/scale/exp + split-store P chunk ----
        #pragma unroll
        for (int ni = 0; ni < 2; ni++) {
            int gl = w*16 + 8*ni + 2*qc;
            int gc = kb*128 + gl;
            int m0 = mask[(size_t)b*SS + gc];
            int m1 = mask[(size_t)b*SS + gc + 1];
            float s0 = m0 ? acc[ni][0]*0.125f : -1e9f;
            float s1 = m1 ? acc[ni][1]*0.125f : -1e9f;
            float s2 = m0 ? acc[ni][2]*0.125f : -1e9f;
            float s3 = m1 ? acc[ni][3]*0.125f : -1e9f;
            s0 = fminf(fmaxf(s0, -80.f), 80.f);
            s1 = fminf(fmaxf(s1, -80.f), 80.f);
            s2 = fminf(fmaxf(s2, -80.f), 80.f);
            s3 = fminf(fmaxf(s3, -80.f), 80.f);
            float e0 = __expf(s0);      // MUFU
            float e1 = exp_poly(s1);    // FMA
            float e2 = exp_poly(s2);
            float e3 = __expf(s3);
            sum0 += e0 + e1;
            sum1 += e2 + e3;
            uint32_t hh, ll;
            split_tf(e0, hh, ll); Phi[ qr   *PCH + gl  ] = hh; Plo[ qr   *PCH + gl  ] = ll;
            split_tf(e1, hh, ll); Phi[ qr   *PCH + gl+1] = hh; Plo[ qr   *PCH + gl+1] = ll;
            split_tf(e2, hh, ll); Phi[(qr+8)*PCH + gl  ] = hh; Plo[(qr+8)*PCH + gl  ] = ll;
            split_tf(e3, hh, ll); Phi[(qr+8)*PCH + gl+1] = hh; Plo[(qr+8)*PCH + gl+1] = ll;
        }
        __syncthreads();   // P chunk ready; K no longer needed

        // ---- dump unnormalized exp chunk to attn + load V chunk ----
        if (write_attn) {
            int row = t>>4, cb = (t&15)*8;
            size_t abase = (((size_t)b*HH + h)*SS + (size_t)(qt*16 + row))*SS + kb*128 + cb;
            float4 v0, v1;
            v0.x = __uint_as_float(Phi[row*PCH+cb  ]) + __uint_as_float(Plo[row*PCH+cb  ]);
            v0.y = __uint_as_float(Phi[row*PCH+cb+1]) + __uint_as_float(Plo[row*PCH+cb+1]);
            v0.z = __uint_as_float(Phi[row*PCH+cb+2]) + __uint_as_float(Plo[row*PCH+cb+2]);
            v0.w = __uint_as_float(Phi[row*PCH+cb+3]) + __uint_as_float(Plo[row*PCH+cb+3]);
            v1.x = __uint_as_float(Phi[row*PCH+cb+4]) + __uint_as_float(Plo[row*PCH+cb+4]);
            v1.y = __uint_as_float(Phi[row*PCH+cb+5]) + __uint_as_float(Plo[row*PCH+cb+5]);
            v1.z = __uint_as_float(Phi[row*PCH+cb+6]) + __uint_as_float(Plo[row*PCH+cb+6]);
            v1.w = __uint_as_float(Phi[row*PCH+cb+7]) + __uint_as_float(Plo[row*PCH+cb+7]);
            *(float4*)(attn + abase)     = v0;
            *(float4*)(attn + abase + 4) = v1;
        }
        #pragma unroll
        for (int p = 0; p < 8; p++) {
            float4 v4 = *(const float4*)(vbase + (size_t)(kb*128 + ldr + 16*p)*DK + ldc);
            *(float4*)&KVs[(ldr+16*p)*KVP2 + ldc] = v4;
        }
        __syncthreads();

        // ---- P @ V for this chunk ----
        #pragma unroll
        for (int ks = 0; ks < 16; ks++) {
            int j8 = ks*8;
            uint32_t ph[4], pl[4], vh2[2], vl2[2];
            ph[0] = Phi[ qr   *PCH + j8+qc  ];
            ph[1] = Phi[(qr+8)*PCH + j8+qc  ];
            ph[2] = Phi[ qr   *PCH + j8+qc+4];
            ph[3] = Phi[(qr+8)*PCH + j8+qc+4];
            pl[0] = Plo[ qr   *PCH + j8+qc  ];
            pl[1] = Plo[(qr+8)*PCH + j8+qc  ];
            pl[2] = Plo[ qr   *PCH + j8+qc+4];
            pl[3] = Plo[(qr+8)*PCH + j8+qc+4];
            split_tf(KVs[(j8+qc  )*KVP2 + 8*w + qr], vh2[0], vl2[0]);
            split_tf(KVs[(j8+qc+4)*KVP2 + 8*w + qr], vh2[1], vl2[1]);
            mma8(oacc, ph, vh2);
            mma8(oacc, ph, vl2);
            mma8(oacc, pl, vh2);
        }
    }

    // ---- row-sum reduction ----
    sum0 += __shfl_xor_sync(0xffffffffu, sum0, 1);
    sum0 += __shfl_xor_sync(0xffffffffu, sum0, 2);
    sum1 += __shfl_xor_sync(0xffffffffu, sum1, 1);
    sum1 += __shfl_xor_sync(0xffffffffu, sum1, 2);
    if (qc == 0) {
        red[ qr   *8 + w] = sum0;
        red[(qr+8)*8 + w] = sum1;
    }
    __syncthreads();
    if (t < 16) {
        float s = 0.f;
        #pragma unroll
        for (int ww = 0; ww < 8; ww++) s += red[t*8 + ww];
        float iv = 1.f / s;
        invs[t] = iv;
        inv_g[((size_t)b*HH + h)*SS + qt*16 + t] = iv;
    }
    __syncthreads();

    float iv0 = invs[qr], iv1 = invs[qr+8];
    size_t r0 = (size_t)b*SS + qt*16 + qr;
    int c0 = h*DK + 8*w + 2*qc;
    o[ r0   *DD + c0  ] = oacc[0]*iv0;
    o[ r0   *DD + c0+1] = oacc[1]*iv0;
    o[(r0+8)*DD + c0  ] = oacc[2]*iv1;
    o[(r0+8)*DD + c0+1] = oacc[3]*iv1;
}

// ---------------------------------------------------------------------------
// Normalize attention probs: attn[row, :] *= inv[row].  One block per row.
// ---------------------------------------------------------------------------
__global__ __launch_bounds__(256)
void attn_scale(float* __restrict__ attn, const float* __restrict__ inv_g)
{
    int row = blockIdx.x;
    float iv = inv_g[row];
    float4* p = (float4*)(attn + (size_t)row*SS);
    int t = threadIdx.x;
    #pragma unroll
    for (int i = 0; i < SS/4/256; i++) {
        float4 v = p[t + 256*i];
        v.x *= iv; v.y *= iv; v.z *= iv; v.w *= iv;
        p[t + 256*i] = v;
    }
}

// ---------------------------------------------------------------------------
extern "C" void kernel_launch(void* const* d_in, const int* in_sizes, int n_in,
                              void* d_out, int out_size)
{
    const float* q    = (const float*)d_in[0];
    const float* k    = (const float*)d_in[1];
    const float* v    = (const float*)d_in[2];
    const int*   mask = (const int*)  d_in[3];
    const float* wq_w = (const float*)d_in[4];
    const float* wq_b = (const float*)d_in[5];
    const float* wk_w = (const float*)d_in[6];
    const float* wk_b = (const float*)d_in[7];
    const float* wv_w = (const float*)d_in[8];
    const float* wv_b = (const float*)d_in[9];
    const float* wo_w = (const float*)d_in[10];
    const float* wo_b = (const float*)d_in[11];

    float *qh_p, *kh_p, *vh_p, *o_p, *inv_p;
    cudaGetSymbolAddress((void**)&qh_p, g_qh);
    cudaGetSymbolAddress((void**)&kh_p, g_kh);
    cudaGetSymbolAddress((void**)&vh_p, g_vh);
    cudaGetSymbolAddress((void**)&o_p,  g_o);
    cudaGetSymbolAddress((void**)&inv_p, g_inv);

    const long OUT_E  = (long)BB*SS*DD;              // 4,194,304
    const long ATTN_E = (long)BB*HH*SS*(long)SS;     // 134,217,728
    float* out_ptr  = nullptr;
    float* attn_ptr = nullptr;
    if ((long)out_size >= OUT_E + ATTN_E) {
        out_ptr  = (float*)d_out;
        attn_ptr = (float*)d_out + OUT_E;
    } else if ((long)out_size >= ATTN_E) {
        attn_ptr = (float*)d_out;
    } else {
        out_ptr  = (float*)d_out;
    }

    cudaFuncSetAttribute(proj_tc<1>, cudaFuncAttributeMaxDynamicSharedMemorySize, PROJ_SMEM);
    cudaFuncSetAttribute(proj_tc<0>, cudaFuncAttributeMaxDynamicSharedMemorySize, PROJ_SMEM);
    dim3 pgrid(DD/64, MM/128);   // 16 x 32
    proj_tc<1><<<pgrid, 256, PROJ_SMEM>>>(q, wq_w, wq_b, qh_p);
    proj_tc<1><<<pgrid, 256, PROJ_SMEM>>>(k, wk_w, wk_b, kh_p);
    proj_tc<1><<<pgrid, 256, PROJ_SMEM>>>(v, wv_w, wv_b, vh_p);

    cudaFuncSetAttribute(attn_fused,
                         cudaFuncAttributeMaxDynamicSharedMemorySize, ATTN_SMEM);
    attn_fused<<<dim3(SS/16, HH, BB), 256, ATTN_SMEM>>>(
        qh_p, kh_p, vh_p, mask, attn_ptr, o_p, inv_p,
        attn_ptr != nullptr ? 1 : 0);

    if (attn_ptr)
        attn_scale<<<BB*HH*SS, 256>>>(attn_ptr, inv_p);

    if (out_ptr)
        proj_tc<0><<<pgrid, 256, PROJ_SMEM>>>(o_p, wo_w, wo_b, out_ptr);
}

// round 10
// speedup vs baseline: 1.5869x; 1.1920x over previous
#include <cuda_runtime.h>
#include <cstdint>

#define BB 2
#define SS 2048
#define DD 1024
#define HH 16
#define DK 64
#define MM (BB*SS)

// Scratch (device globals: allocation-free per harness rules)
__device__ float g_qh [(size_t)BB*HH*SS*DK];
__device__ float g_kh [(size_t)BB*HH*SS*DK];
__device__ float g_vh [(size_t)BB*HH*SS*DK];
__device__ float g_o  [(size_t)BB*SS*DD];
__device__ float g_inv[(size_t)BB*HH*SS];

// ---------------------------------------------------------------------------
// tf32 helpers
// ---------------------------------------------------------------------------
__device__ __forceinline__ uint32_t f2tf(float x){
    uint32_t r; asm("cvt.rna.tf32.f32 %0, %1;" : "=r"(r) : "f"(x)); return r;
}
__device__ __forceinline__ void split_tf(float x, uint32_t& hi, uint32_t& lo){
    hi = f2tf(x);
    lo = f2tf(x - __uint_as_float(hi));
}
__device__ __forceinline__ void mma8(float* d, const uint32_t* a, const uint32_t* b){
    asm volatile("mma.sync.aligned.m16n8k8.row.col.f32.tf32.tf32.f32 "
        "{%0,%1,%2,%3},{%4,%5,%6,%7},{%8,%9},{%0,%1,%2,%3};"
        : "+f"(d[0]),"+f"(d[1]),"+f"(d[2]),"+f"(d[3])
        : "r"(a[0]),"r"(a[1]),"r"(a[2]),"r"(a[3]),"r"(b[0]),"r"(b[1]));
}

// FFMA-pipe exp: e^x via 2^(x*log2e), degree-5 poly. Valid |x|<=80, rel ~5e-7.
__device__ __forceinline__ float exp_poly(float x){
    float y = x * 1.4426950408889634f;
    float t = y + 12582912.0f;
    int   n = __float_as_int(t) - 0x4B400000;
    float f = y - (t - 12582912.0f);
    float p =              1.33335581e-3f;
    p = fmaf(p, f, 9.61812910e-3f);
    p = fmaf(p, f, 5.55041087e-2f);
    p = fmaf(p, f, 2.40226507e-1f);
    p = fmaf(p, f, 6.93147180e-1f);
    p = fmaf(p, f, 1.0f);
    return __int_as_float(__float_as_int(p) + (n << 23));
}

// ---------------------------------------------------------------------------
// Projection GEMM (unchanged — split-at-smem-store 3xTF32, pure LDS+MMA core).
// ---------------------------------------------------------------------------
#define PSTR 36
#define PROJ_SMEM ((2*128*PSTR + 2*64*PSTR) * 4)
template<int MODE>
__global__ __launch_bounds__(256)
void proj_tc(const float* __restrict__ A, const float* __restrict__ W,
             const float* __restrict__ bias, float* __restrict__ C)
{
    extern __shared__ uint32_t ps[];
    uint32_t* Ash = ps;
    uint32_t* Asl = Ash + 128*PSTR;
    uint32_t* Wsh = Asl + 128*PSTR;
    uint32_t* Wsl = Wsh + 64*PSTR;

    const int bm = blockIdx.y*128, bn = blockIdx.x*64;
    const int t = threadIdx.x, wid = t>>5, lane = t&31;
    const int qr = lane>>2, qc = lane&3;
    const int wm = (wid&3)*32, wn = (wid>>2)*32;
    const int lr = t>>3, lc = (t&7)*4;

    float acc[2][4][4] = {};

    for (int kc = 0; kc < DD; kc += 32) {
        __syncthreads();
        #pragma unroll
        for (int p = 0; p < 4; p++) {
            int row = lr + 32*p;
            float4 v4 = *(const float4*)(A + (size_t)(bm+row)*DD + kc + lc);
            uint4 h4, l4;
            split_tf(v4.x, h4.x, l4.x); split_tf(v4.y, h4.y, l4.y);
            split_tf(v4.z, h4.z, l4.z); split_tf(v4.w, h4.w, l4.w);
            *(uint4*)(Ash + row*PSTR + lc) = h4;
            *(uint4*)(Asl + row*PSTR + lc) = l4;
        }
        #pragma unroll
        for (int p = 0; p < 2; p++) {
            int row = lr + 32*p;
            float4 v4 = *(const float4*)(W + (size_t)(bn+row)*DD + kc + lc);
            uint4 h4, l4;
            split_tf(v4.x, h4.x, l4.x); split_tf(v4.y, h4.y, l4.y);
            split_tf(v4.z, h4.z, l4.z); split_tf(v4.w, h4.w, l4.w);
            *(uint4*)(Wsh + row*PSTR + lc) = h4;
            *(uint4*)(Wsl + row*PSTR + lc) = l4;
        }
        __syncthreads();
        #pragma unroll
        for (int ks = 0; ks < 4; ks++) {
            int k0 = ks*8;
            uint32_t ah[2][4], al[2][4], bh[4][2], bl[4][2];
            #pragma unroll
            for (int mi = 0; mi < 2; mi++) {
                int r0 = wm + 16*mi + qr;
                ah[mi][0] = Ash[ r0   *PSTR + k0+qc  ];
                ah[mi][1] = Ash[(r0+8)*PSTR + k0+qc  ];
                ah[mi][2] = Ash[ r0   *PSTR + k0+qc+4];
                ah[mi][3] = Ash[(r0+8)*PSTR + k0+qc+4];
                al[mi][0] = Asl[ r0   *PSTR + k0+qc  ];
                al[mi][1] = Asl[(r0+8)*PSTR + k0+qc  ];
                al[mi][2] = Asl[ r0   *PSTR + k0+qc+4];
                al[mi][3] = Asl[(r0+8)*PSTR + k0+qc+4];
            }
            #pragma unroll
            for (int ni = 0; ni < 4; ni++) {
                int rn = wn + 8*ni + qr;
                bh[ni][0] = Wsh[rn*PSTR + k0+qc  ];
                bh[ni][1] = Wsh[rn*PSTR + k0+qc+4];
                bl[ni][0] = Wsl[rn*PSTR + k0+qc  ];
                bl[ni][1] = Wsl[rn*PSTR + k0+qc+4];
            }
            #pragma unroll
            for (int mi = 0; mi < 2; mi++)
                #pragma unroll
                for (int ni = 0; ni < 4; ni++) {
                    mma8(acc[mi][ni], ah[mi], bh[ni]);
                    mma8(acc[mi][ni], ah[mi], bl[ni]);
                    mma8(acc[mi][ni], al[mi], bh[ni]);
                }
        }
    }
    #pragma unroll
    for (int mi = 0; mi < 2; mi++) {
        int r0 = bm + wm + 16*mi + qr;
        #pragma unroll
        for (int ni = 0; ni < 4; ni++) {
            int c0 = bn + wn + 8*ni + 2*qc;
            #pragma unroll
            for (int e = 0; e < 4; e++) {
                int m = r0 + ((e>=2) ? 8 : 0);
                int n = c0 + (e&1);
                float val = acc[mi][ni][e] + bias[n];
                if (MODE == 0) {
                    C[(size_t)m*DD + n] = val;
                } else {
                    int b = m/SS, s = m%SS, h = n/DK, dk = n%DK;
                    C[(((size_t)b*HH+h)*SS+s)*DK+dk] = val;
                }
            }
        }
    }
}

// ---------------------------------------------------------------------------
// Fused attention v2: 2-term tf32, plain-float P buffer (split at PV load),
// PV contraction split 4-way x dk 2-way, end reduction through smem.
// Block = (b,h,16 q rows), 256 threads, 8 warps. smem ~48KB -> 3 CTAs/SM.
// ---------------------------------------------------------------------------
#define KVP2 68
#define PCH  132
#define QSP  68
#define ATTN_SMEM ((128*KVP2 + 16*PCH + 16*QSP + 16*8 + 16) * (int)sizeof(float))

__global__ __launch_bounds__(256, 3)
void attn_fused(const float* __restrict__ qh, const float* __restrict__ kh,
                const float* __restrict__ vh, const int* __restrict__ mask,
                float* __restrict__ attn, float* __restrict__ o,
                float* __restrict__ inv_g, int write_attn)
{
    extern __shared__ float smem[];
    float*    KVs  = smem;                           // [128][KVP2] (K, then V, then O-reduce)
    float*    Pch  = smem + 128*KVP2;                // [16][PCH] plain-float P
    uint32_t* Qhi  = (uint32_t*)(Pch + 16*PCH);      // [16][QSP] tf32-hi Q
    float*    red2 = (float*)(Qhi + 16*QSP);         // [16][8] row-sum partials
    float*    invs = red2 + 16*8;                    // [16]

    const int qt = blockIdx.x, h = blockIdx.y, b = blockIdx.z;
    const int t = threadIdx.x, w = t>>5, lane = t&31;
    const int qr = lane>>2, qc = lane&3;
    const int cw = w & 3;         // PV contraction slice
    const int dw = w >> 2;        // PV dk half

    const float* qbase = qh + (((size_t)b*HH+h)*SS + (size_t)qt*16)*DK;
    const float* kbase = kh + ((size_t)b*HH+h)*SS*DK;
    const float* vbase = vh + ((size_t)b*HH+h)*SS*DK;

    // load Q tile (16x64), keep tf32-hi only (2-term scheme)
    {
        int row = t>>4, col = (t&15)*4;
        float4 v4 = *(const float4*)(qbase + (size_t)row*DK + col);
        uint4 h4;
        h4.x = f2tf(v4.x); h4.y = f2tf(v4.y); h4.z = f2tf(v4.z); h4.w = f2tf(v4.w);
        *(uint4*)(Qhi + row*QSP + col) = h4;
    }

    float sum0 = 0.f, sum1 = 0.f;
    float oacc[4][4] = {};

    const int ldr = t>>4, ldc = (t&15)*4;   // K/V tile loader coords

    for (int kb = 0; kb < SS/128; kb++) {
        __syncthreads();   // prev chunk fully consumed (also covers Q init)
        #pragma unroll
        for (int p = 0; p < 8; p++) {
            float4 v4 = *(const float4*)(kbase + (size_t)(kb*128 + ldr + 16*p)*DK + ldc);
            *(float4*)&KVs[(ldr+16*p)*KVP2 + ldc] = v4;
        }
        __syncthreads();

        // ---- scores: qh*(kh + kl), warp w owns cols [16w, 16w+16) ----
        float acc[2][4] = {};
        #pragma unroll
        for (int ks = 0; ks < 8; ks++) {
            int k0 = ks*8;
            uint32_t qh4[4];
            qh4[0] = Qhi[ qr   *QSP + k0+qc  ];
            qh4[1] = Qhi[(qr+8)*QSP + k0+qc  ];
            qh4[2] = Qhi[ qr   *QSP + k0+qc+4];
            qh4[3] = Qhi[(qr+8)*QSP + k0+qc+4];
            #pragma unroll
            for (int ni = 0; ni < 2; ni++) {
                int rn = w*16 + 8*ni + qr;
                uint32_t bh[2], bl[2];
                split_tf(KVs[rn*KVP2 + k0+qc  ], bh[0], bl[0]);
                split_tf(KVs[rn*KVP2 + k0+qc+4], bh[1], bl[1]);
                mma8(acc[ni], qh4, bh);
                mma8(acc[ni], qh4, bl);
            }
        }

        // ---- mask/scale/exp, store plain-float P chunk ----
        #pragma unroll
        for (int ni = 0; ni < 2; ni++) {
            int gl = w*16 + 8*ni + 2*qc;
            int gc = kb*128 + gl;
            int m0 = mask[(size_t)b*SS + gc];
            int m1 = mask[(size_t)b*SS + gc + 1];
            float s0 = m0 ? acc[ni][0]*0.125f : -1e9f;
            float s1 = m1 ? acc[ni][1]*0.125f : -1e9f;
            float s2 = m0 ? acc[ni][2]*0.125f : -1e9f;
            float s3 = m1 ? acc[ni][3]*0.125f : -1e9f;
            s0 = fminf(fmaxf(s0, -80.f), 80.f);
            s1 = fminf(fmaxf(s1, -80.f), 80.f);
            s2 = fminf(fmaxf(s2, -80.f), 80.f);
            s3 = fminf(fmaxf(s3, -80.f), 80.f);
            float e0 = __expf(s0);      // MUFU
            float e1 = exp_poly(s1);    // FMA
            float e2 = exp_poly(s2);
            float e3 = __expf(s3);
            sum0 += e0 + e1;
            sum1 += e2 + e3;
            Pch[ qr   *PCH + gl  ] = e0;
            Pch[ qr   *PCH + gl+1] = e1;
            Pch[(qr+8)*PCH + gl  ] = e2;
            Pch[(qr+8)*PCH + gl+1] = e3;
        }
        __syncthreads();   // P ready; K no longer needed

        // ---- dump unnormalized exp chunk + load V chunk ----
        if (write_attn) {
            int row = t>>4, cb = (t&15)*8;
            size_t abase = (((size_t)b*HH + h)*SS + (size_t)(qt*16 + row))*SS + kb*128 + cb;
            *(float4*)(attn + abase)     = *(const float4*)(Pch + row*PCH + cb);
            *(float4*)(attn + abase + 4) = *(const float4*)(Pch + row*PCH + cb + 4);
        }
        #pragma unroll
        for (int p = 0; p < 8; p++) {
            float4 v4 = *(const float4*)(vbase + (size_t)(kb*128 + ldr + 16*p)*DK + ldc);
            *(float4*)&KVs[(ldr+16*p)*KVP2 + ldc] = v4;
        }
        __syncthreads();

        // ---- PV: warp contracts cols [cw*32,+32), dk cols [dw*32,+32) ----
        #pragma unroll
        for (int ks = 0; ks < 4; ks++) {
            int j8 = cw*32 + ks*8;
            uint32_t ph[4], pl[4];
            split_tf(Pch[ qr   *PCH + j8+qc  ], ph[0], pl[0]);
            split_tf(Pch[(qr+8)*PCH + j8+qc  ], ph[1], pl[1]);
            split_tf(Pch[ qr   *PCH + j8+qc+4], ph[2], pl[2]);
            split_tf(Pch[(qr+8)*PCH + j8+qc+4], ph[3], pl[3]);
            #pragma unroll
            for (int ni = 0; ni < 4; ni++) {
                int n0 = dw*32 + ni*8 + qr;
                uint32_t vh2[2];
                vh2[0] = f2tf(KVs[(j8+qc  )*KVP2 + n0]);
                vh2[1] = f2tf(KVs[(j8+qc+4)*KVP2 + n0]);
                mma8(oacc[ni], ph, vh2);
                mma8(oacc[ni], pl, vh2);
            }
        }
    }

    // ---- row-sum reduction -> invs ----
    sum0 += __shfl_xor_sync(0xffffffffu, sum0, 1);
    sum0 += __shfl_xor_sync(0xffffffffu, sum0, 2);
    sum1 += __shfl_xor_sync(0xffffffffu, sum1, 1);
    sum1 += __shfl_xor_sync(0xffffffffu, sum1, 2);
    if (qc == 0) {
        red2[ qr   *8 + w] = sum0;
        red2[(qr+8)*8 + w] = sum1;
    }
    __syncthreads();   // also: all PV reads of KVs done -> safe to reuse
    if (t < 16) {
        float s = 0.f;
        #pragma unroll
        for (int ww = 0; ww < 8; ww++) s += red2[t*8 + ww];
        float iv = 1.f / s;
        invs[t] = iv;
        inv_g[((size_t)b*HH + h)*SS + qt*16 + t] = iv;
    }

    // ---- O partial reduction through smem (reuse KVs: [8][16][36]) ----
    float* redO = KVs;
    #pragma unroll
    for (int ni = 0; ni < 4; ni++) {
        int c0 = ni*8 + 2*qc;
        redO[w*576 +  qr   *36 + c0  ] = oacc[ni][0];
        redO[w*576 +  qr   *36 + c0+1] = oacc[ni][1];
        redO[w*576 + (qr+8)*36 + c0  ] = oacc[ni][2];
        redO[w*576 + (qr+8)*36 + c0+1] = oacc[ni][3];
    }
    __syncthreads();
    {
        int row = t>>4;
        float iv = invs[row];
        size_t orow = (size_t)b*SS + qt*16 + row;
        #pragma unroll
        for (int j = 0; j < 4; j++) {
            int col = (t&15)*4 + j;
            int dwo = col>>5, lc = col&31;
            float s = redO[(dwo*4+0)*576 + row*36 + lc]
                    + redO[(dwo*4+1)*576 + row*36 + lc]
                    + redO[(dwo*4+2)*576 + row*36 + lc]
                    + redO[(dwo*4+3)*576 + row*36 + lc];
            o[orow*DD + h*DK + col] = s * iv;
        }
    }
}

// ---------------------------------------------------------------------------
// Normalize attention probs: attn[row, :] *= inv[row].  One block per row.
// ---------------------------------------------------------------------------
__global__ __launch_bounds__(256)
void attn_scale(float* __restrict__ attn, const float* __restrict__ inv_g)
{
    int row = blockIdx.x;
    float iv = inv_g[row];
    float4* p = (float4*)(attn + (size_t)row*SS);
    int t = threadIdx.x;
    #pragma unroll
    for (int i = 0; i < SS/4/256; i++) {
        float4 v = p[t + 256*i];
        v.x *= iv; v.y *= iv; v.z *= iv; v.w *= iv;
        p[t + 256*i] = v;
    }
}

// ---------------------------------------------------------------------------
extern "C" void kernel_launch(void* const* d_in, const int* in_sizes, int n_in,
                              void* d_out, int out_size)
{
    const float* q    = (const float*)d_in[0];
    const float* k    = (const float*)d_in[1];
    const float* v    = (const float*)d_in[2];
    const int*   mask = (const int*)  d_in[3];
    const float* wq_w = (const float*)d_in[4];
    const float* wq_b = (const float*)d_in[5];
    const float* wk_w = (const float*)d_in[6];
    const float* wk_b = (const float*)d_in[7];
    const float* wv_w = (const float*)d_in[8];
    const float* wv_b = (const float*)d_in[9];
    const float* wo_w = (const float*)d_in[10];
    const float* wo_b = (const float*)d_in[11];

    float *qh_p, *kh_p, *vh_p, *o_p, *inv_p;
    cudaGetSymbolAddress((void**)&qh_p, g_qh);
    cudaGetSymbolAddress((void**)&kh_p, g_kh);
    cudaGetSymbolAddress((void**)&vh_p, g_vh);
    cudaGetSymbolAddress((void**)&o_p,  g_o);
    cudaGetSymbolAddress((void**)&inv_p, g_inv);

    const long OUT_E  = (long)BB*SS*DD;              // 4,194,304
    const long ATTN_E = (long)BB*HH*SS*(long)SS;     // 134,217,728
    float* out_ptr  = nullptr;
    float* attn_ptr = nullptr;
    if ((long)out_size >= OUT_E + ATTN_E) {
        out_ptr  = (float*)d_out;
        attn_ptr = (float*)d_out + OUT_E;
    } else if ((long)out_size >= ATTN_E) {
        attn_ptr = (float*)d_out;
    } else {
        out_ptr  = (float*)d_out;
    }

    cudaFuncSetAttribute(proj_tc<1>, cudaFuncAttributeMaxDynamicSharedMemorySize, PROJ_SMEM);
    cudaFuncSetAttribute(proj_tc<0>, cudaFuncAttributeMaxDynamicSharedMemorySize, PROJ_SMEM);
    dim3 pgrid(DD/64, MM/128);   // 16 x 32
    proj_tc<1><<<pgrid, 256, PROJ_SMEM>>>(q, wq_w, wq_b, qh_p);
    proj_tc<1><<<pgrid, 256, PROJ_SMEM>>>(k, wk_w, wk_b, kh_p);
    proj_tc<1><<<pgrid, 256, PROJ_SMEM>>>(v, wv_w, wv_b, vh_p);

    cudaFuncSetAttribute(attn_fused,
                         cudaFuncAttributeMaxDynamicSharedMemorySize, ATTN_SMEM);
    attn_fused<<<dim3(SS/16, HH, BB), 256, ATTN_SMEM>>>(
        qh_p, kh_p, vh_p, mask, attn_ptr, o_p, inv_p,
        attn_ptr != nullptr ? 1 : 0);

    if (attn_ptr)
        attn_scale<<<BB*HH*SS, 256>>>(attn_ptr, inv_p);

    if (out_ptr)
        proj_tc<0><<<pgrid, 256, PROJ_SMEM>>>(o_p, wo_w, wo_b, out_ptr);
}

// round 11
// speedup vs baseline: 1.8258x; 1.1505x over previous
#include <cuda_runtime.h>
#include <cstdint>

#define BB 2
#define SS 2048
#define DD 1024
#define HH 16
#define DK 64
#define MM (BB*SS)

// Scratch (device globals: allocation-free per harness rules)
__device__ float g_qh [(size_t)BB*HH*SS*DK];
__device__ float g_kh [(size_t)BB*HH*SS*DK];
__device__ float g_vh [(size_t)BB*HH*SS*DK];
__device__ float g_o  [(size_t)BB*SS*DD];
__device__ float g_inv[(size_t)BB*HH*SS];

// ---------------------------------------------------------------------------
// tf32 helpers
// ---------------------------------------------------------------------------
__device__ __forceinline__ uint32_t f2tf(float x){
    uint32_t r; asm("cvt.rna.tf32.f32 %0, %1;" : "=r"(r) : "f"(x)); return r;
}
__device__ __forceinline__ void split_tf(float x, uint32_t& hi, uint32_t& lo){
    hi = f2tf(x);
    lo = f2tf(x - __uint_as_float(hi));
}
__device__ __forceinline__ void mma8(float* d, const uint32_t* a, const uint32_t* b){
    asm volatile("mma.sync.aligned.m16n8k8.row.col.f32.tf32.tf32.f32 "
        "{%0,%1,%2,%3},{%4,%5,%6,%7},{%8,%9},{%0,%1,%2,%3};"
        : "+f"(d[0]),"+f"(d[1]),"+f"(d[2]),"+f"(d[3])
        : "r"(a[0]),"r"(a[1]),"r"(a[2]),"r"(a[3]),"r"(b[0]),"r"(b[1]));
}
__device__ __forceinline__ void cpa16(void* dst_smem, const void* src){
    uint32_t d = (uint32_t)__cvta_generic_to_shared(dst_smem);
    asm volatile("cp.async.cg.shared.global [%0], [%1], 16;" :: "r"(d), "l"(src));
}

// FFMA-pipe exp: e^x via 2^(x*log2e), degree-5 poly. Valid |x|<=80, rel ~5e-7.
__device__ __forceinline__ float exp_poly(float x){
    float y = x * 1.4426950408889634f;
    float t = y + 12582912.0f;
    int   n = __float_as_int(t) - 0x4B400000;
    float f = y - (t - 12582912.0f);
    float p =              1.33335581e-3f;
    p = fmaf(p, f, 9.61812910e-3f);
    p = fmaf(p, f, 5.55041087e-2f);
    p = fmaf(p, f, 2.40226507e-1f);
    p = fmaf(p, f, 6.93147180e-1f);
    p = fmaf(p, f, 1.0f);
    return __int_as_float(__float_as_int(p) + (n << 23));
}

// ---------------------------------------------------------------------------
// Projection GEMM (unchanged — split-at-smem-store 3xTF32, pure LDS+MMA core).
// ---------------------------------------------------------------------------
#define PSTR 36
#define PROJ_SMEM ((2*128*PSTR + 2*64*PSTR) * 4)
template<int MODE>
__global__ __launch_bounds__(256)
void proj_tc(const float* __restrict__ A, const float* __restrict__ W,
             const float* __restrict__ bias, float* __restrict__ C)
{
    extern __shared__ uint32_t ps[];
    uint32_t* Ash = ps;
    uint32_t* Asl = Ash + 128*PSTR;
    uint32_t* Wsh = Asl + 128*PSTR;
    uint32_t* Wsl = Wsh + 64*PSTR;

    const int bm = blockIdx.y*128, bn = blockIdx.x*64;
    const int t = threadIdx.x, wid = t>>5, lane = t&31;
    const int qr = lane>>2, qc = lane&3;
    const int wm = (wid&3)*32, wn = (wid>>2)*32;
    const int lr = t>>3, lc = (t&7)*4;

    float acc[2][4][4] = {};

    for (int kc = 0; kc < DD; kc += 32) {
        __syncthreads();
        #pragma unroll
        for (int p = 0; p < 4; p++) {
            int row = lr + 32*p;
            float4 v4 = *(const float4*)(A + (size_t)(bm+row)*DD + kc + lc);
            uint4 h4, l4;
            split_tf(v4.x, h4.x, l4.x); split_tf(v4.y, h4.y, l4.y);
            split_tf(v4.z, h4.z, l4.z); split_tf(v4.w, h4.w, l4.w);
            *(uint4*)(Ash + row*PSTR + lc) = h4;
            *(uint4*)(Asl + row*PSTR + lc) = l4;
        }
        #pragma unroll
        for (int p = 0; p < 2; p++) {
            int row = lr + 32*p;
            float4 v4 = *(const float4*)(W + (size_t)(bn+row)*DD + kc + lc);
            uint4 h4, l4;
            split_tf(v4.x, h4.x, l4.x); split_tf(v4.y, h4.y, l4.y);
            split_tf(v4.z, h4.z, l4.z); split_tf(v4.w, h4.w, l4.w);
            *(uint4*)(Wsh + row*PSTR + lc) = h4;
            *(uint4*)(Wsl + row*PSTR + lc) = l4;
        }
        __syncthreads();
        #pragma unroll
        for (int ks = 0; ks < 4; ks++) {
            int k0 = ks*8;
            uint32_t ah[2][4], al[2][4], bh[4][2], bl[4][2];
            #pragma unroll
            for (int mi = 0; mi < 2; mi++) {
                int r0 = wm + 16*mi + qr;
                ah[mi][0] = Ash[ r0   *PSTR + k0+qc  ];
                ah[mi][1] = Ash[(r0+8)*PSTR + k0+qc  ];
                ah[mi][2] = Ash[ r0   *PSTR + k0+qc+4];
                ah[mi][3] = Ash[(r0+8)*PSTR + k0+qc+4];
                al[mi][0] = Asl[ r0   *PSTR + k0+qc  ];
                al[mi][1] = Asl[(r0+8)*PSTR + k0+qc  ];
                al[mi][2] = Asl[ r0   *PSTR + k0+qc+4];
                al[mi][3] = Asl[(r0+8)*PSTR + k0+qc+4];
            }
            #pragma unroll
            for (int ni = 0; ni < 4; ni++) {
                int rn = wn + 8*ni + qr;
                bh[ni][0] = Wsh[rn*PSTR + k0+qc  ];
                bh[ni][1] = Wsh[rn*PSTR + k0+qc+4];
                bl[ni][0] = Wsl[rn*PSTR + k0+qc  ];
                bl[ni][1] = Wsl[rn*PSTR + k0+qc+4];
            }
            #pragma unroll
            for (int mi = 0; mi < 2; mi++)
                #pragma unroll
                for (int ni = 0; ni < 4; ni++) {
                    mma8(acc[mi][ni], ah[mi], bh[ni]);
                    mma8(acc[mi][ni], ah[mi], bl[ni]);
                    mma8(acc[mi][ni], al[mi], bh[ni]);
                }
        }
    }
    #pragma unroll
    for (int mi = 0; mi < 2; mi++) {
        int r0 = bm + wm + 16*mi + qr;
        #pragma unroll
        for (int ni = 0; ni < 4; ni++) {
            int c0 = bn + wn + 8*ni + 2*qc;
            #pragma unroll
            for (int e = 0; e < 4; e++) {
                int m = r0 + ((e>=2) ? 8 : 0);
                int n = c0 + (e&1);
                float val = acc[mi][ni][e] + bias[n];
                if (MODE == 0) {
                    C[(size_t)m*DD + n] = val;
                } else {
                    int b = m/SS, s = m%SS, h = n/DK, dk = n%DK;
                    C[(((size_t)b*HH+h)*SS+s)*DK+dk] = val;
                }
            }
        }
    }
}

// ---------------------------------------------------------------------------
// Fused attention v3: 32 q-rows per CTA, 2-term tf32, register-direct attn
// dump, V pre-converted at stage, KVP2=72 (conflict-free PV V-reads),
// cp.async K staging. 256 threads, 8 warps. smem ~62KB -> 3 CTAs/SM.
// Score: warp w owns cols [16w,16w+16) for both 16-row M-tiles.
// PV: warp (mh=w>>2, dw=(w>>1)&1, cw=w&1): rows [16mh,+16), dk [32dw,+32),
//     contraction [64cw,+64); 2-way cw reduction through smem at the end.
// ---------------------------------------------------------------------------
#define KVP2 72
#define PCH  132
#define QSP  68
#define ATTN_SMEM ((128*KVP2 + 32*PCH + 32*QSP + 32*8 + 32) * (int)sizeof(float))

__global__ __launch_bounds__(256, 3)
void attn_fused(const float* __restrict__ qh, const float* __restrict__ kh,
                const float* __restrict__ vh, const int* __restrict__ mask,
                float* __restrict__ attn, float* __restrict__ o,
                float* __restrict__ inv_g, int write_attn)
{
    extern __shared__ float smem[];
    float*    KVs  = smem;                           // [128][KVP2]
    float*    Pch  = smem + 128*KVP2;                // [32][PCH]
    uint32_t* Qhi  = (uint32_t*)(Pch + 32*PCH);      // [32][QSP] tf32 of Q/8
    float*    red2 = (float*)(Qhi + 32*QSP);         // [32][8]
    float*    invs = red2 + 32*8;                    // [32]

    const int qt = blockIdx.x, h = blockIdx.y, b = blockIdx.z;
    const int t = threadIdx.x, w = t>>5, lane = t&31;
    const int qr = lane>>2, qc = lane&3;
    const int mh = w>>2, dw = (w>>1)&1, cw = w&1;    // PV roles

    const float* qbase = qh + (((size_t)b*HH+h)*SS + (size_t)qt*32)*DK;
    const float* kbase = kh + ((size_t)b*HH+h)*SS*DK;
    const float* vbase = vh + ((size_t)b*HH+h)*SS*DK;

    // load Q tile (32x64), pre-scaled by 1/8, tf32-hi only
    {
        int row = t>>3, col = (t&7)*8;
        #pragma unroll
        for (int u = 0; u < 2; u++) {
            float4 v4 = *(const float4*)(qbase + (size_t)row*DK + col + u*4);
            uint4 h4;
            h4.x = f2tf(0.125f*v4.x); h4.y = f2tf(0.125f*v4.y);
            h4.z = f2tf(0.125f*v4.z); h4.w = f2tf(0.125f*v4.w);
            *(uint4*)(Qhi + row*QSP + col + u*4) = h4;
        }
    }

    float s00 = 0.f, s01 = 0.f, s10 = 0.f, s11 = 0.f;   // row sums [mt][half]
    float oacc[4][4] = {};

    const int ldr = t>>4, ldc = (t&15)*4;   // K/V tile loader coords

    for (int kb = 0; kb < SS/128; kb++) {
        __syncthreads();   // prev chunk fully consumed (also covers Q init)
        #pragma unroll
        for (int p = 0; p < 8; p++)
            cpa16(&KVs[(ldr+16*p)*KVP2 + ldc],
                  kbase + (size_t)(kb*128 + ldr + 16*p)*DK + ldc);
        asm volatile("cp.async.commit_group;");
        asm volatile("cp.async.wait_group 0;");
        __syncthreads();

        // ---- scores: qh*(kh + kl), warp w cols [16w,+16), both M-tiles ----
        float acc[2][2][4] = {};
        #pragma unroll
        for (int ks = 0; ks < 8; ks++) {
            int k0 = ks*8;
            uint32_t kh_[2][2], kl_[2][2];
            #pragma unroll
            for (int ni = 0; ni < 2; ni++) {
                int rn = w*16 + 8*ni + qr;
                split_tf(KVs[rn*KVP2 + k0+qc  ], kh_[ni][0], kl_[ni][0]);
                split_tf(KVs[rn*KVP2 + k0+qc+4], kh_[ni][1], kl_[ni][1]);
            }
            #pragma unroll
            for (int mt = 0; mt < 2; mt++) {
                uint32_t qh4[4];
                qh4[0] = Qhi[(mt*16+qr  )*QSP + k0+qc  ];
                qh4[1] = Qhi[(mt*16+qr+8)*QSP + k0+qc  ];
                qh4[2] = Qhi[(mt*16+qr  )*QSP + k0+qc+4];
                qh4[3] = Qhi[(mt*16+qr+8)*QSP + k0+qc+4];
                #pragma unroll
                for (int ni = 0; ni < 2; ni++) {
                    mma8(acc[mt][ni], qh4, kh_[ni]);
                    mma8(acc[mt][ni], qh4, kl_[ni]);
                }
            }
        }

        // ---- mask/exp, store P, dump unnormalized probs from registers ----
        #pragma unroll
        for (int mt = 0; mt < 2; mt++) {
            #pragma unroll
            for (int ni = 0; ni < 2; ni++) {
                int gl = w*16 + 8*ni + 2*qc;
                int gc = kb*128 + gl;
                int m0 = mask[(size_t)b*SS + gc];
                int m1 = mask[(size_t)b*SS + gc + 1];
                float v0 = m0 ? acc[mt][ni][0] : -1e9f;
                float v1 = m1 ? acc[mt][ni][1] : -1e9f;
                float v2 = m0 ? acc[mt][ni][2] : -1e9f;
                float v3 = m1 ? acc[mt][ni][3] : -1e9f;
                v0 = fminf(fmaxf(v0, -80.f), 80.f);
                v1 = fminf(fmaxf(v1, -80.f), 80.f);
                v2 = fminf(fmaxf(v2, -80.f), 80.f);
                v3 = fminf(fmaxf(v3, -80.f), 80.f);
                float e0 = __expf(v0);      // MUFU
                float e1 = exp_poly(v1);    // FMA
                float e2 = exp_poly(v2);
                float e3 = __expf(v3);
                if (mt == 0) { s00 += e0 + e1; s01 += e2 + e3; }
                else         { s10 += e0 + e1; s11 += e2 + e3; }
                Pch[(mt*16+qr  )*PCH + gl  ] = e0;
                Pch[(mt*16+qr  )*PCH + gl+1] = e1;
                Pch[(mt*16+qr+8)*PCH + gl  ] = e2;
                Pch[(mt*16+qr+8)*PCH + gl+1] = e3;
                if (write_attn) {
                    size_t ar0 = (((size_t)b*HH + h)*SS + (size_t)(qt*32 + mt*16 + qr))*SS + gc;
                    size_t ar1 = ar0 + (size_t)8*SS;
                    float2 p0 = make_float2(e0, e1);
                    float2 p1 = make_float2(e2, e3);
                    *(float2*)(attn + ar0) = p0;
                    *(float2*)(attn + ar1) = p1;
                }
            }
        }
        __syncthreads();   // P ready; K reads done

        // ---- stage V (pre-converted to tf32) ----
        #pragma unroll
        for (int p = 0; p < 8; p++) {
            float4 v4 = *(const float4*)(vbase + (size_t)(kb*128 + ldr + 16*p)*DK + ldc);
            uint4 c4;
            c4.x = f2tf(v4.x); c4.y = f2tf(v4.y); c4.z = f2tf(v4.z); c4.w = f2tf(v4.w);
            *(uint4*)&KVs[(ldr+16*p)*KVP2 + ldc] = c4;
        }
        __syncthreads();

        // ---- PV: rows [16mh,+16), dk [32dw,+32), contraction [64cw,+64) ----
        #pragma unroll
        for (int ks = 0; ks < 8; ks++) {
            int j8 = cw*64 + ks*8;
            uint32_t ph[4], pl[4];
            split_tf(Pch[(mh*16+qr  )*PCH + j8+qc  ], ph[0], pl[0]);
            split_tf(Pch[(mh*16+qr+8)*PCH + j8+qc  ], ph[1], pl[1]);
            split_tf(Pch[(mh*16+qr  )*PCH + j8+qc+4], ph[2], pl[2]);
            split_tf(Pch[(mh*16+qr+8)*PCH + j8+qc+4], ph[3], pl[3]);
            #pragma unroll
            for (int ni = 0; ni < 4; ni++) {
                int n0 = dw*32 + ni*8 + qr;
                uint32_t vh2[2];
                vh2[0] = __float_as_uint(KVs[(j8+qc  )*KVP2 + n0]);
                vh2[1] = __float_as_uint(KVs[(j8+qc+4)*KVP2 + n0]);
                mma8(oacc[ni], ph, vh2);
                mma8(oacc[ni], pl, vh2);
            }
        }
    }

    // ---- row-sum reduction -> invs ----
    s00 += __shfl_xor_sync(0xffffffffu, s00, 1);
    s00 += __shfl_xor_sync(0xffffffffu, s00, 2);
    s01 += __shfl_xor_sync(0xffffffffu, s01, 1);
    s01 += __shfl_xor_sync(0xffffffffu, s01, 2);
    s10 += __shfl_xor_sync(0xffffffffu, s10, 1);
    s10 += __shfl_xor_sync(0xffffffffu, s10, 2);
    s11 += __shfl_xor_sync(0xffffffffu, s11, 1);
    s11 += __shfl_xor_sync(0xffffffffu, s11, 2);
    if (qc == 0) {
        red2[( qr   )*8 + w] = s00;
        red2[( qr+8 )*8 + w] = s01;
        red2[(16+qr  )*8 + w] = s10;
        red2[(16+qr+8)*8 + w] = s11;
    }
    __syncthreads();   // also: all PV reads of KVs done -> safe to reuse
    if (t < 32) {
        float s = 0.f;
        #pragma unroll
        for (int ww = 0; ww < 8; ww++) s += red2[t*8 + ww];
        float iv = 1.f / s;
        invs[t] = iv;
        inv_g[((size_t)b*HH + h)*SS + qt*32 + t] = iv;
    }

    // ---- O partial reduction through smem: redO[2cw][32][68] ----
    float* redO = KVs;
    #pragma unroll
    for (int ni = 0; ni < 4; ni++) {
        int c0 = dw*32 + ni*8 + 2*qc;
        redO[cw*32*68 + (mh*16+qr  )*68 + c0  ] = oacc[ni][0];
        redO[cw*32*68 + (mh*16+qr  )*68 + c0+1] = oacc[ni][1];
        redO[cw*32*68 + (mh*16+qr+8)*68 + c0  ] = oacc[ni][2];
        redO[cw*32*68 + (mh*16+qr+8)*68 + c0+1] = oacc[ni][3];
    }
    __syncthreads();
    {
        int row = t>>3, cb = (t&7)*8;
        float iv = invs[row];
        size_t orow = (size_t)b*SS + qt*32 + row;
        #pragma unroll
        for (int j = 0; j < 8; j++) {
            int col = cb + j;
            float s = redO[row*68 + col] + redO[32*68 + row*68 + col];
            o[orow*DD + h*DK + col] = s * iv;
        }
    }
}

// ---------------------------------------------------------------------------
// Normalize attention probs: attn[row, :] *= inv[row].  One block per row.
// ---------------------------------------------------------------------------
__global__ __launch_bounds__(256)
void attn_scale(float* __restrict__ attn, const float* __restrict__ inv_g)
{
    int row = blockIdx.x;
    float iv = inv_g[row];
    float4* p = (float4*)(attn + (size_t)row*SS);
    int t = threadIdx.x;
    #pragma unroll
    for (int i = 0; i < SS/4/256; i++) {
        float4 v = p[t + 256*i];
        v.x *= iv; v.y *= iv; v.z *= iv; v.w *= iv;
        p[t + 256*i] = v;
    }
}

// ---------------------------------------------------------------------------
extern "C" void kernel_launch(void* const* d_in, const int* in_sizes, int n_in,
                              void* d_out, int out_size)
{
    const float* q    = (const float*)d_in[0];
    const float* k    = (const float*)d_in[1];
    const float* v    = (const float*)d_in[2];
    const int*   mask = (const int*)  d_in[3];
    const float* wq_w = (const float*)d_in[4];
    const float* wq_b = (const float*)d_in[5];
    const float* wk_w = (const float*)d_in[6];
    const float* wk_b = (const float*)d_in[7];
    const float* wv_w = (const float*)d_in[8];
    const float* wv_b = (const float*)d_in[9];
    const float* wo_w = (const float*)d_in[10];
    const float* wo_b = (const float*)d_in[11];

    float *qh_p, *kh_p, *vh_p, *o_p, *inv_p;
    cudaGetSymbolAddress((void**)&qh_p, g_qh);
    cudaGetSymbolAddress((void**)&kh_p, g_kh);
    cudaGetSymbolAddress((void**)&vh_p, g_vh);
    cudaGetSymbolAddress((void**)&o_p,  g_o);
    cudaGetSymbolAddress((void**)&inv_p, g_inv);

    const long OUT_E  = (long)BB*SS*DD;              // 4,194,304
    const long ATTN_E = (long)BB*HH*SS*(long)SS;     // 134,217,728
    float* out_ptr  = nullptr;
    float* attn_ptr = nullptr;
    if ((long)out_size >= OUT_E + ATTN_E) {
        out_ptr  = (float*)d_out;
        attn_ptr = (float*)d_out + OUT_E;
    } else if ((long)out_size >= ATTN_E) {
        attn_ptr = (float*)d_out;
    } else {
        out_ptr  = (float*)d_out;
    }

    cudaFuncSetAttribute(proj_tc<1>, cudaFuncAttributeMaxDynamicSharedMemorySize, PROJ_SMEM);
    cudaFuncSetAttribute(proj_tc<0>, cudaFuncAttributeMaxDynamicSharedMemorySize, PROJ_SMEM);
    dim3 pgrid(DD/64, MM/128);   // 16 x 32
    proj_tc<1><<<pgrid, 256, PROJ_SMEM>>>(q, wq_w, wq_b, qh_p);
    proj_tc<1><<<pgrid, 256, PROJ_SMEM>>>(k, wk_w, wk_b, kh_p);
    proj_tc<1><<<pgrid, 256, PROJ_SMEM>>>(v, wv_w, wv_b, vh_p);

    cudaFuncSetAttribute(attn_fused,
                         cudaFuncAttributeMaxDynamicSharedMemorySize, ATTN_SMEM);
    attn_fused<<<dim3(SS/32, HH, BB), 256, ATTN_SMEM>>>(
        qh_p, kh_p, vh_p, mask, attn_ptr, o_p, inv_p,
        attn_ptr != nullptr ? 1 : 0);

    if (attn_ptr)
        attn_scale<<<BB*HH*SS, 256>>>(attn_ptr, inv_p);

    if (out_ptr)
        proj_tc<0><<<pgrid, 256, PROJ_SMEM>>>(o_p, wo_w, wo_b, out_ptr);
}

// round 12
// speedup vs baseline: 1.9616x; 1.0744x over previous
#include <cuda_runtime.h>
#include <cstdint>

#define BB 2
#define SS 2048
#define DD 1024
#define HH 16
#define DK 64
#define MM (BB*SS)

// Scratch (device globals: allocation-free per harness rules)
__device__ float g_qh [(size_t)BB*HH*SS*DK];
__device__ float g_kh [(size_t)BB*HH*SS*DK];
__device__ float g_vh [(size_t)BB*HH*SS*DK];
__device__ float g_o  [(size_t)BB*SS*DD];
__device__ float g_inv[(size_t)BB*HH*SS];

// ---------------------------------------------------------------------------
// tf32 helpers
// ---------------------------------------------------------------------------
__device__ __forceinline__ uint32_t f2tf(float x){
    uint32_t r; asm("cvt.rna.tf32.f32 %0, %1;" : "=r"(r) : "f"(x)); return r;
}
__device__ __forceinline__ void split_tf(float x, uint32_t& hi, uint32_t& lo){
    hi = f2tf(x);
    lo = f2tf(x - __uint_as_float(hi));
}
__device__ __forceinline__ void mma8(float* d, const uint32_t* a, const uint32_t* b){
    asm volatile("mma.sync.aligned.m16n8k8.row.col.f32.tf32.tf32.f32 "
        "{%0,%1,%2,%3},{%4,%5,%6,%7},{%8,%9},{%0,%1,%2,%3};"
        : "+f"(d[0]),"+f"(d[1]),"+f"(d[2]),"+f"(d[3])
        : "r"(a[0]),"r"(a[1]),"r"(a[2]),"r"(a[3]),"r"(b[0]),"r"(b[1]));
}
__device__ __forceinline__ void cpa16(void* dst_smem, const void* src){
    uint32_t d = (uint32_t)__cvta_generic_to_shared(dst_smem);
    asm volatile("cp.async.cg.shared.global [%0], [%1], 16;" :: "r"(d), "l"(src));
}

// FFMA-pipe exp: e^x via 2^(x*log2e), degree-5 poly. Valid |x|<=80, rel ~5e-7.
__device__ __forceinline__ float exp_poly(float x){
    float y = x * 1.4426950408889634f;
    float t = y + 12582912.0f;
    int   n = __float_as_int(t) - 0x4B400000;
    float f = y - (t - 12582912.0f);
    float p =              1.33335581e-3f;
    p = fmaf(p, f, 9.61812910e-3f);
    p = fmaf(p, f, 5.55041087e-2f);
    p = fmaf(p, f, 2.40226507e-1f);
    p = fmaf(p, f, 6.93147180e-1f);
    p = fmaf(p, f, 1.0f);
    return __int_as_float(__float_as_int(p) + (n << 23));
}

// ---------------------------------------------------------------------------
// Projection GEMM: split-at-smem-store 3xTF32, register-prefetch pipeline.
// C[M,N] = A[M,K] * W[N,K]^T + bias.  Tile 128x64, BK=32, 256 thr, 8 warps.
// ---------------------------------------------------------------------------
#define PSTR 36
#define PROJ_SMEM ((2*128*PSTR + 2*64*PSTR) * 4)
template<int MODE>
__global__ __launch_bounds__(256)
void proj_tc(const float* __restrict__ A, const float* __restrict__ W,
             const float* __restrict__ bias, float* __restrict__ C)
{
    extern __shared__ uint32_t ps[];
    uint32_t* Ash = ps;
    uint32_t* Asl = Ash + 128*PSTR;
    uint32_t* Wsh = Asl + 128*PSTR;
    uint32_t* Wsl = Wsh + 64*PSTR;

    const int bm = blockIdx.y*128, bn = blockIdx.x*64;
    const int t = threadIdx.x, wid = t>>5, lane = t&31;
    const int qr = lane>>2, qc = lane&3;
    const int wm = (wid&3)*32, wn = (wid>>2)*32;
    const int lr = t>>3, lc = (t&7)*4;

    float acc[2][4][4] = {};

    const float* Abase = A + (size_t)(bm + lr)*DD + lc;
    const float* Wbase = W + (size_t)(bn + lr)*DD + lc;

    // register prefetch of kc=0
    float4 pa[4], pw[2];
    #pragma unroll
    for (int p = 0; p < 4; p++) pa[p] = *(const float4*)(Abase + (size_t)32*p*DD);
    #pragma unroll
    for (int p = 0; p < 2; p++) pw[p] = *(const float4*)(Wbase + (size_t)32*p*DD);

    for (int kc = 0; kc < DD; kc += 32) {
        __syncthreads();   // buffers free (prev compute done)
        #pragma unroll
        for (int p = 0; p < 4; p++) {
            int row = lr + 32*p;
            uint4 h4, l4;
            split_tf(pa[p].x, h4.x, l4.x); split_tf(pa[p].y, h4.y, l4.y);
            split_tf(pa[p].z, h4.z, l4.z); split_tf(pa[p].w, h4.w, l4.w);
            *(uint4*)(Ash + row*PSTR + lc) = h4;
            *(uint4*)(Asl + row*PSTR + lc) = l4;
        }
        #pragma unroll
        for (int p = 0; p < 2; p++) {
            int row = lr + 32*p;
            uint4 h4, l4;
            split_tf(pw[p].x, h4.x, l4.x); split_tf(pw[p].y, h4.y, l4.y);
            split_tf(pw[p].z, h4.z, l4.z); split_tf(pw[p].w, h4.w, l4.w);
            *(uint4*)(Wsh + row*PSTR + lc) = h4;
            *(uint4*)(Wsl + row*PSTR + lc) = l4;
        }
        __syncthreads();

        // issue next-iteration loads BEFORE the compute block (latency hidden)
        if (kc + 32 < DD) {
            #pragma unroll
            for (int p = 0; p < 4; p++)
                pa[p] = *(const float4*)(Abase + (size_t)32*p*DD + kc + 32);
            #pragma unroll
            for (int p = 0; p < 2; p++)
                pw[p] = *(const float4*)(Wbase + (size_t)32*p*DD + kc + 32);
        }

        #pragma unroll
        for (int ks = 0; ks < 4; ks++) {
            int k0 = ks*8;
            uint32_t ah[2][4], al[2][4], bh[4][2], bl[4][2];
            #pragma unroll
            for (int mi = 0; mi < 2; mi++) {
                int r0 = wm + 16*mi + qr;
                ah[mi][0] = Ash[ r0   *PSTR + k0+qc  ];
                ah[mi][1] = Ash[(r0+8)*PSTR + k0+qc  ];
                ah[mi][2] = Ash[ r0   *PSTR + k0+qc+4];
                ah[mi][3] = Ash[(r0+8)*PSTR + k0+qc+4];
                al[mi][0] = Asl[ r0   *PSTR + k0+qc  ];
                al[mi][1] = Asl[(r0+8)*PSTR + k0+qc  ];
                al[mi][2] = Asl[ r0   *PSTR + k0+qc+4];
                al[mi][3] = Asl[(r0+8)*PSTR + k0+qc+4];
            }
            #pragma unroll
            for (int ni = 0; ni < 4; ni++) {
                int rn = wn + 8*ni + qr;
                bh[ni][0] = Wsh[rn*PSTR + k0+qc  ];
                bh[ni][1] = Wsh[rn*PSTR + k0+qc+4];
                bl[ni][0] = Wsl[rn*PSTR + k0+qc  ];
                bl[ni][1] = Wsl[rn*PSTR + k0+qc+4];
            }
            #pragma unroll
            for (int mi = 0; mi < 2; mi++)
                #pragma unroll
                for (int ni = 0; ni < 4; ni++) {
                    mma8(acc[mi][ni], ah[mi], bh[ni]);
                    mma8(acc[mi][ni], ah[mi], bl[ni]);
                    mma8(acc[mi][ni], al[mi], bh[ni]);
                }
        }
    }
    #pragma unroll
    for (int mi = 0; mi < 2; mi++) {
        int r0 = bm + wm + 16*mi + qr;
        #pragma unroll
        for (int ni = 0; ni < 4; ni++) {
            int c0 = bn + wn + 8*ni + 2*qc;
            #pragma unroll
            for (int e = 0; e < 4; e++) {
                int m = r0 + ((e>=2) ? 8 : 0);
                int n = c0 + (e&1);
                float val = acc[mi][ni][e] + bias[n];
                if (MODE == 0) {
                    C[(size_t)m*DD + n] = val;
                } else {
                    int b = m/SS, s = m%SS, h = n/DK, dk = n%DK;
                    C[(((size_t)b*HH+h)*SS+s)*DK+dk] = val;
                }
            }
        }
    }
}

// ---------------------------------------------------------------------------
// Fused attention v4: as v3 but V staged raw via cp.async issued right after
// K is consumed (latency hidden behind exp/P-store/dump); f2tf at PV load.
// 32 q-rows per CTA, 256 threads, 8 warps, smem ~62KB -> 3 CTAs/SM.
// ---------------------------------------------------------------------------
#define KVP2 72
#define PCH  132
#define QSP  68
#define ATTN_SMEM ((128*KVP2 + 32*PCH + 32*QSP + 32*8 + 32) * (int)sizeof(float))

__global__ __launch_bounds__(256, 3)
void attn_fused(const float* __restrict__ qh, const float* __restrict__ kh,
                const float* __restrict__ vh, const int* __restrict__ mask,
                float* __restrict__ attn, float* __restrict__ o,
                float* __restrict__ inv_g, int write_attn)
{
    extern __shared__ float smem[];
    float*    KVs  = smem;                           // [128][KVP2]
    float*    Pch  = smem + 128*KVP2;                // [32][PCH]
    uint32_t* Qhi  = (uint32_t*)(Pch + 32*PCH);      // [32][QSP] tf32 of Q/8
    float*    red2 = (float*)(Qhi + 32*QSP);         // [32][8]
    float*    invs = red2 + 32*8;                    // [32]

    const int qt = blockIdx.x, h = blockIdx.y, b = blockIdx.z;
    const int t = threadIdx.x, w = t>>5, lane = t&31;
    const int qr = lane>>2, qc = lane&3;
    const int mh = w>>2, dw = (w>>1)&1, cw = w&1;    // PV roles

    const float* qbase = qh + (((size_t)b*HH+h)*SS + (size_t)qt*32)*DK;
    const float* kbase = kh + ((size_t)b*HH+h)*SS*DK;
    const float* vbase = vh + ((size_t)b*HH+h)*SS*DK;

    // load Q tile (32x64), pre-scaled by 1/8, tf32-hi only
    {
        int row = t>>3, col = (t&7)*8;
        #pragma unroll
        for (int u = 0; u < 2; u++) {
            float4 v4 = *(const float4*)(qbase + (size_t)row*DK + col + u*4);
            uint4 h4;
            h4.x = f2tf(0.125f*v4.x); h4.y = f2tf(0.125f*v4.y);
            h4.z = f2tf(0.125f*v4.z); h4.w = f2tf(0.125f*v4.w);
            *(uint4*)(Qhi + row*QSP + col + u*4) = h4;
        }
    }

    float s00 = 0.f, s01 = 0.f, s10 = 0.f, s11 = 0.f;   // row sums [mt][half]
    float oacc[4][4] = {};

    const int ldr = t>>4, ldc = (t&15)*4;   // K/V tile loader coords

    for (int kb = 0; kb < SS/128; kb++) {
        __syncthreads();   // prev chunk PV reads of KVs/Pch done (also Q init)
        #pragma unroll
        for (int p = 0; p < 8; p++)
            cpa16(&KVs[(ldr+16*p)*KVP2 + ldc],
                  kbase + (size_t)(kb*128 + ldr + 16*p)*DK + ldc);
        asm volatile("cp.async.commit_group;");
        asm volatile("cp.async.wait_group 0;");
        __syncthreads();

        // ---- scores: qh*(kh + kl), warp w cols [16w,+16), both M-tiles ----
        float acc[2][2][4] = {};
        #pragma unroll
        for (int ks = 0; ks < 8; ks++) {
            int k0 = ks*8;
            uint32_t kh_[2][2], kl_[2][2];
            #pragma unroll
            for (int ni = 0; ni < 2; ni++) {
                int rn = w*16 + 8*ni + qr;
                split_tf(KVs[rn*KVP2 + k0+qc  ], kh_[ni][0], kl_[ni][0]);
                split_tf(KVs[rn*KVP2 + k0+qc+4], kh_[ni][1], kl_[ni][1]);
            }
            #pragma unroll
            for (int mt = 0; mt < 2; mt++) {
                uint32_t qh4[4];
                qh4[0] = Qhi[(mt*16+qr  )*QSP + k0+qc  ];
                qh4[1] = Qhi[(mt*16+qr+8)*QSP + k0+qc  ];
                qh4[2] = Qhi[(mt*16+qr  )*QSP + k0+qc+4];
                qh4[3] = Qhi[(mt*16+qr+8)*QSP + k0+qc+4];
                #pragma unroll
                for (int ni = 0; ni < 2; ni++) {
                    mma8(acc[mt][ni], qh4, kh_[ni]);
                    mma8(acc[mt][ni], qh4, kl_[ni]);
                }
            }
        }
        __syncthreads();   // K fully consumed -> KVs free for V

        // ---- issue V cp.async now; latency hides behind exp/P-store/dump ----
        #pragma unroll
        for (int p = 0; p < 8; p++)
            cpa16(&KVs[(ldr+16*p)*KVP2 + ldc],
                  vbase + (size_t)(kb*128 + ldr + 16*p)*DK + ldc);
        asm volatile("cp.async.commit_group;");

        // ---- mask/exp, store P, dump unnormalized probs from registers ----
        #pragma unroll
        for (int mt = 0; mt < 2; mt++) {
            #pragma unroll
            for (int ni = 0; ni < 2; ni++) {
                int gl = w*16 + 8*ni + 2*qc;
                int gc = kb*128 + gl;
                int m0 = mask[(size_t)b*SS + gc];
                int m1 = mask[(size_t)b*SS + gc + 1];
                float v0 = m0 ? acc[mt][ni][0] : -1e9f;
                float v1 = m1 ? acc[mt][ni][1] : -1e9f;
                float v2 = m0 ? acc[mt][ni][2] : -1e9f;
                float v3 = m1 ? acc[mt][ni][3] : -1e9f;
                v0 = fminf(fmaxf(v0, -80.f), 80.f);
                v1 = fminf(fmaxf(v1, -80.f), 80.f);
                v2 = fminf(fmaxf(v2, -80.f), 80.f);
                v3 = fminf(fmaxf(v3, -80.f), 80.f);
                float e0 = __expf(v0);      // MUFU
                float e1 = exp_poly(v1);    // FMA
                float e2 = exp_poly(v2);
                float e3 = __expf(v3);
                if (mt == 0) { s00 += e0 + e1; s01 += e2 + e3; }
                else         { s10 += e0 + e1; s11 += e2 + e3; }
                Pch[(mt*16+qr  )*PCH + gl  ] = e0;
                Pch[(mt*16+qr  )*PCH + gl+1] = e1;
                Pch[(mt*16+qr+8)*PCH + gl  ] = e2;
                Pch[(mt*16+qr+8)*PCH + gl+1] = e3;
                if (write_attn) {
                    size_t ar0 = (((size_t)b*HH + h)*SS + (size_t)(qt*32 + mt*16 + qr))*SS + gc;
                    size_t ar1 = ar0 + (size_t)8*SS;
                    float2 p0 = make_float2(e0, e1);
                    float2 p1 = make_float2(e2, e3);
                    *(float2*)(attn + ar0) = p0;
                    *(float2*)(attn + ar1) = p1;
                }
            }
        }
        asm volatile("cp.async.wait_group 0;");
        __syncthreads();   // P ready + V visible

        // ---- PV: rows [16mh,+16), dk [32dw,+32), contraction [64cw,+64) ----
        #pragma unroll
        for (int ks = 0; ks < 8; ks++) {
            int j8 = cw*64 + ks*8;
            uint32_t ph[4], pl[4];
            split_tf(Pch[(mh*16+qr  )*PCH + j8+qc  ], ph[0], pl[0]);
            split_tf(Pch[(mh*16+qr+8)*PCH + j8+qc  ], ph[1], pl[1]);
            split_tf(Pch[(mh*16+qr  )*PCH + j8+qc+4], ph[2], pl[2]);
            split_tf(Pch[(mh*16+qr+8)*PCH + j8+qc+4], ph[3], pl[3]);
            #pragma unroll
            for (int ni = 0; ni < 4; ni++) {
                int n0 = dw*32 + ni*8 + qr;
                uint32_t vh2[2];
                vh2[0] = f2tf(KVs[(j8+qc  )*KVP2 + n0]);
                vh2[1] = f2tf(KVs[(j8+qc+4)*KVP2 + n0]);
                mma8(oacc[ni], ph, vh2);
                mma8(oacc[ni], pl, vh2);
            }
        }
    }

    // ---- row-sum reduction -> invs ----
    s00 += __shfl_xor_sync(0xffffffffu, s00, 1);
    s00 += __shfl_xor_sync(0xffffffffu, s00, 2);
    s01 += __shfl_xor_sync(0xffffffffu, s01, 1);
    s01 += __shfl_xor_sync(0xffffffffu, s01, 2);
    s10 += __shfl_xor_sync(0xffffffffu, s10, 1);
    s10 += __shfl_xor_sync(0xffffffffu, s10, 2);
    s11 += __shfl_xor_sync(0xffffffffu, s11, 1);
    s11 += __shfl_xor_sync(0xffffffffu, s11, 2);
    if (qc == 0) {
        red2[( qr   )*8 + w] = s00;
        red2[( qr+8 )*8 + w] = s01;
        red2[(16+qr  )*8 + w] = s10;
        red2[(16+qr+8)*8 + w] = s11;
    }
    __syncthreads();   // also: all PV reads of KVs done -> safe to reuse
    if (t < 32) {
        float s = 0.f;
        #pragma unroll
        for (int ww = 0; ww < 8; ww++) s += red2[t*8 + ww];
        float iv = 1.f / s;
        invs[t] = iv;
        inv_g[((size_t)b*HH + h)*SS + qt*32 + t] = iv;
    }

    // ---- O partial reduction through smem: redO[2cw][32][68] ----
    float* redO = KVs;
    #pragma unroll
    for (int ni = 0; ni < 4; ni++) {
        int c0 = dw*32 + ni*8 + 2*qc;
        redO[cw*32*68 + (mh*16+qr  )*68 + c0  ] = oacc[ni][0];
        redO[cw*32*68 + (mh*16+qr  )*68 + c0+1] = oacc[ni][1];
        redO[cw*32*68 + (mh*16+qr+8)*68 + c0  ] = oacc[ni][2];
        redO[cw*32*68 + (mh*16+qr+8)*68 + c0+1] = oacc[ni][3];
    }
    __syncthreads();
    {
        int row = t>>3, cb = (t&7)*8;
        float iv = invs[row];
        size_t orow = (size_t)b*SS + qt*32 + row;
        #pragma unroll
        for (int j = 0; j < 8; j++) {
            int col = cb + j;
            float s = redO[row*68 + col] + redO[32*68 + row*68 + col];
            o[orow*DD + h*DK + col] = s * iv;
        }
    }
}

// ---------------------------------------------------------------------------
// Normalize attention probs: attn[row, :] *= inv[row].  One block per row.
// ---------------------------------------------------------------------------
__global__ __launch_bounds__(256)
void attn_scale(float* __restrict__ attn, const float* __restrict__ inv_g)
{
    int row = blockIdx.x;
    float iv = inv_g[row];
    float4* p = (float4*)(attn + (size_t)row*SS);
    int t = threadIdx.x;
    #pragma unroll
    for (int i = 0; i < SS/4/256; i++) {
        float4 v = p[t + 256*i];
        v.x *= iv; v.y *= iv; v.z *= iv; v.w *= iv;
        p[t + 256*i] = v;
    }
}

// ---------------------------------------------------------------------------
extern "C" void kernel_launch(void* const* d_in, const int* in_sizes, int n_in,
                              void* d_out, int out_size)
{
    const float* q    = (const float*)d_in[0];
    const float* k    = (const float*)d_in[1];
    const float* v    = (const float*)d_in[2];
    const int*   mask = (const int*)  d_in[3];
    const float* wq_w = (const float*)d_in[4];
    const float* wq_b = (const float*)d_in[5];
    const float* wk_w = (const float*)d_in[6];
    const float* wk_b = (const float*)d_in[7];
    const float* wv_w = (const float*)d_in[8];
    const float* wv_b = (const float*)d_in[9];
    const float* wo_w = (const float*)d_in[10];
    const float* wo_b = (const float*)d_in[11];

    float *qh_p, *kh_p, *vh_p, *o_p, *inv_p;
    cudaGetSymbolAddress((void**)&qh_p, g_qh);
    cudaGetSymbolAddress((void**)&kh_p, g_kh);
    cudaGetSymbolAddress((void**)&vh_p, g_vh);
    cudaGetSymbolAddress((void**)&o_p,  g_o);
    cudaGetSymbolAddress((void**)&inv_p, g_inv);

    const long OUT_E  = (long)BB*SS*DD;              // 4,194,304
    const long ATTN_E = (long)BB*HH*SS*(long)SS;     // 134,217,728
    float* out_ptr  = nullptr;
    float* attn_ptr = nullptr;
    if ((long)out_size >= OUT_E + ATTN_E) {
        out_ptr  = (float*)d_out;
        attn_ptr = (float*)d_out + OUT_E;
    } else if ((long)out_size >= ATTN_E) {
        attn_ptr = (float*)d_out;
    } else {
        out_ptr  = (float*)d_out;
    }

    cudaFuncSetAttribute(proj_tc<1>, cudaFuncAttributeMaxDynamicSharedMemorySize, PROJ_SMEM);
    cudaFuncSetAttribute(proj_tc<0>, cudaFuncAttributeMaxDynamicSharedMemorySize, PROJ_SMEM);
    dim3 pgrid(DD/64, MM/128);   // 16 x 32
    proj_tc<1><<<pgrid, 256, PROJ_SMEM>>>(q, wq_w, wq_b, qh_p);
    proj_tc<1><<<pgrid, 256, PROJ_SMEM>>>(k, wk_w, wk_b, kh_p);
    proj_tc<1><<<pgrid, 256, PROJ_SMEM>>>(v, wv_w, wv_b, vh_p);

    cudaFuncSetAttribute(attn_fused,
                         cudaFuncAttributeMaxDynamicSharedMemorySize, ATTN_SMEM);
    attn_fused<<<dim3(SS/32, HH, BB), 256, ATTN_SMEM>>>(
        qh_p, kh_p, vh_p, mask, attn_ptr, o_p, inv_p,
        attn_ptr != nullptr ? 1 : 0);

    if (attn_ptr)
        attn_scale<<<BB*HH*SS, 256>>>(attn_ptr, inv_p);

    if (out_ptr)
        proj_tc<0><<<pgrid, 256, PROJ_SMEM>>>(o_p, wo_w, wo_b, out_ptr);
}

// round 13
// speedup vs baseline: 2.1180x; 1.0797x over previous
#include <cuda_runtime.h>
#include <cstdint>

#define BB 2
#define SS 2048
#define DD 1024
#define HH 16
#define DK 64
#define MM (BB*SS)

// Scratch (device globals: allocation-free per harness rules)
__device__ float g_qh [(size_t)BB*HH*SS*DK];
__device__ float g_kh [(size_t)BB*HH*SS*DK];
__device__ float g_vh [(size_t)BB*HH*SS*DK];
__device__ float g_o  [(size_t)BB*SS*DD];
__device__ float g_inv[(size_t)BB*HH*SS];

// ---------------------------------------------------------------------------
// tf32 helpers
// ---------------------------------------------------------------------------
__device__ __forceinline__ uint32_t f2tf(float x){
    uint32_t r; asm("cvt.rna.tf32.f32 %0, %1;" : "=r"(r) : "f"(x)); return r;
}
__device__ __forceinline__ void split_tf(float x, uint32_t& hi, uint32_t& lo){
    hi = f2tf(x);
    lo = f2tf(x - __uint_as_float(hi));
}
__device__ __forceinline__ void mma8(float* d, const uint32_t* a, const uint32_t* b){
    asm volatile("mma.sync.aligned.m16n8k8.row.col.f32.tf32.tf32.f32 "
        "{%0,%1,%2,%3},{%4,%5,%6,%7},{%8,%9},{%0,%1,%2,%3};"
        : "+f"(d[0]),"+f"(d[1]),"+f"(d[2]),"+f"(d[3])
        : "r"(a[0]),"r"(a[1]),"r"(a[2]),"r"(a[3]),"r"(b[0]),"r"(b[1]));
}
__device__ __forceinline__ void cpa16(void* dst_smem, const void* src){
    uint32_t d = (uint32_t)__cvta_generic_to_shared(dst_smem);
    asm volatile("cp.async.cg.shared.global [%0], [%1], 16;" :: "r"(d), "l"(src));
}

// FFMA-pipe exp: e^x via 2^(x*log2e), degree-5 poly. Valid |x|<=80, rel ~5e-7.
__device__ __forceinline__ float exp_poly(float x){
    float y = x * 1.4426950408889634f;
    float t = y + 12582912.0f;
    int   n = __float_as_int(t) - 0x4B400000;
    float f = y - (t - 12582912.0f);
    float p =              1.33335581e-3f;
    p = fmaf(p, f, 9.61812910e-3f);
    p = fmaf(p, f, 5.55041087e-2f);
    p = fmaf(p, f, 2.40226507e-1f);
    p = fmaf(p, f, 6.93147180e-1f);
    p = fmaf(p, f, 1.0f);
    return __int_as_float(__float_as_int(p) + (n << 23));
}

// ---------------------------------------------------------------------------
// Projection GEMM: split-at-smem-store, register-prefetch pipeline.
// TERMS=3: ah*bh + ah*bl + al*bh (Q/K proj, O proj — error-critical paths)
// TERMS=2: ah*bh + ah*bl         (V proj — error sqrtN-suppressed via PV)
// ---------------------------------------------------------------------------
#define PSTR 36
#define PROJ_SMEM3 ((2*128*PSTR + 2*64*PSTR) * 4)
#define PROJ_SMEM2 ((1*128*PSTR + 2*64*PSTR) * 4)
template<int MODE, int TERMS>
__global__ __launch_bounds__(256)
void proj_tc(const float* __restrict__ A, const float* __restrict__ W,
             const float* __restrict__ bias, float* __restrict__ C)
{
    extern __shared__ uint32_t ps[];
    uint32_t* Ash = ps;
    uint32_t* Asl = Ash + 128*PSTR;                          // TERMS==3 only
    uint32_t* Wsh = Ash + (TERMS==3 ? 2 : 1)*128*PSTR;
    uint32_t* Wsl = Wsh + 64*PSTR;

    const int bm = blockIdx.y*128, bn = blockIdx.x*64;
    const int t = threadIdx.x, wid = t>>5, lane = t&31;
    const int qr = lane>>2, qc = lane&3;
    const int wm = (wid&3)*32, wn = (wid>>2)*32;
    const int lr = t>>3, lc = (t&7)*4;

    float acc[2][4][4] = {};

    const float* Abase = A + (size_t)(bm + lr)*DD + lc;
    const float* Wbase = W + (size_t)(bn + lr)*DD + lc;

    float4 pa[4], pw[2];
    #pragma unroll
    for (int p = 0; p < 4; p++) pa[p] = *(const float4*)(Abase + (size_t)32*p*DD);
    #pragma unroll
    for (int p = 0; p < 2; p++) pw[p] = *(const float4*)(Wbase + (size_t)32*p*DD);

    for (int kc = 0; kc < DD; kc += 32) {
        __syncthreads();
        #pragma unroll
        for (int p = 0; p < 4; p++) {
            int row = lr + 32*p;
            uint4 h4, l4;
            split_tf(pa[p].x, h4.x, l4.x); split_tf(pa[p].y, h4.y, l4.y);
            split_tf(pa[p].z, h4.z, l4.z); split_tf(pa[p].w, h4.w, l4.w);
            *(uint4*)(Ash + row*PSTR + lc) = h4;
            if (TERMS == 3) *(uint4*)(Asl + row*PSTR + lc) = l4;
        }
        #pragma unroll
        for (int p = 0; p < 2; p++) {
            int row = lr + 32*p;
            uint4 h4, l4;
            split_tf(pw[p].x, h4.x, l4.x); split_tf(pw[p].y, h4.y, l4.y);
            split_tf(pw[p].z, h4.z, l4.z); split_tf(pw[p].w, h4.w, l4.w);
            *(uint4*)(Wsh + row*PSTR + lc) = h4;
            *(uint4*)(Wsl + row*PSTR + lc) = l4;
        }
        __syncthreads();

        if (kc + 32 < DD) {
            #pragma unroll
            for (int p = 0; p < 4; p++)
                pa[p] = *(const float4*)(Abase + (size_t)32*p*DD + kc + 32);
            #pragma unroll
            for (int p = 0; p < 2; p++)
                pw[p] = *(const float4*)(Wbase + (size_t)32*p*DD + kc + 32);
        }

        #pragma unroll
        for (int ks = 0; ks < 4; ks++) {
            int k0 = ks*8;
            uint32_t ah[2][4], al[2][4], bh[4][2], bl[4][2];
            #pragma unroll
            for (int mi = 0; mi < 2; mi++) {
                int r0 = wm + 16*mi + qr;
                ah[mi][0] = Ash[ r0   *PSTR + k0+qc  ];
                ah[mi][1] = Ash[(r0+8)*PSTR + k0+qc  ];
                ah[mi][2] = Ash[ r0   *PSTR + k0+qc+4];
                ah[mi][3] = Ash[(r0+8)*PSTR + k0+qc+4];
                if (TERMS == 3) {
                    al[mi][0] = Asl[ r0   *PSTR + k0+qc  ];
                    al[mi][1] = Asl[(r0+8)*PSTR + k0+qc  ];
                    al[mi][2] = Asl[ r0   *PSTR + k0+qc+4];
                    al[mi][3] = Asl[(r0+8)*PSTR + k0+qc+4];
                }
            }
            #pragma unroll
            for (int ni = 0; ni < 4; ni++) {
                int rn = wn + 8*ni + qr;
                bh[ni][0] = Wsh[rn*PSTR + k0+qc  ];
                bh[ni][1] = Wsh[rn*PSTR + k0+qc+4];
                bl[ni][0] = Wsl[rn*PSTR + k0+qc  ];
                bl[ni][1] = Wsl[rn*PSTR + k0+qc+4];
            }
            #pragma unroll
            for (int mi = 0; mi < 2; mi++)
                #pragma unroll
                for (int ni = 0; ni < 4; ni++) {
                    mma8(acc[mi][ni], ah[mi], bh[ni]);
                    mma8(acc[mi][ni], ah[mi], bl[ni]);
                    if (TERMS == 3) mma8(acc[mi][ni], al[mi], bh[ni]);
                }
        }
    }
    #pragma unroll
    for (int mi = 0; mi < 2; mi++) {
        int r0 = bm + wm + 16*mi + qr;
        #pragma unroll
        for (int ni = 0; ni < 4; ni++) {
            int c0 = bn + wn + 8*ni + 2*qc;
            #pragma unroll
            for (int e = 0; e < 4; e++) {
                int m = r0 + ((e>=2) ? 8 : 0);
                int n = c0 + (e&1);
                float val = acc[mi][ni][e] + bias[n];
                if (MODE == 0) {
                    C[(size_t)m*DD + n] = val;
                } else {
                    int b = m/SS, s = m%SS, h = n/DK, dk = n%DK;
                    C[(((size_t)b*HH+h)*SS+s)*DK+dk] = val;
                }
            }
        }
    }
}

// ---------------------------------------------------------------------------
// Fused attention v5: as v4 but PV uses 1-term P (f2tf only, no split).
// 32 q-rows per CTA, 256 threads, 8 warps, smem ~62KB -> 3 CTAs/SM.
// ---------------------------------------------------------------------------
#define KVP2 72
#define PCH  132
#define QSP  68
#define ATTN_SMEM ((128*KVP2 + 32*PCH + 32*QSP + 32*8 + 32) * (int)sizeof(float))

__global__ __launch_bounds__(256, 3)
void attn_fused(const float* __restrict__ qh, const float* __restrict__ kh,
                const float* __restrict__ vh, const int* __restrict__ mask,
                float* __restrict__ attn, float* __restrict__ o,
                float* __restrict__ inv_g, int write_attn)
{
    extern __shared__ float smem[];
    float*    KVs  = smem;                           // [128][KVP2]
    float*    Pch  = smem + 128*KVP2;                // [32][PCH]
    uint32_t* Qhi  = (uint32_t*)(Pch + 32*PCH);      // [32][QSP] tf32 of Q/8
    float*    red2 = (float*)(Qhi + 32*QSP);         // [32][8]
    float*    invs = red2 + 32*8;                    // [32]

    const int qt = blockIdx.x, h = blockIdx.y, b = blockIdx.z;
    const int t = threadIdx.x, w = t>>5, lane = t&31;
    const int qr = lane>>2, qc = lane&3;
    const int mh = w>>2, dw = (w>>1)&1, cw = w&1;    // PV roles

    const float* qbase = qh + (((size_t)b*HH+h)*SS + (size_t)qt*32)*DK;
    const float* kbase = kh + ((size_t)b*HH+h)*SS*DK;
    const float* vbase = vh + ((size_t)b*HH+h)*SS*DK;

    // load Q tile (32x64), pre-scaled by 1/8, tf32-hi only
    {
        int row = t>>3, col = (t&7)*8;
        #pragma unroll
        for (int u = 0; u < 2; u++) {
            float4 v4 = *(const float4*)(qbase + (size_t)row*DK + col + u*4);
            uint4 h4;
            h4.x = f2tf(0.125f*v4.x); h4.y = f2tf(0.125f*v4.y);
            h4.z = f2tf(0.125f*v4.z); h4.w = f2tf(0.125f*v4.w);
            *(uint4*)(Qhi + row*QSP + col + u*4) = h4;
        }
    }

    float s00 = 0.f, s01 = 0.f, s10 = 0.f, s11 = 0.f;   // row sums [mt][half]
    float oacc[4][4] = {};

    const int ldr = t>>4, ldc = (t&15)*4;   // K/V tile loader coords

    for (int kb = 0; kb < SS/128; kb++) {
        __syncthreads();   // prev chunk PV reads of KVs/Pch done (also Q init)
        #pragma unroll
        for (int p = 0; p < 8; p++)
            cpa16(&KVs[(ldr+16*p)*KVP2 + ldc],
                  kbase + (size_t)(kb*128 + ldr + 16*p)*DK + ldc);
        asm volatile("cp.async.commit_group;");
        asm volatile("cp.async.wait_group 0;");
        __syncthreads();

        // ---- scores: qh*(kh + kl), warp w cols [16w,+16), both M-tiles ----
        float acc[2][2][4] = {};
        #pragma unroll
        for (int ks = 0; ks < 8; ks++) {
            int k0 = ks*8;
            uint32_t kh_[2][2], kl_[2][2];
            #pragma unroll
            for (int ni = 0; ni < 2; ni++) {
                int rn = w*16 + 8*ni + qr;
                split_tf(KVs[rn*KVP2 + k0+qc  ], kh_[ni][0], kl_[ni][0]);
                split_tf(KVs[rn*KVP2 + k0+qc+4], kh_[ni][1], kl_[ni][1]);
            }
            #pragma unroll
            for (int mt = 0; mt < 2; mt++) {
                uint32_t qh4[4];
                qh4[0] = Qhi[(mt*16+qr  )*QSP + k0+qc  ];
                qh4[1] = Qhi[(mt*16+qr+8)*QSP + k0+qc  ];
                qh4[2] = Qhi[(mt*16+qr  )*QSP + k0+qc+4];
                qh4[3] = Qhi[(mt*16+qr+8)*QSP + k0+qc+4];
                #pragma unroll
                for (int ni = 0; ni < 2; ni++) {
                    mma8(acc[mt][ni], qh4, kh_[ni]);
                    mma8(acc[mt][ni], qh4, kl_[ni]);
                }
            }
        }
        __syncthreads();   // K fully consumed -> KVs free for V

        // ---- issue V cp.async now; latency hides behind exp/P-store/dump ----
        #pragma unroll
        for (int p = 0; p < 8; p++)
            cpa16(&KVs[(ldr+16*p)*KVP2 + ldc],
                  vbase + (size_t)(kb*128 + ldr + 16*p)*DK + ldc);
        asm volatile("cp.async.commit_group;");

        // ---- mask/exp, store P, dump unnormalized probs from registers ----
        #pragma unroll
        for (int mt = 0; mt < 2; mt++) {
            #pragma unroll
            for (int ni = 0; ni < 2; ni++) {
                int gl = w*16 + 8*ni + 2*qc;
                int gc = kb*128 + gl;
                int m0 = mask[(size_t)b*SS + gc];
                int m1 = mask[(size_t)b*SS + gc + 1];
                float v0 = m0 ? acc[mt][ni][0] : -1e9f;
                float v1 = m1 ? acc[mt][ni][1] : -1e9f;
                float v2 = m0 ? acc[mt][ni][2] : -1e9f;
                float v3 = m1 ? acc[mt][ni][3] : -1e9f;
                v0 = fminf(fmaxf(v0, -80.f), 80.f);
                v1 = fminf(fmaxf(v1, -80.f), 80.f);
                v2 = fminf(fmaxf(v2, -80.f), 80.f);
                v3 = fminf(fmaxf(v3, -80.f), 80.f);
                float e0 = __expf(v0);      // MUFU
                float e1 = exp_poly(v1);    // FMA
                float e2 = exp_poly(v2);
                float e3 = __expf(v3);
                if (mt == 0) { s00 += e0 + e1; s01 += e2 + e3; }
                else         { s10 += e0 + e1; s11 += e2 + e3; }
                Pch[(mt*16+qr  )*PCH + gl  ] = e0;
                Pch[(mt*16+qr  )*PCH + gl+1] = e1;
                Pch[(mt*16+qr+8)*PCH + gl  ] = e2;
                Pch[(mt*16+qr+8)*PCH + gl+1] = e3;
                if (write_attn) {
                    size_t ar0 = (((size_t)b*HH + h)*SS + (size_t)(qt*32 + mt*16 + qr))*SS + gc;
                    size_t ar1 = ar0 + (size_t)8*SS;
                    float2 p0 = make_float2(e0, e1);
                    float2 p1 = make_float2(e2, e3);
                    *(float2*)(attn + ar0) = p0;
                    *(float2*)(attn + ar1) = p1;
                }
            }
        }
        asm volatile("cp.async.wait_group 0;");
        __syncthreads();   // P ready + V visible

        // ---- PV (1-term P): rows [16mh,+16), dk [32dw,+32), contr [64cw,+64) ----
        #pragma unroll
        for (int ks = 0; ks < 8; ks++) {
            int j8 = cw*64 + ks*8;
            uint32_t ph[4];
            ph[0] = f2tf(Pch[(mh*16+qr  )*PCH + j8+qc  ]);
            ph[1] = f2tf(Pch[(mh*16+qr+8)*PCH + j8+qc  ]);
            ph[2] = f2tf(Pch[(mh*16+qr  )*PCH + j8+qc+4]);
            ph[3] = f2tf(Pch[(mh*16+qr+8)*PCH + j8+qc+4]);
            #pragma unroll
            for (int ni = 0; ni < 4; ni++) {
                int n0 = dw*32 + ni*8 + qr;
                uint32_t vh2[2];
                vh2[0] = f2tf(KVs[(j8+qc  )*KVP2 + n0]);
                vh2[1] = f2tf(KVs[(j8+qc+4)*KVP2 + n0]);
                mma8(oacc[ni], ph, vh2);
            }
        }
    }

    // ---- row-sum reduction -> invs ----
    s00 += __shfl_xor_sync(0xffffffffu, s00, 1);
    s00 += __shfl_xor_sync(0xffffffffu, s00, 2);
    s01 += __shfl_xor_sync(0xffffffffu, s01, 1);
    s01 += __shfl_xor_sync(0xffffffffu, s01, 2);
    s10 += __shfl_xor_sync(0xffffffffu, s10, 1);
    s10 += __shfl_xor_sync(0xffffffffu, s10, 2);
    s11 += __shfl_xor_sync(0xffffffffu, s11, 1);
    s11 += __shfl_xor_sync(0xffffffffu, s11, 2);
    if (qc == 0) {
        red2[( qr   )*8 + w] = s00;
        red2[( qr+8 )*8 + w] = s01;
        red2[(16+qr  )*8 + w] = s10;
        red2[(16+qr+8)*8 + w] = s11;
    }
    __syncthreads();   // also: all PV reads of KVs done -> safe to reuse
    if (t < 32) {
        float s = 0.f;
        #pragma unroll
        for (int ww = 0; ww < 8; ww++) s += red2[t*8 + ww];
        float iv = 1.f / s;
        invs[t] = iv;
        inv_g[((size_t)b*HH + h)*SS + qt*32 + t] = iv;
    }

    // ---- O partial reduction through smem: redO[2cw][32][68] ----
    float* redO = KVs;
    #pragma unroll
    for (int ni = 0; ni < 4; ni++) {
        int c0 = dw*32 + ni*8 + 2*qc;
        redO[cw*32*68 + (mh*16+qr  )*68 + c0  ] = oacc[ni][0];
        redO[cw*32*68 + (mh*16+qr  )*68 + c0+1] = oacc[ni][1];
        redO[cw*32*68 + (mh*16+qr+8)*68 + c0  ] = oacc[ni][2];
        redO[cw*32*68 + (mh*16+qr+8)*68 + c0+1] = oacc[ni][3];
    }
    __syncthreads();
    {
        int row = t>>3, cb = (t&7)*8;
        float iv = invs[row];
        size_t orow = (size_t)b*SS + qt*32 + row;
        #pragma unroll
        for (int j = 0; j < 8; j++) {
            int col = cb + j;
            float s = redO[row*68 + col] + redO[32*68 + row*68 + col];
            o[orow*DD + h*DK + col] = s * iv;
        }
    }
}

// ---------------------------------------------------------------------------
// Normalize attention probs: attn[row, :] *= inv[row].  One block per row.
// ---------------------------------------------------------------------------
__global__ __launch_bounds__(256)
void attn_scale(float* __restrict__ attn, const float* __restrict__ inv_g)
{
    int row = blockIdx.x;
    float iv = inv_g[row];
    float4* p = (float4*)(attn + (size_t)row*SS);
    int t = threadIdx.x;
    #pragma unroll
    for (int i = 0; i < SS/4/256; i++) {
        float4 v = p[t + 256*i];
        v.x *= iv; v.y *= iv; v.z *= iv; v.w *= iv;
        p[t + 256*i] = v;
    }
}

// ---------------------------------------------------------------------------
extern "C" void kernel_launch(void* const* d_in, const int* in_sizes, int n_in,
                              void* d_out, int out_size)
{
    const float* q    = (const float*)d_in[0];
    const float* k    = (const float*)d_in[1];
    const float* v    = (const float*)d_in[2];
    const int*   mask = (const int*)  d_in[3];
    const float* wq_w = (const float*)d_in[4];
    const float* wq_b = (const float*)d_in[5];
    const float* wk_w = (const float*)d_in[6];
    const float* wk_b = (const float*)d_in[7];
    const float* wv_w = (const float*)d_in[8];
    const float* wv_b = (const float*)d_in[9];
    const float* wo_w = (const float*)d_in[10];
    const float* wo_b = (const float*)d_in[11];

    float *qh_p, *kh_p, *vh_p, *o_p, *inv_p;
    cudaGetSymbolAddress((void**)&qh_p, g_qh);
    cudaGetSymbolAddress((void**)&kh_p, g_kh);
    cudaGetSymbolAddress((void**)&vh_p, g_vh);
    cudaGetSymbolAddress((void**)&o_p,  g_o);
    cudaGetSymbolAddress((void**)&inv_p, g_inv);

    // Lazily created side stream + events for scale ∥ out-proj overlap.
    // Created on the first (non-captured correctness) call; reused thereafter.
    static cudaStream_t s2 = nullptr;
    static cudaEvent_t  ev1 = nullptr, ev2 = nullptr;
    static int overlap_ok = -1;
    if (overlap_ok < 0) {
        overlap_ok = 1;
        if (cudaStreamCreateWithFlags(&s2, cudaStreamNonBlocking) != cudaSuccess) overlap_ok = 0;
        if (overlap_ok && cudaEventCreateWithFlags(&ev1, cudaEventDisableTiming) != cudaSuccess) overlap_ok = 0;
        if (overlap_ok && cudaEventCreateWithFlags(&ev2, cudaEventDisableTiming) != cudaSuccess) overlap_ok = 0;
    }

    const long OUT_E  = (long)BB*SS*DD;              // 4,194,304
    const long ATTN_E = (long)BB*HH*SS*(long)SS;     // 134,217,728
    float* out_ptr  = nullptr;
    float* attn_ptr = nullptr;
    if ((long)out_size >= OUT_E + ATTN_E) {
        out_ptr  = (float*)d_out;
        attn_ptr = (float*)d_out + OUT_E;
    } else if ((long)out_size >= ATTN_E) {
        attn_ptr = (float*)d_out;
    } else {
        out_ptr  = (float*)d_out;
    }

    cudaFuncSetAttribute((const void*)proj_tc<1,3>, cudaFuncAttributeMaxDynamicSharedMemorySize, PROJ_SMEM3);
    cudaFuncSetAttribute((const void*)proj_tc<1,2>, cudaFuncAttributeMaxDynamicSharedMemorySize, PROJ_SMEM2);
    cudaFuncSetAttribute((const void*)proj_tc<0,3>, cudaFuncAttributeMaxDynamicSharedMemorySize, PROJ_SMEM3);
    dim3 pgrid(DD/64, MM/128);   // 16 x 32
    proj_tc<1,3><<<pgrid, 256, PROJ_SMEM3>>>(q, wq_w, wq_b, qh_p);
    proj_tc<1,3><<<pgrid, 256, PROJ_SMEM3>>>(k, wk_w, wk_b, kh_p);
    proj_tc<1,2><<<pgrid, 256, PROJ_SMEM2>>>(v, wv_w, wv_b, vh_p);

    cudaFuncSetAttribute(attn_fused,
                         cudaFuncAttributeMaxDynamicSharedMemorySize, ATTN_SMEM);
    attn_fused<<<dim3(SS/32, HH, BB), 256, ATTN_SMEM>>>(
        qh_p, kh_p, vh_p, mask, attn_ptr, o_p, inv_p,
        attn_ptr != nullptr ? 1 : 0);

    if (attn_ptr && out_ptr && overlap_ok) {
        // fork: attn_scale on side stream, concurrent with out-projection
        cudaEventRecord(ev1, 0);
        cudaStreamWaitEvent(s2, ev1, 0);
        attn_scale<<<BB*HH*SS, 256, 0, s2>>>(attn_ptr, inv_p);
        cudaEventRecord(ev2, s2);
        proj_tc<0,3><<<pgrid, 256, PROJ_SMEM3>>>(o_p, wo_w, wo_b, out_ptr);
        cudaStreamWaitEvent(0, ev2, 0);   // join before capture ends
    } else {
        if (attn_ptr)
            attn_scale<<<BB*HH*SS, 256>>>(attn_ptr, inv_p);
        if (out_ptr)
            proj_tc<0,3><<<pgrid, 256, PROJ_SMEM3>>>(o_p, wo_w, wo_b, out_ptr);
    }
}

// round 15
// speedup vs baseline: 2.1405x; 1.0106x over previous
#include <cuda_runtime.h>
#include <cstdint>

#define BB 2
#define SS 2048
#define DD 1024
#define HH 16
#define DK 64
#define MM (BB*SS)

// Scratch (device globals: allocation-free per harness rules)
__device__ float g_qh [(size_t)BB*HH*SS*DK];
__device__ float g_kh [(size_t)BB*HH*SS*DK];
__device__ float g_vh [(size_t)BB*HH*SS*DK];
__device__ float g_o  [(size_t)BB*SS*DD];
__device__ float g_inv[(size_t)BB*HH*SS];

// ---------------------------------------------------------------------------
// tf32 helpers
// ---------------------------------------------------------------------------
__device__ __forceinline__ uint32_t f2tf(float x){
    uint32_t r; asm("cvt.rna.tf32.f32 %0, %1;" : "=r"(r) : "f"(x)); return r;
}
__device__ __forceinline__ void split_tf(float x, uint32_t& hi, uint32_t& lo){
    hi = f2tf(x);
    lo = f2tf(x - __uint_as_float(hi));
}
__device__ __forceinline__ void mma8(float* d, const uint32_t* a, const uint32_t* b){
    asm volatile("mma.sync.aligned.m16n8k8.row.col.f32.tf32.tf32.f32 "
        "{%0,%1,%2,%3},{%4,%5,%6,%7},{%8,%9},{%0,%1,%2,%3};"
        : "+f"(d[0]),"+f"(d[1]),"+f"(d[2]),"+f"(d[3])
        : "r"(a[0]),"r"(a[1]),"r"(a[2]),"r"(a[3]),"r"(b[0]),"r"(b[1]));
}
__device__ __forceinline__ void cpa16(void* dst_smem, const void* src){
    uint32_t d = (uint32_t)__cvta_generic_to_shared(dst_smem);
    asm volatile("cp.async.cg.shared.global [%0], [%1], 16;" :: "r"(d), "l"(src));
}

// FFMA-pipe exp: e^x via 2^(x*log2e), degree-4 Taylor, magic-constant round.
// Valid |x|<=80; rel err ~4e-5 (fine vs 1e-3 gate).
__device__ __forceinline__ float exp_poly(float x){
    float y = x * 1.4426950408889634f;
    float t = y + 12582912.0f;
    int   n = __float_as_int(t) - 0x4B400000;
    float f = y - (t - 12582912.0f);
    float p =              9.61812910e-3f;
    p = fmaf(p, f, 5.55041087e-2f);
    p = fmaf(p, f, 2.40226507e-1f);
    p = fmaf(p, f, 6.93147180e-1f);
    p = fmaf(p, f, 1.0f);
    return __int_as_float(__float_as_int(p) + (n << 23));
}

// ---------------------------------------------------------------------------
// Fused Q/K/V projection: grid.z selects (input, weight, bias, output).
// z==2 (V): 2-term MMA + epilogue tf32 pre-conversion (PV reads it raw).
// Split-at-smem-store, register-prefetch pipeline. Tile 128x64, BK=32.
// ---------------------------------------------------------------------------
#define PSTR 36
#define PROJ_SMEM3 ((2*128*PSTR + 2*64*PSTR) * 4)
__global__ __launch_bounds__(256)
void proj_qkv(const float* __restrict__ qi, const float* __restrict__ ki,
              const float* __restrict__ vi,
              const float* __restrict__ wq, const float* __restrict__ wk,
              const float* __restrict__ wv,
              const float* __restrict__ bq, const float* __restrict__ bk,
              const float* __restrict__ bv,
              float* __restrict__ cq, float* __restrict__ ck,
              float* __restrict__ cv)
{
    extern __shared__ uint32_t ps[];
    uint32_t* Ash = ps;
    uint32_t* Asl = Ash + 128*PSTR;
    uint32_t* Wsh = Ash + 2*128*PSTR;
    uint32_t* Wsl = Wsh + 64*PSTR;

    const int z = blockIdx.z;
    const float* A    = (z==0) ? qi : (z==1) ? ki : vi;
    const float* W    = (z==0) ? wq : (z==1) ? wk : wv;
    const float* bias = (z==0) ? bq : (z==1) ? bk : bv;
    float*       C    = (z==0) ? cq : (z==1) ? ck : cv;
    const bool vpath = (z==2);

    const int bm = blockIdx.y*128, bn = blockIdx.x*64;
    const int t = threadIdx.x, wid = t>>5, lane = t&31;
    const int qr = lane>>2, qc = lane&3;
    const int wm = (wid&3)*32, wn = (wid>>2)*32;
    const int lr = t>>3, lc = (t&7)*4;

    float acc[2][4][4] = {};

    const float* Abase = A + (size_t)(bm + lr)*DD + lc;
    const float* Wbase = W + (size_t)(bn + lr)*DD + lc;

    float4 pa[4], pw[2];
    #pragma unroll
    for (int p = 0; p < 4; p++) pa[p] = *(const float4*)(Abase + (size_t)32*p*DD);
    #pragma unroll
    for (int p = 0; p < 2; p++) pw[p] = *(const float4*)(Wbase + (size_t)32*p*DD);

    for (int kc = 0; kc < DD; kc += 32) {
        __syncthreads();
        #pragma unroll
        for (int p = 0; p < 4; p++) {
            int row = lr + 32*p;
            uint4 h4, l4;
            split_tf(pa[p].x, h4.x, l4.x); split_tf(pa[p].y, h4.y, l4.y);
            split_tf(pa[p].z, h4.z, l4.z); split_tf(pa[p].w, h4.w, l4.w);
            *(uint4*)(Ash + row*PSTR + lc) = h4;
            if (!vpath) *(uint4*)(Asl + row*PSTR + lc) = l4;
        }
        #pragma unroll
        for (int p = 0; p < 2; p++) {
            int row = lr + 32*p;
            uint4 h4, l4;
            split_tf(pw[p].x, h4.x, l4.x); split_tf(pw[p].y, h4.y, l4.y);
            split_tf(pw[p].z, h4.z, l4.z); split_tf(pw[p].w, h4.w, l4.w);
            *(uint4*)(Wsh + row*PSTR + lc) = h4;
            *(uint4*)(Wsl + row*PSTR + lc) = l4;
        }
        __syncthreads();

        if (kc + 32 < DD) {
            #pragma unroll
            for (int p = 0; p < 4; p++)
                pa[p] = *(const float4*)(Abase + (size_t)32*p*DD + kc + 32);
            #pragma unroll
            for (int p = 0; p < 2; p++)
                pw[p] = *(const float4*)(Wbase + (size_t)32*p*DD + kc + 32);
        }

        #pragma unroll
        for (int ks = 0; ks < 4; ks++) {
            int k0 = ks*8;
            uint32_t ah[2][4], al[2][4], bh[4][2], bl[4][2];
            #pragma unroll
            for (int mi = 0; mi < 2; mi++) {
                int r0 = wm + 16*mi + qr;
                ah[mi][0] = Ash[ r0   *PSTR + k0+qc  ];
                ah[mi][1] = Ash[(r0+8)*PSTR + k0+qc  ];
                ah[mi][2] = Ash[ r0   *PSTR + k0+qc+4];
                ah[mi][3] = Ash[(r0+8)*PSTR + k0+qc+4];
                if (!vpath) {
                    al[mi][0] = Asl[ r0   *PSTR + k0+qc  ];
                    al[mi][1] = Asl[(r0+8)*PSTR + k0+qc  ];
                    al[mi][2] = Asl[ r0   *PSTR + k0+qc+4];
                    al[mi][3] = Asl[(r0+8)*PSTR + k0+qc+4];
                }
            }
            #pragma unroll
            for (int ni = 0; ni < 4; ni++) {
                int rn = wn + 8*ni + qr;
                bh[ni][0] = Wsh[rn*PSTR + k0+qc  ];
                bh[ni][1] = Wsh[rn*PSTR + k0+qc+4];
                bl[ni][0] = Wsl[rn*PSTR + k0+qc  ];
                bl[ni][1] = Wsl[rn*PSTR + k0+qc+4];
            }
            #pragma unroll
            for (int mi = 0; mi < 2; mi++)
                #pragma unroll
                for (int ni = 0; ni < 4; ni++) {
                    mma8(acc[mi][ni], ah[mi], bh[ni]);
                    mma8(acc[mi][ni], ah[mi], bl[ni]);
                    if (!vpath) mma8(acc[mi][ni], al[mi], bh[ni]);
                }
        }
    }
    #pragma unroll
    for (int mi = 0; mi < 2; mi++) {
        int r0 = bm + wm + 16*mi + qr;
        #pragma unroll
        for (int ni = 0; ni < 4; ni++) {
            int c0 = bn + wn + 8*ni + 2*qc;
            #pragma unroll
            for (int e = 0; e < 4; e++) {
                int m = r0 + ((e>=2) ? 8 : 0);
                int n = c0 + (e&1);
                float val = acc[mi][ni][e] + bias[n];
                if (vpath) val = __uint_as_float(f2tf(val));  // pre-tf32 for PV
                int b = m/SS, s = m%SS, h = n/DK, dk = n%DK;
                C[(((size_t)b*HH+h)*SS+s)*DK+dk] = val;
            }
        }
    }
}

// ---------------------------------------------------------------------------
// Output projection (row-major store, 3-term) — as before.
// ---------------------------------------------------------------------------
__global__ __launch_bounds__(256)
void proj_out(const float* __restrict__ A, const float* __restrict__ W,
              const float* __restrict__ bias, float* __restrict__ C)
{
    extern __shared__ uint32_t ps[];
    uint32_t* Ash = ps;
    uint32_t* Asl = Ash + 128*PSTR;
    uint32_t* Wsh = Ash + 2*128*PSTR;
    uint32_t* Wsl = Wsh + 64*PSTR;

    const int bm = blockIdx.y*128, bn = blockIdx.x*64;
    const int t = threadIdx.x, wid = t>>5, lane = t&31;
    const int qr = lane>>2, qc = lane&3;
    const int wm = (wid&3)*32, wn = (wid>>2)*32;
    const int lr = t>>3, lc = (t&7)*4;

    float acc[2][4][4] = {};

    const float* Abase = A + (size_t)(bm + lr)*DD + lc;
    const float* Wbase = W + (size_t)(bn + lr)*DD + lc;

    float4 pa[4], pw[2];
    #pragma unroll
    for (int p = 0; p < 4; p++) pa[p] = *(const float4*)(Abase + (size_t)32*p*DD);
    #pragma unroll
    for (int p = 0; p < 2; p++) pw[p] = *(const float4*)(Wbase + (size_t)32*p*DD);

    for (int kc = 0; kc < DD; kc += 32) {
        __syncthreads();
        #pragma unroll
        for (int p = 0; p < 4; p++) {
            int row = lr + 32*p;
            uint4 h4, l4;
            split_tf(pa[p].x, h4.x, l4.x); split_tf(pa[p].y, h4.y, l4.y);
            split_tf(pa[p].z, h4.z, l4.z); split_tf(pa[p].w, h4.w, l4.w);
            *(uint4*)(Ash + row*PSTR + lc) = h4;
            *(uint4*)(Asl + row*PSTR + lc) = l4;
        }
        #pragma unroll
        for (int p = 0; p < 2; p++) {
            int row = lr + 32*p;
            uint4 h4, l4;
            split_tf(pw[p].x, h4.x, l4.x); split_tf(pw[p].y, h4.y, l4.y);
            split_tf(pw[p].z, h4.z, l4.z); split_tf(pw[p].w, h4.w, l4.w);
            *(uint4*)(Wsh + row*PSTR + lc) = h4;
            *(uint4*)(Wsl + row*PSTR + lc) = l4;
        }
        __syncthreads();

        if (kc + 32 < DD) {
            #pragma unroll
            for (int p = 0; p < 4; p++)
                pa[p] = *(const float4*)(Abase + (size_t)32*p*DD + kc + 32);
            #pragma unroll
            for (int p = 0; p < 2; p++)
                pw[p] = *(const float4*)(Wbase + (size_t)32*p*DD + kc + 32);
        }

        #pragma unroll
        for (int ks = 0; ks < 4; ks++) {
            int k0 = ks*8;
            uint32_t ah[2][4], al[2][4], bh[4][2], bl[4][2];
            #pragma unroll
            for (int mi = 0; mi < 2; mi++) {
                int r0 = wm + 16*mi + qr;
                ah[mi][0] = Ash[ r0   *PSTR + k0+qc  ];
                ah[mi][1] = Ash[(r0+8)*PSTR + k0+qc  ];
                ah[mi][2] = Ash[ r0   *PSTR + k0+qc+4];
                ah[mi][3] = Ash[(r0+8)*PSTR + k0+qc+4];
                al[mi][0] = Asl[ r0   *PSTR + k0+qc  ];
                al[mi][1] = Asl[(r0+8)*PSTR + k0+qc  ];
                al[mi][2] = Asl[ r0   *PSTR + k0+qc+4];
                al[mi][3] = Asl[(r0+8)*PSTR + k0+qc+4];
            }
            #pragma unroll
            for (int ni = 0; ni < 4; ni++) {
                int rn = wn + 8*ni + qr;
                bh[ni][0] = Wsh[rn*PSTR + k0+qc  ];
                bh[ni][1] = Wsh[rn*PSTR + k0+qc+4];
                bl[ni][0] = Wsl[rn*PSTR + k0+qc  ];
                bl[ni][1] = Wsl[rn*PSTR + k0+qc+4];
            }
            #pragma unroll
            for (int mi = 0; mi < 2; mi++)
                #pragma unroll
                for (int ni = 0; ni < 4; ni++) {
                    mma8(acc[mi][ni], ah[mi], bh[ni]);
                    mma8(acc[mi][ni], ah[mi], bl[ni]);
                    mma8(acc[mi][ni], al[mi], bh[ni]);
                }
        }
    }
    #pragma unroll
    for (int mi = 0; mi < 2; mi++) {
        int r0 = bm + wm + 16*mi + qr;
        #pragma unroll
        for (int ni = 0; ni < 4; ni++) {
            int c0 = bn + wn + 8*ni + 2*qc;
            #pragma unroll
            for (int e = 0; e < 4; e++) {
                int m = r0 + ((e>=2) ? 8 : 0);
                int n = c0 + (e&1);
                C[(size_t)m*DD + n] = acc[mi][ni][e] + bias[n];
            }
        }
    }
}

// ---------------------------------------------------------------------------
// Fused attention v6: exp mix rebalanced to ~3/8 MUFU / 5/8 poly (MUFU-pipe
// capacity model), V arrives pre-tf32 (no cvt in PV). Otherwise as v5.
// ---------------------------------------------------------------------------
#define KVP2 72
#define PCH  132
#define QSP  68
#define ATTN_SMEM ((128*KVP2 + 32*PCH + 32*QSP + 32*8 + 32) * (int)sizeof(float))

__global__ __launch_bounds__(256, 3)
void attn_fused(const float* __restrict__ qh, const float* __restrict__ kh,
                const float* __restrict__ vh, const int* __restrict__ mask,
                float* __restrict__ attn, float* __restrict__ o,
                float* __restrict__ inv_g, int write_attn)
{
    extern __shared__ float smem[];
    float*    KVs  = smem;                           // [128][KVP2]
    float*    Pch  = smem + 128*KVP2;                // [32][PCH]
    uint32_t* Qhi  = (uint32_t*)(Pch + 32*PCH);      // [32][QSP] tf32 of Q/8
    float*    red2 = (float*)(Qhi + 32*QSP);         // [32][8]
    float*    invs = red2 + 32*8;                    // [32]

    const int qt = blockIdx.x, h = blockIdx.y, b = blockIdx.z;
    const int t = threadIdx.x, w = t>>5, lane = t&31;
    const int qr = lane>>2, qc = lane&3;
    const int mh = w>>2, dw = (w>>1)&1, cw = w&1;    // PV roles

    const float* qbase = qh + (((size_t)b*HH+h)*SS + (size_t)qt*32)*DK;
    const float* kbase = kh + ((size_t)b*HH+h)*SS*DK;
    const float* vbase = vh + ((size_t)b*HH+h)*SS*DK;

    // load Q tile (32x64), pre-scaled by 1/8, tf32-hi only
    {
        int row = t>>3, col = (t&7)*8;
        #pragma unroll
        for (int u = 0; u < 2; u++) {
            float4 v4 = *(const float4*)(qbase + (size_t)row*DK + col + u*4);
            uint4 h4;
            h4.x = f2tf(0.125f*v4.x); h4.y = f2tf(0.125f*v4.y);
            h4.z = f2tf(0.125f*v4.z); h4.w = f2tf(0.125f*v4.w);
            *(uint4*)(Qhi + row*QSP + col + u*4) = h4;
        }
    }

    float s00 = 0.f, s01 = 0.f, s10 = 0.f, s11 = 0.f;   // row sums [mt][half]
    float oacc[4][4] = {};

    const int ldr = t>>4, ldc = (t&15)*4;   // K/V tile loader coords

    for (int kb = 0; kb < SS/128; kb++) {
        __syncthreads();   // prev chunk PV reads of KVs/Pch done (also Q init)
        #pragma unroll
        for (int p = 0; p < 8; p++)
            cpa16(&KVs[(ldr+16*p)*KVP2 + ldc],
                  kbase + (size_t)(kb*128 + ldr + 16*p)*DK + ldc);
        asm volatile("cp.async.commit_group;");
        asm volatile("cp.async.wait_group 0;");
        __syncthreads();

        // ---- scores: qh*(kh + kl), warp w cols [16w,+16), both M-tiles ----
        float acc[2][2][4] = {};
        #pragma unroll
        for (int ks = 0; ks < 8; ks++) {
            int k0 = ks*8;
            uint32_t kh_[2][2], kl_[2][2];
            #pragma unroll
            for (int ni = 0; ni < 2; ni++) {
                int rn = w*16 + 8*ni + qr;
                split_tf(KVs[rn*KVP2 + k0+qc  ], kh_[ni][0], kl_[ni][0]);
                split_tf(KVs[rn*KVP2 + k0+qc+4], kh_[ni][1], kl_[ni][1]);
            }
            #pragma unroll
            for (int mt = 0; mt < 2; mt++) {
                uint32_t qh4[4];
                qh4[0] = Qhi[(mt*16+qr  )*QSP + k0+qc  ];
                qh4[1] = Qhi[(mt*16+qr+8)*QSP + k0+qc  ];
                qh4[2] = Qhi[(mt*16+qr  )*QSP + k0+qc+4];
                qh4[3] = Qhi[(mt*16+qr+8)*QSP + k0+qc+4];
                #pragma unroll
                for (int ni = 0; ni < 2; ni++) {
                    mma8(acc[mt][ni], qh4, kh_[ni]);
                    mma8(acc[mt][ni], qh4, kl_[ni]);
                }
            }
        }
        __syncthreads();   // K fully consumed -> KVs free for V

        // ---- issue V cp.async now; latency hides behind exp/P-store/dump ----
        #pragma unroll
        for (int p = 0; p < 8; p++)
            cpa16(&KVs[(ldr+16*p)*KVP2 + ldc],
                  vbase + (size_t)(kb*128 + ldr + 16*p)*DK + ldc);
        asm volatile("cp.async.commit_group;");

        // ---- mask/exp (3/8 MUFU, 5/8 poly), store P, dump probs ----
        #pragma unroll
        for (int mt = 0; mt < 2; mt++) {
            #pragma unroll
            for (int ni = 0; ni < 2; ni++) {
                int g = mt*2 + ni;
                int gl = w*16 + 8*ni + 2*qc;
                int gc = kb*128 + gl;
                int m0 = mask[(size_t)b*SS + gc];
                int m1 = mask[(size_t)b*SS + gc + 1];
                float v0 = m0 ? acc[mt][ni][0] : -1e9f;
                float v1 = m1 ? acc[mt][ni][1] : -1e9f;
                float v2 = m0 ? acc[mt][ni][2] : -1e9f;
                float v3 = m1 ? acc[mt][ni][3] : -1e9f;
                v0 = fminf(fmaxf(v0, -80.f), 80.f);
                v1 = fminf(fmaxf(v1, -80.f), 80.f);
                v2 = fminf(fmaxf(v2, -80.f), 80.f);
                v3 = fminf(fmaxf(v3, -80.f), 80.f);
                float e0 = __expf(v0);                       // MUFU always
                float e1 = exp_poly(v1);
                float e2 = (g & 1) ? __expf(v2)              // MUFU in odd groups
                                   : exp_poly(v2);
                float e3 = exp_poly(v3);
                if (mt == 0) { s00 += e0 + e1; s01 += e2 + e3; }
                else         { s10 += e0 + e1; s11 += e2 + e3; }
                Pch[(mt*16+qr  )*PCH + gl  ] = e0;
                Pch[(mt*16+qr  )*PCH + gl+1] = e1;
                Pch[(mt*16+qr+8)*PCH + gl  ] = e2;
                Pch[(mt*16+qr+8)*PCH + gl+1] = e3;
                if (write_attn) {
                    size_t ar0 = (((size_t)b*HH + h)*SS + (size_t)(qt*32 + mt*16 + qr))*SS + gc;
                    size_t ar1 = ar0 + (size_t)8*SS;
                    float2 p0 = make_float2(e0, e1);
                    float2 p1 = make_float2(e2, e3);
                    *(float2*)(attn + ar0) = p0;
                    *(float2*)(attn + ar1) = p1;
                }
            }
        }
        asm volatile("cp.async.wait_group 0;");
        __syncthreads();   // P ready + V visible

        // ---- PV (V pre-tf32): rows [16mh,+16), dk [32dw,+32), contr [64cw,+64) ----
        #pragma unroll
        for (int ks = 0; ks < 8; ks++) {
            int j8 = cw*64 + ks*8;
            uint32_t ph[4];
            ph[0] = f2tf(Pch[(mh*16+qr  )*PCH + j8+qc  ]);
            ph[1] = f2tf(Pch[(mh*16+qr+8)*PCH + j8+qc  ]);
            ph[2] = f2tf(Pch[(mh*16+qr  )*PCH + j8+qc+4]);
            ph[3] = f2tf(Pch[(mh*16+qr+8)*PCH + j8+qc+4]);
            #pragma unroll
            for (int ni = 0; ni < 4; ni++) {
                int n0 = dw*32 + ni*8 + qr;
                uint32_t vh2[2];
                vh2[0] = __float_as_uint(KVs[(j8+qc  )*KVP2 + n0]);
                vh2[1] = __float_as_uint(KVs[(j8+qc+4)*KVP2 + n0]);
                mma8(oacc[ni], ph, vh2);
            }
        }
    }

    // ---- row-sum reduction -> invs ----
    s00 += __shfl_xor_sync(0xffffffffu, s00, 1);
    s00 += __shfl_xor_sync(0xffffffffu, s00, 2);
    s01 += __shfl_xor_sync(0xffffffffu, s01, 1);
    s01 += __shfl_xor_sync(0xffffffffu, s01, 2);
    s10 += __shfl_xor_sync(0xffffffffu, s10, 1);
    s10 += __shfl_xor_sync(0xffffffffu, s10, 2);
    s11 += __shfl_xor_sync(0xffffffffu, s11, 1);
    s11 += __shfl_xor_sync(0xffffffffu, s11, 2);
    if (qc == 0) {
        red2[( qr   )*8 + w] = s00;
        red2[( qr+8 )*8 + w] = s01;
        red2[(16+qr  )*8 + w] = s10;
        red2[(16+qr+8)*8 + w] = s11;
    }
    __syncthreads();   // also: all PV reads of KVs done -> safe to reuse
    if (t < 32) {
        float s = 0.f;
        #pragma unroll
        for (int ww = 0; ww < 8; ww++) s += red2[t*8 + ww];
        float iv = 1.f / s;
        invs[t] = iv;
        inv_g[((size_t)b*HH + h)*SS + qt*32 + t] = iv;
    }

    // ---- O partial reduction through smem: redO[2cw][32][68] ----
    float* redO = KVs;
    #pragma unroll
    for (int ni = 0; ni < 4; ni++) {
        int c0 = dw*32 + ni*8 + 2*qc;
        redO[cw*32*68 + (mh*16+qr  )*68 + c0  ] = oacc[ni][0];
        redO[cw*32*68 + (mh*16+qr  )*68 + c0+1] = oacc[ni][1];
        redO[cw*32*68 + (mh*16+qr+8)*68 + c0  ] = oacc[ni][2];
        redO[cw*32*68 + (mh*16+qr+8)*68 + c0+1] = oacc[ni][3];
    }
    __syncthreads();
    {
        int row = t>>3, cb = (t&7)*8;
        float iv = invs[row];
        size_t orow = (size_t)b*SS + qt*32 + row;
        #pragma unroll
        for (int j = 0; j < 8; j++) {
            int col = cb + j;
            float s = redO[row*68 + col] + redO[32*68 + row*68 + col];
            o[orow*DD + h*DK + col] = s * iv;
        }
    }
}

// ---------------------------------------------------------------------------
// Normalize attention probs: attn[row, :] *= inv[row].  One block per row.
// ---------------------------------------------------------------------------
__global__ __launch_bounds__(256)
void attn_scale(float* __restrict__ attn, const float* __restrict__ inv_g)
{
    int row = blockIdx.x;
    float iv = inv_g[row];
    float4* p = (float4*)(attn + (size_t)row*SS);
    int t = threadIdx.x;
    #pragma unroll
    for (int i = 0; i < SS/4/256; i++) {
        float4 v = p[t + 256*i];
        v.x *= iv; v.y *= iv; v.z *= iv; v.w *= iv;
        p[t + 256*i] = v;
    }
}

// ---------------------------------------------------------------------------
extern "C" void kernel_launch(void* const* d_in, const int* in_sizes, int n_in,
                              void* d_out, int out_size)
{
    const float* q    = (const float*)d_in[0];
    const float* k    = (const float*)d_in[1];
    const float* v    = (const float*)d_in[2];
    const int*   mask = (const int*)  d_in[3];
    const float* wq_w = (const float*)d_in[4];
    const float* wq_b = (const float*)d_in[5];
    const float* wk_w = (const float*)d_in[6];
    const float* wk_b = (const float*)d_in[7];
    const float* wv_w = (const float*)d_in[8];
    const float* wv_b = (const float*)d_in[9];
    const float* wo_w = (const float*)d_in[10];
    const float* wo_b = (const float*)d_in[11];

    float *qh_p, *kh_p, *vh_p, *o_p, *inv_p;
    cudaGetSymbolAddress((void**)&qh_p, g_qh);
    cudaGetSymbolAddress((void**)&kh_p, g_kh);
    cudaGetSymbolAddress((void**)&vh_p, g_vh);
    cudaGetSymbolAddress((void**)&o_p,  g_o);
    cudaGetSymbolAddress((void**)&inv_p, g_inv);

    // Lazily created side stream + events for scale ∥ out-proj overlap.
    static cudaStream_t s2 = nullptr;
    static cudaEvent_t  ev1 = nullptr, ev2 = nullptr;
    static int overlap_ok = -1;
    if (overlap_ok < 0) {
        overlap_ok = 1;
        if (cudaStreamCreateWithFlags(&s2, cudaStreamNonBlocking) != cudaSuccess) overlap_ok = 0;
        if (overlap_ok && cudaEventCreateWithFlags(&ev1, cudaEventDisableTiming) != cudaSuccess) overlap_ok = 0;
        if (overlap_ok && cudaEventCreateWithFlags(&ev2, cudaEventDisableTiming) != cudaSuccess) overlap_ok = 0;
    }

    const long OUT_E  = (long)BB*SS*DD;              // 4,194,304
    const long ATTN_E = (long)BB*HH*SS*(long)SS;     // 134,217,728
    float* out_ptr  = nullptr;
    float* attn_ptr = nullptr;
    if ((long)out_size >= OUT_E + ATTN_E) {
        out_ptr  = (float*)d_out;
        attn_ptr = (float*)d_out + OUT_E;
    } else if ((long)out_size >= ATTN_E) {
        attn_ptr = (float*)d_out;
    } else {
        out_ptr  = (float*)d_out;
    }

    cudaFuncSetAttribute(proj_qkv, cudaFuncAttributeMaxDynamicSharedMemorySize, PROJ_SMEM3);
    cudaFuncSetAttribute(proj_out, cudaFuncAttributeMaxDynamicSharedMemorySize, PROJ_SMEM3);

    // fused Q/K/V projection: one launch, grid.z selects the projection
    proj_qkv<<<dim3(DD/64, MM/128, 3), 256, PROJ_SMEM3>>>(
        q, k, v, wq_w, wk_w, wv_w, wq_b, wk_b, wv_b, qh_p, kh_p, vh_p);

    cudaFuncSetAttribute(attn_fused,
                         cudaFuncAttributeMaxDynamicSharedMemorySize, ATTN_SMEM);
    attn_fused<<<dim3(SS/32, HH, BB), 256, ATTN_SMEM>>>(
        qh_p, kh_p, vh_p, mask, attn_ptr, o_p, inv_p,
        attn_ptr != nullptr ? 1 : 0);

    dim3 pgrid(DD/64, MM/128);   // 16 x 32
    if (attn_ptr && out_ptr && overlap_ok) {
        cudaEventRecord(ev1, 0);
        cudaStreamWaitEvent(s2, ev1, 0);
        attn_scale<<<BB*HH*SS, 256, 0, s2>>>(attn_ptr, inv_p);
        cudaEventRecord(ev2, s2);
        proj_out<<<pgrid, 256, PROJ_SMEM3>>>(o_p, wo_w, wo_b, out_ptr);
        cudaStreamWaitEvent(0, ev2, 0);
    } else {
        if (attn_ptr)
            attn_scale<<<BB*HH*SS, 256>>>(attn_ptr, inv_p);
        if (out_ptr)
            proj_out<<<pgrid, 256, PROJ_SMEM3>>>(o_p, wo_w, wo_b, out_ptr);
    }
}

// round 16
// speedup vs baseline: 2.1604x; 1.0093x over previous
#include <cuda_runtime.h>
#include <cstdint>

#define BB 2
#define SS 2048
#define DD 1024
#define HH 16
#define DK 64
#define MM (BB*SS)

// Scratch (device globals: allocation-free per harness rules)
__device__ float g_qh [(size_t)BB*HH*SS*DK];
__device__ float g_kh [(size_t)BB*HH*SS*DK];
__device__ float g_vh [(size_t)BB*HH*SS*DK];
__device__ float g_o  [(size_t)BB*SS*DD];
__device__ float g_inv[(size_t)BB*HH*SS];

// ---------------------------------------------------------------------------
// tf32 helpers
// ---------------------------------------------------------------------------
__device__ __forceinline__ uint32_t f2tf(float x){
    uint32_t r; asm("cvt.rna.tf32.f32 %0, %1;" : "=r"(r) : "f"(x)); return r;
}
__device__ __forceinline__ void split_tf(float x, uint32_t& hi, uint32_t& lo){
    hi = f2tf(x);
    lo = f2tf(x - __uint_as_float(hi));
}
__device__ __forceinline__ void mma8(float* d, const uint32_t* a, const uint32_t* b){
    asm volatile("mma.sync.aligned.m16n8k8.row.col.f32.tf32.tf32.f32 "
        "{%0,%1,%2,%3},{%4,%5,%6,%7},{%8,%9},{%0,%1,%2,%3};"
        : "+f"(d[0]),"+f"(d[1]),"+f"(d[2]),"+f"(d[3])
        : "r"(a[0]),"r"(a[1]),"r"(a[2]),"r"(a[3]),"r"(b[0]),"r"(b[1]));
}
__device__ __forceinline__ void cpa16(void* dst_smem, const void* src){
    uint32_t d = (uint32_t)__cvta_generic_to_shared(dst_smem);
    asm volatile("cp.async.cg.shared.global [%0], [%1], 16;" :: "r"(d), "l"(src));
}

// FFMA-pipe exp: e^x via 2^(x*log2e), degree-4 Taylor, magic-constant round.
__device__ __forceinline__ float exp_poly(float x){
    float y = x * 1.4426950408889634f;
    float t = y + 12582912.0f;
    int   n = __float_as_int(t) - 0x4B400000;
    float f = y - (t - 12582912.0f);
    float p =              9.61812910e-3f;
    p = fmaf(p, f, 5.55041087e-2f);
    p = fmaf(p, f, 2.40226507e-1f);
    p = fmaf(p, f, 6.93147180e-1f);
    p = fmaf(p, f, 1.0f);
    return __int_as_float(__float_as_int(p) + (n << 23));
}

// ---------------------------------------------------------------------------
// Projection GEMM core, DOUBLE-BUFFERED split smem: one barrier per K-step.
//   iter: LDG(next) -> MMA(cur buf) -> split-store(next buf) -> sync
// Tile 128x64, BK=32, 256 threads (8 warps 4Mx2N).
// ---------------------------------------------------------------------------
#define PSTR 36
#define PBUF ((2*128 + 2*64)*PSTR)                 // one buffer (u32 words)
#define PROJ_SMEM (2*PBUF*4)                       // 110592 B

// ---- fused Q/K/V projection (z selects path; z==2 is V: 2-term + pre-tf32)
__global__ __launch_bounds__(256)
void proj_qkv(const float* __restrict__ qi, const float* __restrict__ ki,
              const float* __restrict__ vi,
              const float* __restrict__ wq, const float* __restrict__ wk,
              const float* __restrict__ wv,
              const float* __restrict__ bq, const float* __restrict__ bk,
              const float* __restrict__ bv,
              float* __restrict__ cq, float* __restrict__ ck,
              float* __restrict__ cv)
{
    extern __shared__ uint32_t ps[];

    const int z = blockIdx.z;
    const float* A    = (z==0) ? qi : (z==1) ? ki : vi;
    const float* W    = (z==0) ? wq : (z==1) ? wk : wv;
    const float* bias = (z==0) ? bq : (z==1) ? bk : bv;
    float*       C    = (z==0) ? cq : (z==1) ? ck : cv;
    const bool vpath = (z==2);

    const int bm = blockIdx.y*128, bn = blockIdx.x*64;
    const int t = threadIdx.x, wid = t>>5, lane = t&31;
    const int qr = lane>>2, qc = lane&3;
    const int wm = (wid&3)*32, wn = (wid>>2)*32;
    const int lr = t>>3, lc = (t&7)*4;

    float acc[2][4][4] = {};

    const float* Abase = A + (size_t)(bm + lr)*DD + lc;
    const float* Wbase = W + (size_t)(bn + lr)*DD + lc;

    float4 pa[4], pw[2];
    #pragma unroll
    for (int p = 0; p < 4; p++) pa[p] = *(const float4*)(Abase + (size_t)32*p*DD);
    #pragma unroll
    for (int p = 0; p < 2; p++) pw[p] = *(const float4*)(Wbase + (size_t)32*p*DD);

    // prologue: store kc=0 into buffer 0
    {
        uint32_t* Ash = ps;
        uint32_t* Asl = Ash + 128*PSTR;
        uint32_t* Wsh = Ash + 2*128*PSTR;
        uint32_t* Wsl = Wsh + 64*PSTR;
        #pragma unroll
        for (int p = 0; p < 4; p++) {
            int row = lr + 32*p;
            uint4 h4, l4;
            split_tf(pa[p].x, h4.x, l4.x); split_tf(pa[p].y, h4.y, l4.y);
            split_tf(pa[p].z, h4.z, l4.z); split_tf(pa[p].w, h4.w, l4.w);
            *(uint4*)(Ash + row*PSTR + lc) = h4;
            if (!vpath) *(uint4*)(Asl + row*PSTR + lc) = l4;
        }
        #pragma unroll
        for (int p = 0; p < 2; p++) {
            int row = lr + 32*p;
            uint4 h4, l4;
            split_tf(pw[p].x, h4.x, l4.x); split_tf(pw[p].y, h4.y, l4.y);
            split_tf(pw[p].z, h4.z, l4.z); split_tf(pw[p].w, h4.w, l4.w);
            *(uint4*)(Wsh + row*PSTR + lc) = h4;
            *(uint4*)(Wsl + row*PSTR + lc) = l4;
        }
    }
    __syncthreads();

    for (int kc = 0; kc < DD; kc += 32) {
        const int cur = (kc>>5)&1, nxt = cur^1;
        uint32_t* Ash = ps + cur*PBUF;
        uint32_t* Asl = Ash + 128*PSTR;
        uint32_t* Wsh = Ash + 2*128*PSTR;
        uint32_t* Wsl = Wsh + 64*PSTR;

        const bool more = (kc + 32 < DD);
        if (more) {
            #pragma unroll
            for (int p = 0; p < 4; p++)
                pa[p] = *(const float4*)(Abase + (size_t)32*p*DD + kc + 32);
            #pragma unroll
            for (int p = 0; p < 2; p++)
                pw[p] = *(const float4*)(Wbase + (size_t)32*p*DD + kc + 32);
        }

        #pragma unroll
        for (int ks = 0; ks < 4; ks++) {
            int k0 = ks*8;
            uint32_t ah[2][4], al[2][4], bh[4][2], bl[4][2];
            #pragma unroll
            for (int mi = 0; mi < 2; mi++) {
                int r0 = wm + 16*mi + qr;
                ah[mi][0] = Ash[ r0   *PSTR + k0+qc  ];
                ah[mi][1] = Ash[(r0+8)*PSTR + k0+qc  ];
                ah[mi][2] = Ash[ r0   *PSTR + k0+qc+4];
                ah[mi][3] = Ash[(r0+8)*PSTR + k0+qc+4];
                if (!vpath) {
                    al[mi][0] = Asl[ r0   *PSTR + k0+qc  ];
                    al[mi][1] = Asl[(r0+8)*PSTR + k0+qc  ];
                    al[mi][2] = Asl[ r0   *PSTR + k0+qc+4];
                    al[mi][3] = Asl[(r0+8)*PSTR + k0+qc+4];
                }
            }
            #pragma unroll
            for (int ni = 0; ni < 4; ni++) {
                int rn = wn + 8*ni + qr;
                bh[ni][0] = Wsh[rn*PSTR + k0+qc  ];
                bh[ni][1] = Wsh[rn*PSTR + k0+qc+4];
                bl[ni][0] = Wsl[rn*PSTR + k0+qc  ];
                bl[ni][1] = Wsl[rn*PSTR + k0+qc+4];
            }
            #pragma unroll
            for (int mi = 0; mi < 2; mi++)
                #pragma unroll
                for (int ni = 0; ni < 4; ni++) {
                    mma8(acc[mi][ni], ah[mi], bh[ni]);
                    mma8(acc[mi][ni], ah[mi], bl[ni]);
                    if (!vpath) mma8(acc[mi][ni], al[mi], bh[ni]);
                }
        }

        if (more) {
            uint32_t* Ash2 = ps + nxt*PBUF;
            uint32_t* Asl2 = Ash2 + 128*PSTR;
            uint32_t* Wsh2 = Ash2 + 2*128*PSTR;
            uint32_t* Wsl2 = Wsh2 + 64*PSTR;
            #pragma unroll
            for (int p = 0; p < 4; p++) {
                int row = lr + 32*p;
                uint4 h4, l4;
                split_tf(pa[p].x, h4.x, l4.x); split_tf(pa[p].y, h4.y, l4.y);
                split_tf(pa[p].z, h4.z, l4.z); split_tf(pa[p].w, h4.w, l4.w);
                *(uint4*)(Ash2 + row*PSTR + lc) = h4;
                if (!vpath) *(uint4*)(Asl2 + row*PSTR + lc) = l4;
            }
            #pragma unroll
            for (int p = 0; p < 2; p++) {
                int row = lr + 32*p;
                uint4 h4, l4;
                split_tf(pw[p].x, h4.x, l4.x); split_tf(pw[p].y, h4.y, l4.y);
                split_tf(pw[p].z, h4.z, l4.z); split_tf(pw[p].w, h4.w, l4.w);
                *(uint4*)(Wsh2 + row*PSTR + lc) = h4;
                *(uint4*)(Wsl2 + row*PSTR + lc) = l4;
            }
        }
        __syncthreads();
    }

    #pragma unroll
    for (int mi = 0; mi < 2; mi++) {
        int r0 = bm + wm + 16*mi + qr;
        #pragma unroll
        for (int ni = 0; ni < 4; ni++) {
            int c0 = bn + wn + 8*ni + 2*qc;
            #pragma unroll
            for (int e = 0; e < 4; e++) {
                int m = r0 + ((e>=2) ? 8 : 0);
                int n = c0 + (e&1);
                float val = acc[mi][ni][e] + bias[n];
                if (vpath) val = __uint_as_float(f2tf(val));  // pre-tf32 for PV
                int b = m/SS, s = m%SS, h = n/DK, dk = n%DK;
                C[(((size_t)b*HH+h)*SS+s)*DK+dk] = val;
            }
        }
    }
}

// ---- output projection (row-major store, 3-term), same double-buffering ----
__global__ __launch_bounds__(256)
void proj_out(const float* __restrict__ A, const float* __restrict__ W,
              const float* __restrict__ bias, float* __restrict__ C)
{
    extern __shared__ uint32_t ps[];

    const int bm = blockIdx.y*128, bn = blockIdx.x*64;
    const int t = threadIdx.x, wid = t>>5, lane = t&31;
    const int qr = lane>>2, qc = lane&3;
    const int wm = (wid&3)*32, wn = (wid>>2)*32;
    const int lr = t>>3, lc = (t&7)*4;

    float acc[2][4][4] = {};

    const float* Abase = A + (size_t)(bm + lr)*DD + lc;
    const float* Wbase = W + (size_t)(bn + lr)*DD + lc;

    float4 pa[4], pw[2];
    #pragma unroll
    for (int p = 0; p < 4; p++) pa[p] = *(const float4*)(Abase + (size_t)32*p*DD);
    #pragma unroll
    for (int p = 0; p < 2; p++) pw[p] = *(const float4*)(Wbase + (size_t)32*p*DD);

    {
        uint32_t* Ash = ps;
        uint32_t* Asl = Ash + 128*PSTR;
        uint32_t* Wsh = Ash + 2*128*PSTR;
        uint32_t* Wsl = Wsh + 64*PSTR;
        #pragma unroll
        for (int p = 0; p < 4; p++) {
            int row = lr + 32*p;
            uint4 h4, l4;
            split_tf(pa[p].x, h4.x, l4.x); split_tf(pa[p].y, h4.y, l4.y);
            split_tf(pa[p].z, h4.z, l4.z); split_tf(pa[p].w, h4.w, l4.w);
            *(uint4*)(Ash + row*PSTR + lc) = h4;
            *(uint4*)(Asl + row*PSTR + lc) = l4;
        }
        #pragma unroll
        for (int p = 0; p < 2; p++) {
            int row = lr + 32*p;
            uint4 h4, l4;
            split_tf(pw[p].x, h4.x, l4.x); split_tf(pw[p].y, h4.y, l4.y);
            split_tf(pw[p].z, h4.z, l4.z); split_tf(pw[p].w, h4.w, l4.w);
            *(uint4*)(Wsh + row*PSTR + lc) = h4;
            *(uint4*)(Wsl + row*PSTR + lc) = l4;
        }
    }
    __syncthreads();

    for (int kc = 0; kc < DD; kc += 32) {
        const int cur = (kc>>5)&1, nxt = cur^1;
        uint32_t* Ash = ps + cur*PBUF;
        uint32_t* Asl = Ash + 128*PSTR;
        uint32_t* Wsh = Ash + 2*128*PSTR;
        uint32_t* Wsl = Wsh + 64*PSTR;

        const bool more = (kc + 32 < DD);
        if (more) {
            #pragma unroll
            for (int p = 0; p < 4; p++)
                pa[p] = *(const float4*)(Abase + (size_t)32*p*DD + kc + 32);
            #pragma unroll
            for (int p = 0; p < 2; p++)
                pw[p] = *(const float4*)(Wbase + (size_t)32*p*DD + kc + 32);
        }

        #pragma unroll
        for (int ks = 0; ks < 4; ks++) {
            int k0 = ks*8;
            uint32_t ah[2][4], al[2][4], bh[4][2], bl[4][2];
            #pragma unroll
            for (int mi = 0; mi < 2; mi++) {
                int r0 = wm + 16*mi + qr;
                ah[mi][0] = Ash[ r0   *PSTR + k0+qc  ];
                ah[mi][1] = Ash[(r0+8)*PSTR + k0+qc  ];
                ah[mi][2] = Ash[ r0   *PSTR + k0+qc+4];
                ah[mi][3] = Ash[(r0+8)*PSTR + k0+qc+4];
                al[mi][0] = Asl[ r0   *PSTR + k0+qc  ];
                al[mi][1] = Asl[(r0+8)*PSTR + k0+qc  ];
                al[mi][2] = Asl[ r0   *PSTR + k0+qc+4];
                al[mi][3] = Asl[(r0+8)*PSTR + k0+qc+4];
            }
            #pragma unroll
            for (int ni = 0; ni < 4; ni++) {
                int rn = wn + 8*ni + qr;
                bh[ni][0] = Wsh[rn*PSTR + k0+qc  ];
                bh[ni][1] = Wsh[rn*PSTR + k0+qc+4];
                bl[ni][0] = Wsl[rn*PSTR + k0+qc  ];
                bl[ni][1] = Wsl[rn*PSTR + k0+qc+4];
            }
            #pragma unroll
            for (int mi = 0; mi < 2; mi++)
                #pragma unroll
                for (int ni = 0; ni < 4; ni++) {
                    mma8(acc[mi][ni], ah[mi], bh[ni]);
                    mma8(acc[mi][ni], ah[mi], bl[ni]);
                    mma8(acc[mi][ni], al[mi], bh[ni]);
                }
        }

        if (more) {
            uint32_t* Ash2 = ps + nxt*PBUF;
            uint32_t* Asl2 = Ash2 + 128*PSTR;
            uint32_t* Wsh2 = Ash2 + 2*128*PSTR;
            uint32_t* Wsl2 = Wsh2 + 64*PSTR;
            #pragma unroll
            for (int p = 0; p < 4; p++) {
                int row = lr + 32*p;
                uint4 h4, l4;
                split_tf(pa[p].x, h4.x, l4.x); split_tf(pa[p].y, h4.y, l4.y);
                split_tf(pa[p].z, h4.z, l4.z); split_tf(pa[p].w, h4.w, l4.w);
                *(uint4*)(Ash2 + row*PSTR + lc) = h4;
                *(uint4*)(Asl2 + row*PSTR + lc) = l4;
            }
            #pragma unroll
            for (int p = 0; p < 2; p++) {
                int row = lr + 32*p;
                uint4 h4, l4;
                split_tf(pw[p].x, h4.x, l4.x); split_tf(pw[p].y, h4.y, l4.y);
                split_tf(pw[p].z, h4.z, l4.z); split_tf(pw[p].w, h4.w, l4.w);
                *(uint4*)(Wsh2 + row*PSTR + lc) = h4;
                *(uint4*)(Wsl2 + row*PSTR + lc) = l4;
            }
        }
        __syncthreads();
    }

    #pragma unroll
    for (int mi = 0; mi < 2; mi++) {
        int r0 = bm + wm + 16*mi + qr;
        #pragma unroll
        for (int ni = 0; ni < 4; ni++) {
            int c0 = bn + wn + 8*ni + 2*qc;
            #pragma unroll
            for (int e = 0; e < 4; e++) {
                int m = r0 + ((e>=2) ? 8 : 0);
                int n = c0 + (e&1);
                C[(size_t)m*DD + n] = acc[mi][ni][e] + bias[n];
            }
        }
    }
}

// ---------------------------------------------------------------------------
// Fused attention v7: as v6, but masked scores write -80 directly (clamps
// removed). V arrives pre-tf32. 32 q-rows/CTA, 256 thr, 3 CTAs/SM.
// ---------------------------------------------------------------------------
#define KVP2 72
#define PCH  132
#define QSP  68
#define ATTN_SMEM ((128*KVP2 + 32*PCH + 32*QSP + 32*8 + 32) * (int)sizeof(float))

__global__ __launch_bounds__(256, 3)
void attn_fused(const float* __restrict__ qh, const float* __restrict__ kh,
                const float* __restrict__ vh, const int* __restrict__ mask,
                float* __restrict__ attn, float* __restrict__ o,
                float* __restrict__ inv_g, int write_attn)
{
    extern __shared__ float smem[];
    float*    KVs  = smem;                           // [128][KVP2]
    float*    Pch  = smem + 128*KVP2;                // [32][PCH]
    uint32_t* Qhi  = (uint32_t*)(Pch + 32*PCH);      // [32][QSP] tf32 of Q/8
    float*    red2 = (float*)(Qhi + 32*QSP);         // [32][8]
    float*    invs = red2 + 32*8;                    // [32]

    const int qt = blockIdx.x, h = blockIdx.y, b = blockIdx.z;
    const int t = threadIdx.x, w = t>>5, lane = t&31;
    const int qr = lane>>2, qc = lane&3;
    const int mh = w>>2, dw = (w>>1)&1, cw = w&1;    // PV roles

    const float* qbase = qh + (((size_t)b*HH+h)*SS + (size_t)qt*32)*DK;
    const float* kbase = kh + ((size_t)b*HH+h)*SS*DK;
    const float* vbase = vh + ((size_t)b*HH+h)*SS*DK;

    // load Q tile (32x64), pre-scaled by 1/8, tf32-hi only
    {
        int row = t>>3, col = (t&7)*8;
        #pragma unroll
        for (int u = 0; u < 2; u++) {
            float4 v4 = *(const float4*)(qbase + (size_t)row*DK + col + u*4);
            uint4 h4;
            h4.x = f2tf(0.125f*v4.x); h4.y = f2tf(0.125f*v4.y);
            h4.z = f2tf(0.125f*v4.z); h4.w = f2tf(0.125f*v4.w);
            *(uint4*)(Qhi + row*QSP + col + u*4) = h4;
        }
    }

    float s00 = 0.f, s01 = 0.f, s10 = 0.f, s11 = 0.f;   // row sums [mt][half]
    float oacc[4][4] = {};

    const int ldr = t>>4, ldc = (t&15)*4;   // K/V tile loader coords

    for (int kb = 0; kb < SS/128; kb++) {
        __syncthreads();   // prev chunk PV reads of KVs/Pch done (also Q init)
        #pragma unroll
        for (int p = 0; p < 8; p++)
            cpa16(&KVs[(ldr+16*p)*KVP2 + ldc],
                  kbase + (size_t)(kb*128 + ldr + 16*p)*DK + ldc);
        asm volatile("cp.async.commit_group;");
        asm volatile("cp.async.wait_group 0;");
        __syncthreads();

        // ---- scores: qh*(kh + kl), warp w cols [16w,+16), both M-tiles ----
        float acc[2][2][4] = {};
        #pragma unroll
        for (int ks = 0; ks < 8; ks++) {
            int k0 = ks*8;
            uint32_t kh_[2][2], kl_[2][2];
            #pragma unroll
            for (int ni = 0; ni < 2; ni++) {
                int rn = w*16 + 8*ni + qr;
                split_tf(KVs[rn*KVP2 + k0+qc  ], kh_[ni][0], kl_[ni][0]);
                split_tf(KVs[rn*KVP2 + k0+qc+4], kh_[ni][1], kl_[ni][1]);
            }
            #pragma unroll
            for (int mt = 0; mt < 2; mt++) {
                uint32_t qh4[4];
                qh4[0] = Qhi[(mt*16+qr  )*QSP + k0+qc  ];
                qh4[1] = Qhi[(mt*16+qr+8)*QSP + k0+qc  ];
                qh4[2] = Qhi[(mt*16+qr  )*QSP + k0+qc+4];
                qh4[3] = Qhi[(mt*16+qr+8)*QSP + k0+qc+4];
                #pragma unroll
                for (int ni = 0; ni < 2; ni++) {
                    mma8(acc[mt][ni], qh4, kh_[ni]);
                    mma8(acc[mt][ni], qh4, kl_[ni]);
                }
            }
        }
        __syncthreads();   // K fully consumed -> KVs free for V

        // ---- issue V cp.async now; latency hides behind exp/P-store/dump ----
        #pragma unroll
        for (int p = 0; p < 8; p++)
            cpa16(&KVs[(ldr+16*p)*KVP2 + ldc],
                  vbase + (size_t)(kb*128 + ldr + 16*p)*DK + ldc);
        asm volatile("cp.async.commit_group;");

        // ---- mask/exp (3/8 MUFU, 5/8 poly), store P, dump probs ----
        #pragma unroll
        for (int mt = 0; mt < 2; mt++) {
            #pragma unroll
            for (int ni = 0; ni < 2; ni++) {
                int g = mt*2 + ni;
                int gl = w*16 + 8*ni + 2*qc;
                int gc = kb*128 + gl;
                int m0 = mask[(size_t)b*SS + gc];
                int m1 = mask[(size_t)b*SS + gc + 1];
                float v0 = m0 ? acc[mt][ni][0] : -80.f;
                float v1 = m1 ? acc[mt][ni][1] : -80.f;
                float v2 = m0 ? acc[mt][ni][2] : -80.f;
                float v3 = m1 ? acc[mt][ni][3] : -80.f;
                float e0 = __expf(v0);                       // MUFU always
                float e1 = exp_poly(v1);
                float e2 = (g & 1) ? __expf(v2)              // MUFU in odd groups
                                   : exp_poly(v2);
                float e3 = exp_poly(v3);
                if (mt == 0) { s00 += e0 + e1; s01 += e2 + e3; }
                else         { s10 += e0 + e1; s11 += e2 + e3; }
                Pch[(mt*16+qr  )*PCH + gl  ] = e0;
                Pch[(mt*16+qr  )*PCH + gl+1] = e1;
                Pch[(mt*16+qr+8)*PCH + gl  ] = e2;
                Pch[(mt*16+qr+8)*PCH + gl+1] = e3;
                if (write_attn) {
                    size_t ar0 = (((size_t)b*HH + h)*SS + (size_t)(qt*32 + mt*16 + qr))*SS + gc;
                    size_t ar1 = ar0 + (size_t)8*SS;
                    float2 p0 = make_float2(e0, e1);
                    float2 p1 = make_float2(e2, e3);
                    *(float2*)(attn + ar0) = p0;
                    *(float2*)(attn + ar1) = p1;
                }
            }
        }
        asm volatile("cp.async.wait_group 0;");
        __syncthreads();   // P ready + V visible

        // ---- PV (V pre-tf32): rows [16mh,+16), dk [32dw,+32), contr [64cw,+64) ----
        #pragma unroll
        for (int ks = 0; ks < 8; ks++) {
            int j8 = cw*64 + ks*8;
            uint32_t ph[4];
            ph[0] = f2tf(Pch[(mh*16+qr  )*PCH + j8+qc  ]);
            ph[1] = f2tf(Pch[(mh*16+qr+8)*PCH + j8+qc  ]);
            ph[2] = f2tf(Pch[(mh*16+qr  )*PCH + j8+qc+4]);
            ph[3] = f2tf(Pch[(mh*16+qr+8)*PCH + j8+qc+4]);
            #pragma unroll
            for (int ni = 0; ni < 4; ni++) {
                int n0 = dw*32 + ni*8 + qr;
                uint32_t vh2[2];
                vh2[0] = __float_as_uint(KVs[(j8+qc  )*KVP2 + n0]);
                vh2[1] = __float_as_uint(KVs[(j8+qc+4)*KVP2 + n0]);
                mma8(oacc[ni], ph, vh2);
            }
        }
    }

    // ---- row-sum reduction -> invs ----
    s00 += __shfl_xor_sync(0xffffffffu, s00, 1);
    s00 += __shfl_xor_sync(0xffffffffu, s00, 2);
    s01 += __shfl_xor_sync(0xffffffffu, s01, 1);
    s01 += __shfl_xor_sync(0xffffffffu, s01, 2);
    s10 += __shfl_xor_sync(0xffffffffu, s10, 1);
    s10 += __shfl_xor_sync(0xffffffffu, s10, 2);
    s11 += __shfl_xor_sync(0xffffffffu, s11, 1);
    s11 += __shfl_xor_sync(0xffffffffu, s11, 2);
    if (qc == 0) {
        red2[( qr   )*8 + w] = s00;
        red2[( qr+8 )*8 + w] = s01;
        red2[(16+qr  )*8 + w] = s10;
        red2[(16+qr+8)*8 + w] = s11;
    }
    __syncthreads();   // also: all PV reads of KVs done -> safe to reuse
    if (t < 32) {
        float s = 0.f;
        #pragma unroll
        for (int ww = 0; ww < 8; ww++) s += red2[t*8 + ww];
        float iv = 1.f / s;
        invs[t] = iv;
        inv_g[((size_t)b*HH + h)*SS + qt*32 + t] = iv;
    }

    // ---- O partial reduction through smem: redO[2cw][32][68] ----
    float* redO = KVs;
    #pragma unroll
    for (int ni = 0; ni < 4; ni++) {
        int c0 = dw*32 + ni*8 + 2*qc;
        redO[cw*32*68 + (mh*16+qr  )*68 + c0  ] = oacc[ni][0];
        redO[cw*32*68 + (mh*16+qr  )*68 + c0+1] = oacc[ni][1];
        redO[cw*32*68 + (mh*16+qr+8)*68 + c0  ] = oacc[ni][2];
        redO[cw*32*68 + (mh*16+qr+8)*68 + c0+1] = oacc[ni][3];
    }
    __syncthreads();
    {
        int row = t>>3, cb = (t&7)*8;
        float iv = invs[row];
        size_t orow = (size_t)b*SS + qt*32 + row;
        #pragma unroll
        for (int j = 0; j < 8; j++) {
            int col = cb + j;
            float s = redO[row*68 + col] + redO[32*68 + row*68 + col];
            o[orow*DD + h*DK + col] = s * iv;
        }
    }
}

// ---------------------------------------------------------------------------
// Normalize attention probs: attn[row, :] *= inv[row].  One block per row.
// ---------------------------------------------------------------------------
__global__ __launch_bounds__(256)
void attn_scale(float* __restrict__ attn, const float* __restrict__ inv_g)
{
    int row = blockIdx.x;
    float iv = inv_g[row];
    float4* p = (float4*)(attn + (size_t)row*SS);
    int t = threadIdx.x;
    #pragma unroll
    for (int i = 0; i < SS/4/256; i++) {
        float4 v = p[t + 256*i];
        v.x *= iv; v.y *= iv; v.z *= iv; v.w *= iv;
        p[t + 256*i] = v;
    }
}

// ---------------------------------------------------------------------------
extern "C" void kernel_launch(void* const* d_in, const int* in_sizes, int n_in,
                              void* d_out, int out_size)
{
    const float* q    = (const float*)d_in[0];
    const float* k    = (const float*)d_in[1];
    const float* v    = (const float*)d_in[2];
    const int*   mask = (const int*)  d_in[3];
    const float* wq_w = (const float*)d_in[4];
    const float* wq_b = (const float*)d_in[5];
    const float* wk_w = (const float*)d_in[6];
    const float* wk_b = (const float*)d_in[7];
    const float* wv_w = (const float*)d_in[8];
    const float* wv_b = (const float*)d_in[9];
    const float* wo_w = (const float*)d_in[10];
    const float* wo_b = (const float*)d_in[11];

    float *qh_p, *kh_p, *vh_p, *o_p, *inv_p;
    cudaGetSymbolAddress((void**)&qh_p, g_qh);
    cudaGetSymbolAddress((void**)&kh_p, g_kh);
    cudaGetSymbolAddress((void**)&vh_p, g_vh);
    cudaGetSymbolAddress((void**)&o_p,  g_o);
    cudaGetSymbolAddress((void**)&inv_p, g_inv);

    // Lazily created side stream + events for scale ∥ out-proj overlap.
    static cudaStream_t s2 = nullptr;
    static cudaEvent_t  ev1 = nullptr, ev2 = nullptr;
    static int overlap_ok = -1;
    if (overlap_ok < 0) {
        overlap_ok = 1;
        if (cudaStreamCreateWithFlags(&s2, cudaStreamNonBlocking) != cudaSuccess) overlap_ok = 0;
        if (overlap_ok && cudaEventCreateWithFlags(&ev1, cudaEventDisableTiming) != cudaSuccess) overlap_ok = 0;
        if (overlap_ok && cudaEventCreateWithFlags(&ev2, cudaEventDisableTiming) != cudaSuccess) overlap_ok = 0;
    }

    const long OUT_E  = (long)BB*SS*DD;              // 4,194,304
    const long ATTN_E = (long)BB*HH*SS*(long)SS;     // 134,217,728
    float* out_ptr  = nullptr;
    float* attn_ptr = nullptr;
    if ((long)out_size >= OUT_E + ATTN_E) {
        out_ptr  = (float*)d_out;
        attn_ptr = (float*)d_out + OUT_E;
    } else if ((long)out_size >= ATTN_E) {
        attn_ptr = (float*)d_out;
    } else {
        out_ptr  = (float*)d_out;
    }

    cudaFuncSetAttribute(proj_qkv, cudaFuncAttributeMaxDynamicSharedMemorySize, PROJ_SMEM);
    cudaFuncSetAttribute(proj_out, cudaFuncAttributeMaxDynamicSharedMemorySize, PROJ_SMEM);

    // fused Q/K/V projection: one launch, grid.z selects the projection
    proj_qkv<<<dim3(DD/64, MM/128, 3), 256, PROJ_SMEM>>>(
        q, k, v, wq_w, wk_w, wv_w, wq_b, wk_b, wv_b, qh_p, kh_p, vh_p);

    cudaFuncSetAttribute(attn_fused,
                         cudaFuncAttributeMaxDynamicSharedMemorySize, ATTN_SMEM);
    attn_fused<<<dim3(SS/32, HH, BB), 256, ATTN_SMEM>>>(
        qh_p, kh_p, vh_p, mask, attn_ptr, o_p, inv_p,
        attn_ptr != nullptr ? 1 : 0);

    dim3 pgrid(DD/64, MM/128);   // 16 x 32
    if (attn_ptr && out_ptr && overlap_ok) {
        cudaEventRecord(ev1, 0);
        cudaStreamWaitEvent(s2, ev1, 0);
        attn_scale<<<BB*HH*SS, 256, 0, s2>>>(attn_ptr, inv_p);
        cudaEventRecord(ev2, s2);
        proj_out<<<pgrid, 256, PROJ_SMEM>>>(o_p, wo_w, wo_b, out_ptr);
        cudaStreamWaitEvent(0, ev2, 0);
    } else {
        if (attn_ptr)
            attn_scale<<<BB*HH*SS, 256>>>(attn_ptr, inv_p);
        if (out_ptr)
            proj_out<<<pgrid, 256, PROJ_SMEM>>>(o_p, wo_w, wo_b, out_ptr);
    }
}

// round 17
// speedup vs baseline: 2.3120x; 1.0702x over previous
#include <cuda_runtime.h>
#include <cstdint>

#define BB 2
#define SS 2048
#define DD 1024
#define HH 16
#define DK 64
#define MM (BB*SS)

// Scratch (device globals: allocation-free per harness rules)
__device__ float g_qh [(size_t)BB*HH*SS*DK];
__device__ float g_kh [(size_t)BB*HH*SS*DK];
__device__ float g_vh [(size_t)BB*HH*SS*DK];
__device__ float g_o  [(size_t)BB*SS*DD];

// ---------------------------------------------------------------------------
// tf32 helpers
// ---------------------------------------------------------------------------
__device__ __forceinline__ uint32_t f2tf(float x){
    uint32_t r; asm("cvt.rna.tf32.f32 %0, %1;" : "=r"(r) : "f"(x)); return r;
}
__device__ __forceinline__ void split_tf(float x, uint32_t& hi, uint32_t& lo){
    hi = f2tf(x);
    lo = f2tf(x - __uint_as_float(hi));
}
__device__ __forceinline__ void mma8(float* d, const uint32_t* a, const uint32_t* b){
    asm volatile("mma.sync.aligned.m16n8k8.row.col.f32.tf32.tf32.f32 "
        "{%0,%1,%2,%3},{%4,%5,%6,%7},{%8,%9},{%0,%1,%2,%3};"
        : "+f"(d[0]),"+f"(d[1]),"+f"(d[2]),"+f"(d[3])
        : "r"(a[0]),"r"(a[1]),"r"(a[2]),"r"(a[3]),"r"(b[0]),"r"(b[1]));
}
__device__ __forceinline__ void cpa16(void* dst_smem, const void* src){
    uint32_t d = (uint32_t)__cvta_generic_to_shared(dst_smem);
    asm volatile("cp.async.cg.shared.global [%0], [%1], 16;" :: "r"(d), "l"(src));
}

// FFMA-pipe exp: e^x via 2^(x*log2e), degree-4 Taylor, magic-constant round.
__device__ __forceinline__ float exp_poly(float x){
    float y = x * 1.4426950408889634f;
    float t = y + 12582912.0f;
    int   n = __float_as_int(t) - 0x4B400000;
    float f = y - (t - 12582912.0f);
    float p =              9.61812910e-3f;
    p = fmaf(p, f, 5.55041087e-2f);
    p = fmaf(p, f, 2.40226507e-1f);
    p = fmaf(p, f, 6.93147180e-1f);
    p = fmaf(p, f, 1.0f);
    return __int_as_float(__float_as_int(p) + (n << 23));
}

// ---------------------------------------------------------------------------
// Fused Q/K/V projection (single-buffer, register-prefetch — R15 form).
// z==2 (V): 2-term MMA + epilogue tf32 pre-conversion (PV reads it raw).
// ---------------------------------------------------------------------------
#define PSTR 36
#define PROJ_SMEM3 ((2*128*PSTR + 2*64*PSTR) * 4)
__global__ __launch_bounds__(256)
void proj_qkv(const float* __restrict__ qi, const float* __restrict__ ki,
              const float* __restrict__ vi,
              const float* __restrict__ wq, const float* __restrict__ wk,
              const float* __restrict__ wv,
              const float* __restrict__ bq, const float* __restrict__ bk,
              const float* __restrict__ bv,
              float* __restrict__ cq, float* __restrict__ ck,
              float* __restrict__ cv)
{
    extern __shared__ uint32_t ps[];
    uint32_t* Ash = ps;
    uint32_t* Asl = Ash + 128*PSTR;
    uint32_t* Wsh = Ash + 2*128*PSTR;
    uint32_t* Wsl = Wsh + 64*PSTR;

    const int z = blockIdx.z;
    const float* A    = (z==0) ? qi : (z==1) ? ki : vi;
    const float* W    = (z==0) ? wq : (z==1) ? wk : wv;
    const float* bias = (z==0) ? bq : (z==1) ? bk : bv;
    float*       C    = (z==0) ? cq : (z==1) ? ck : cv;
    const bool vpath = (z==2);

    const int bm = blockIdx.y*128, bn = blockIdx.x*64;
    const int t = threadIdx.x, wid = t>>5, lane = t&31;
    const int qr = lane>>2, qc = lane&3;
    const int wm = (wid&3)*32, wn = (wid>>2)*32;
    const int lr = t>>3, lc = (t&7)*4;

    float acc[2][4][4] = {};

    const float* Abase = A + (size_t)(bm + lr)*DD + lc;
    const float* Wbase = W + (size_t)(bn + lr)*DD + lc;

    float4 pa[4], pw[2];
    #pragma unroll
    for (int p = 0; p < 4; p++) pa[p] = *(const float4*)(Abase + (size_t)32*p*DD);
    #pragma unroll
    for (int p = 0; p < 2; p++) pw[p] = *(const float4*)(Wbase + (size_t)32*p*DD);

    for (int kc = 0; kc < DD; kc += 32) {
        __syncthreads();
        #pragma unroll
        for (int p = 0; p < 4; p++) {
            int row = lr + 32*p;
            uint4 h4, l4;
            split_tf(pa[p].x, h4.x, l4.x); split_tf(pa[p].y, h4.y, l4.y);
            split_tf(pa[p].z, h4.z, l4.z); split_tf(pa[p].w, h4.w, l4.w);
            *(uint4*)(Ash + row*PSTR + lc) = h4;
            if (!vpath) *(uint4*)(Asl + row*PSTR + lc) = l4;
        }
        #pragma unroll
        for (int p = 0; p < 2; p++) {
            int row = lr + 32*p;
            uint4 h4, l4;
            split_tf(pw[p].x, h4.x, l4.x); split_tf(pw[p].y, h4.y, l4.y);
            split_tf(pw[p].z, h4.z, l4.z); split_tf(pw[p].w, h4.w, l4.w);
            *(uint4*)(Wsh + row*PSTR + lc) = h4;
            *(uint4*)(Wsl + row*PSTR + lc) = l4;
        }
        __syncthreads();

        if (kc + 32 < DD) {
            #pragma unroll
            for (int p = 0; p < 4; p++)
                pa[p] = *(const float4*)(Abase + (size_t)32*p*DD + kc + 32);
            #pragma unroll
            for (int p = 0; p < 2; p++)
                pw[p] = *(const float4*)(Wbase + (size_t)32*p*DD + kc + 32);
        }

        #pragma unroll
        for (int ks = 0; ks < 4; ks++) {
            int k0 = ks*8;
            uint32_t ah[2][4], al[2][4], bh[4][2], bl[4][2];
            #pragma unroll
            for (int mi = 0; mi < 2; mi++) {
                int r0 = wm + 16*mi + qr;
                ah[mi][0] = Ash[ r0   *PSTR + k0+qc  ];
                ah[mi][1] = Ash[(r0+8)*PSTR + k0+qc  ];
                ah[mi][2] = Ash[ r0   *PSTR + k0+qc+4];
                ah[mi][3] = Ash[(r0+8)*PSTR + k0+qc+4];
                if (!vpath) {
                    al[mi][0] = Asl[ r0   *PSTR + k0+qc  ];
                    al[mi][1] = Asl[(r0+8)*PSTR + k0+qc  ];
                    al[mi][2] = Asl[ r0   *PSTR + k0+qc+4];
                    al[mi][3] = Asl[(r0+8)*PSTR + k0+qc+4];
                }
            }
            #pragma unroll
            for (int ni = 0; ni < 4; ni++) {
                int rn = wn + 8*ni + qr;
                bh[ni][0] = Wsh[rn*PSTR + k0+qc  ];
                bh[ni][1] = Wsh[rn*PSTR + k0+qc+4];
                bl[ni][0] = Wsl[rn*PSTR + k0+qc  ];
                bl[ni][1] = Wsl[rn*PSTR + k0+qc+4];
            }
            #pragma unroll
            for (int mi = 0; mi < 2; mi++)
                #pragma unroll
                for (int ni = 0; ni < 4; ni++) {
                    mma8(acc[mi][ni], ah[mi], bh[ni]);
                    mma8(acc[mi][ni], ah[mi], bl[ni]);
                    if (!vpath) mma8(acc[mi][ni], al[mi], bh[ni]);
                }
        }
    }
    #pragma unroll
    for (int mi = 0; mi < 2; mi++) {
        int r0 = bm + wm + 16*mi + qr;
        #pragma unroll
        for (int ni = 0; ni < 4; ni++) {
            int c0 = bn + wn + 8*ni + 2*qc;
            #pragma unroll
            for (int e = 0; e < 4; e++) {
                int m = r0 + ((e>=2) ? 8 : 0);
                int n = c0 + (e&1);
                float val = acc[mi][ni][e] + bias[n];
                if (vpath) val = __uint_as_float(f2tf(val));  // pre-tf32 for PV
                int b = m/SS, s = m%SS, h = n/DK, dk = n%DK;
                C[(((size_t)b*HH+h)*SS+s)*DK+dk] = val;
            }
        }
    }
}

// ---------------------------------------------------------------------------
// Output projection (row-major store, 3-term, single-buffer — R15 form).
// ---------------------------------------------------------------------------
__global__ __launch_bounds__(256)
void proj_out(const float* __restrict__ A, const float* __restrict__ W,
              const float* __restrict__ bias, float* __restrict__ C)
{
    extern __shared__ uint32_t ps[];
    uint32_t* Ash = ps;
    uint32_t* Asl = Ash + 128*PSTR;
    uint32_t* Wsh = Ash + 2*128*PSTR;
    uint32_t* Wsl = Wsh + 64*PSTR;

    const int bm = blockIdx.y*128, bn = blockIdx.x*64;
    const int t = threadIdx.x, wid = t>>5, lane = t&31;
    const int qr = lane>>2, qc = lane&3;
    const int wm = (wid&3)*32, wn = (wid>>2)*32;
    const int lr = t>>3, lc = (t&7)*4;

    float acc[2][4][4] = {};

    const float* Abase = A + (size_t)(bm + lr)*DD + lc;
    const float* Wbase = W + (size_t)(bn + lr)*DD + lc;

    float4 pa[4], pw[2];
    #pragma unroll
    for (int p = 0; p < 4; p++) pa[p] = *(const float4*)(Abase + (size_t)32*p*DD);
    #pragma unroll
    for (int p = 0; p < 2; p++) pw[p] = *(const float4*)(Wbase + (size_t)32*p*DD);

    for (int kc = 0; kc < DD; kc += 32) {
        __syncthreads();
        #pragma unroll
        for (int p = 0; p < 4; p++) {
            int row = lr + 32*p;
            uint4 h4, l4;
            split_tf(pa[p].x, h4.x, l4.x); split_tf(pa[p].y, h4.y, l4.y);
            split_tf(pa[p].z, h4.z, l4.z); split_tf(pa[p].w, h4.w, l4.w);
            *(uint4*)(Ash + row*PSTR + lc) = h4;
            *(uint4*)(Asl + row*PSTR + lc) = l4;
        }
        #pragma unroll
        for (int p = 0; p < 2; p++) {
            int row = lr + 32*p;
            uint4 h4, l4;
            split_tf(pw[p].x, h4.x, l4.x); split_tf(pw[p].y, h4.y, l4.y);
            split_tf(pw[p].z, h4.z, l4.z); split_tf(pw[p].w, h4.w, l4.w);
            *(uint4*)(Wsh + row*PSTR + lc) = h4;
            *(uint4*)(Wsl + row*PSTR + lc) = l4;
        }
        __syncthreads();

        if (kc + 32 < DD) {
            #pragma unroll
            for (int p = 0; p < 4; p++)
                pa[p] = *(const float4*)(Abase + (size_t)32*p*DD + kc + 32);
            #pragma unroll
            for (int p = 0; p < 2; p++)
                pw[p] = *(const float4*)(Wbase + (size_t)32*p*DD + kc + 32);
        }

        #pragma unroll
        for (int ks = 0; ks < 4; ks++) {
            int k0 = ks*8;
            uint32_t ah[2][4], al[2][4], bh[4][2], bl[4][2];
            #pragma unroll
            for (int mi = 0; mi < 2; mi++) {
                int r0 = wm + 16*mi + qr;
                ah[mi][0] = Ash[ r0   *PSTR + k0+qc  ];
                ah[mi][1] = Ash[(r0+8)*PSTR + k0+qc  ];
                ah[mi][2] = Ash[ r0   *PSTR + k0+qc+4];
                ah[mi][3] = Ash[(r0+8)*PSTR + k0+qc+4];
                al[mi][0] = Asl[ r0   *PSTR + k0+qc  ];
                al[mi][1] = Asl[(r0+8)*PSTR + k0+qc  ];
                al[mi][2] = Asl[ r0   *PSTR + k0+qc+4];
                al[mi][3] = Asl[(r0+8)*PSTR + k0+qc+4];
            }
            #pragma unroll
            for (int ni = 0; ni < 4; ni++) {
                int rn = wn + 8*ni + qr;
                bh[ni][0] = Wsh[rn*PSTR + k0+qc  ];
                bh[ni][1] = Wsh[rn*PSTR + k0+qc+4];
                bl[ni][0] = Wsl[rn*PSTR + k0+qc  ];
                bl[ni][1] = Wsl[rn*PSTR + k0+qc+4];
            }
            #pragma unroll
            for (int mi = 0; mi < 2; mi++)
                #pragma unroll
                for (int ni = 0; ni < 4; ni++) {
                    mma8(acc[mi][ni], ah[mi], bh[ni]);
                    mma8(acc[mi][ni], ah[mi], bl[ni]);
                    mma8(acc[mi][ni], al[mi], bh[ni]);
                }
        }
    }
    #pragma unroll
    for (int mi = 0; mi < 2; mi++) {
        int r0 = bm + wm + 16*mi + qr;
        #pragma unroll
        for (int ni = 0; ni < 4; ni++) {
            int c0 = bn + wn + 8*ni + 2*qc;
            #pragma unroll
            for (int e = 0; e < 4; e++) {
                int m = r0 + ((e>=2) ? 8 : 0);
                int n = c0 + (e&1);
                C[(size_t)m*DD + n] = acc[mi][ni][e] + bias[n];
            }
        }
    }
}

// ---------------------------------------------------------------------------
// Fused attention v8: in-kernel prob normalization. The loop dumps
// unnormalized exp; at block end (inv known, block writes L2-visible after
// __syncthreads) a coalesced float4 pass rescales the block's own 32x2048
// rows in place. attn_scale kernel + stream fork deleted.
// ---------------------------------------------------------------------------
#define KVP2 72
#define PCH  132
#define QSP  68
#define ATTN_SMEM ((128*KVP2 + 32*PCH + 32*QSP + 32*8 + 32) * (int)sizeof(float))

__global__ __launch_bounds__(256, 3)
void attn_fused(const float* __restrict__ qh, const float* __restrict__ kh,
                const float* __restrict__ vh, const int* __restrict__ mask,
                float* __restrict__ attn, float* __restrict__ o,
                int write_attn)
{
    extern __shared__ float smem[];
    float*    KVs  = smem;                           // [128][KVP2]
    float*    Pch  = smem + 128*KVP2;                // [32][PCH]
    uint32_t* Qhi  = (uint32_t*)(Pch + 32*PCH);      // [32][QSP] tf32 of Q/8
    float*    red2 = (float*)(Qhi + 32*QSP);         // [32][8]
    float*    invs = red2 + 32*8;                    // [32]

    const int qt = blockIdx.x, h = blockIdx.y, b = blockIdx.z;
    const int t = threadIdx.x, w = t>>5, lane = t&31;
    const int qr = lane>>2, qc = lane&3;
    const int mh = w>>2, dw = (w>>1)&1, cw = w&1;    // PV roles

    const float* qbase = qh + (((size_t)b*HH+h)*SS + (size_t)qt*32)*DK;
    const float* kbase = kh + ((size_t)b*HH+h)*SS*DK;
    const float* vbase = vh + ((size_t)b*HH+h)*SS*DK;

    // load Q tile (32x64), pre-scaled by 1/8, tf32-hi only
    {
        int row = t>>3, col = (t&7)*8;
        #pragma unroll
        for (int u = 0; u < 2; u++) {
            float4 v4 = *(const float4*)(qbase + (size_t)row*DK + col + u*4);
            uint4 h4;
            h4.x = f2tf(0.125f*v4.x); h4.y = f2tf(0.125f*v4.y);
            h4.z = f2tf(0.125f*v4.z); h4.w = f2tf(0.125f*v4.w);
            *(uint4*)(Qhi + row*QSP + col + u*4) = h4;
        }
    }

    float s00 = 0.f, s01 = 0.f, s10 = 0.f, s11 = 0.f;   // row sums [mt][half]
    float oacc[4][4] = {};

    const int ldr = t>>4, ldc = (t&15)*4;   // K/V tile loader coords

    for (int kb = 0; kb < SS/128; kb++) {
        __syncthreads();   // prev chunk PV reads of KVs/Pch done (also Q init)
        #pragma unroll
        for (int p = 0; p < 8; p++)
            cpa16(&KVs[(ldr+16*p)*KVP2 + ldc],
                  kbase + (size_t)(kb*128 + ldr + 16*p)*DK + ldc);
        asm volatile("cp.async.commit_group;");
        asm volatile("cp.async.wait_group 0;");
        __syncthreads();

        // ---- scores: qh*(kh + kl), warp w cols [16w,+16), both M-tiles ----
        float acc[2][2][4] = {};
        #pragma unroll
        for (int ks = 0; ks < 8; ks++) {
            int k0 = ks*8;
            uint32_t kh_[2][2], kl_[2][2];
            #pragma unroll
            for (int ni = 0; ni < 2; ni++) {
                int rn = w*16 + 8*ni + qr;
                split_tf(KVs[rn*KVP2 + k0+qc  ], kh_[ni][0], kl_[ni][0]);
                split_tf(KVs[rn*KVP2 + k0+qc+4], kh_[ni][1], kl_[ni][1]);
            }
            #pragma unroll
            for (int mt = 0; mt < 2; mt++) {
                uint32_t qh4[4];
                qh4[0] = Qhi[(mt*16+qr  )*QSP + k0+qc  ];
                qh4[1] = Qhi[(mt*16+qr+8)*QSP + k0+qc  ];
                qh4[2] = Qhi[(mt*16+qr  )*QSP + k0+qc+4];
                qh4[3] = Qhi[(mt*16+qr+8)*QSP + k0+qc+4];
                #pragma unroll
                for (int ni = 0; ni < 2; ni++) {
                    mma8(acc[mt][ni], qh4, kh_[ni]);
                    mma8(acc[mt][ni], qh4, kl_[ni]);
                }
            }
        }
        __syncthreads();   // K fully consumed -> KVs free for V

        // ---- issue V cp.async now; latency hides behind exp/P-store/dump ----
        #pragma unroll
        for (int p = 0; p < 8; p++)
            cpa16(&KVs[(ldr+16*p)*KVP2 + ldc],
                  vbase + (size_t)(kb*128 + ldr + 16*p)*DK + ldc);
        asm volatile("cp.async.commit_group;");

        // ---- mask/exp (3/8 MUFU, 5/8 poly), store P, dump probs ----
        #pragma unroll
        for (int mt = 0; mt < 2; mt++) {
            #pragma unroll
            for (int ni = 0; ni < 2; ni++) {
                int g = mt*2 + ni;
                int gl = w*16 + 8*ni + 2*qc;
                int gc = kb*128 + gl;
                int m0 = mask[(size_t)b*SS + gc];
                int m1 = mask[(size_t)b*SS + gc + 1];
                float v0 = m0 ? acc[mt][ni][0] : -80.f;
                float v1 = m1 ? acc[mt][ni][1] : -80.f;
                float v2 = m0 ? acc[mt][ni][2] : -80.f;
                float v3 = m1 ? acc[mt][ni][3] : -80.f;
                float e0 = __expf(v0);                       // MUFU always
                float e1 = exp_poly(v1);
                float e2 = (g & 1) ? __expf(v2)              // MUFU in odd groups
                                   : exp_poly(v2);
                float e3 = exp_poly(v3);
                if (mt == 0) { s00 += e0 + e1; s01 += e2 + e3; }
                else         { s10 += e0 + e1; s11 += e2 + e3; }
                Pch[(mt*16+qr  )*PCH + gl  ] = e0;
                Pch[(mt*16+qr  )*PCH + gl+1] = e1;
                Pch[(mt*16+qr+8)*PCH + gl  ] = e2;
                Pch[(mt*16+qr+8)*PCH + gl+1] = e3;
                if (write_attn) {
                    size_t ar0 = (((size_t)b*HH + h)*SS + (size_t)(qt*32 + mt*16 + qr))*SS + gc;
                    size_t ar1 = ar0 + (size_t)8*SS;
                    float2 p0 = make_float2(e0, e1);
                    float2 p1 = make_float2(e2, e3);
                    *(float2*)(attn + ar0) = p0;
                    *(float2*)(attn + ar1) = p1;
                }
            }
        }
        asm volatile("cp.async.wait_group 0;");
        __syncthreads();   // P ready + V visible

        // ---- PV (V pre-tf32): rows [16mh,+16), dk [32dw,+32), contr [64cw,+64) ----
        #pragma unroll
        for (int ks = 0; ks < 8; ks++) {
            int j8 = cw*64 + ks*8;
            uint32_t ph[4];
            ph[0] = f2tf(Pch[(mh*16+qr  )*PCH + j8+qc  ]);
            ph[1] = f2tf(Pch[(mh*16+qr+8)*PCH + j8+qc  ]);
            ph[2] = f2tf(Pch[(mh*16+qr  )*PCH + j8+qc+4]);
            ph[3] = f2tf(Pch[(mh*16+qr+8)*PCH + j8+qc+4]);
            #pragma unroll
            for (int ni = 0; ni < 4; ni++) {
                int n0 = dw*32 + ni*8 + qr;
                uint32_t vh2[2];
                vh2[0] = __float_as_uint(KVs[(j8+qc  )*KVP2 + n0]);
                vh2[1] = __float_as_uint(KVs[(j8+qc+4)*KVP2 + n0]);
                mma8(oacc[ni], ph, vh2);
            }
        }
    }

    // ---- row-sum reduction -> invs ----
    s00 += __shfl_xor_sync(0xffffffffu, s00, 1);
    s00 += __shfl_xor_sync(0xffffffffu, s00, 2);
    s01 += __shfl_xor_sync(0xffffffffu, s01, 1);
    s01 += __shfl_xor_sync(0xffffffffu, s01, 2);
    s10 += __shfl_xor_sync(0xffffffffu, s10, 1);
    s10 += __shfl_xor_sync(0xffffffffu, s10, 2);
    s11 += __shfl_xor_sync(0xffffffffu, s11, 1);
    s11 += __shfl_xor_sync(0xffffffffu, s11, 2);
    if (qc == 0) {
        red2[( qr   )*8 + w] = s00;
        red2[( qr+8 )*8 + w] = s01;
        red2[(16+qr  )*8 + w] = s10;
        red2[(16+qr+8)*8 + w] = s11;
    }
    __syncthreads();   // also: all PV reads of KVs done -> safe to reuse
    if (t < 32) {
        float s = 0.f;
        #pragma unroll
        for (int ww = 0; ww < 8; ww++) s += red2[t*8 + ww];
        invs[t] = 1.f / s;
    }

    // ---- O partial reduction through smem: redO[2cw][32][68] ----
    float* redO = KVs;
    #pragma unroll
    for (int ni = 0; ni < 4; ni++) {
        int c0 = dw*32 + ni*8 + 2*qc;
        redO[cw*32*68 + (mh*16+qr  )*68 + c0  ] = oacc[ni][0];
        redO[cw*32*68 + (mh*16+qr  )*68 + c0+1] = oacc[ni][1];
        redO[cw*32*68 + (mh*16+qr+8)*68 + c0  ] = oacc[ni][2];
        redO[cw*32*68 + (mh*16+qr+8)*68 + c0+1] = oacc[ni][3];
    }
    __syncthreads();   // invs + redO visible; block's global prob writes visible
    {
        int row = t>>3, cb = (t&7)*8;
        float iv = invs[row];
        size_t orow = (size_t)b*SS + qt*32 + row;
        #pragma unroll
        for (int j = 0; j < 8; j++) {
            int col = cb + j;
            float s = redO[row*68 + col] + redO[32*68 + row*68 + col];
            o[orow*DD + h*DK + col] = s * iv;
        }
    }

    // ---- in-place normalization of this block's 32x2048 prob rows ----
    if (write_attn) {
        float4* abase4 = (float4*)(attn + (((size_t)b*HH + h)*SS + (size_t)qt*32)*SS);
        // 32 rows x 512 float4 = 16384 float4; 256 threads -> 64 iters, coalesced
        #pragma unroll 4
        for (int it = 0; it < 64; it++) {
            int idx = it*256 + t;
            int row = idx >> 9;            // 512 float4 per row
            float iv = invs[row];
            float4 v = abase4[idx];
            v.x *= iv; v.y *= iv; v.z *= iv; v.w *= iv;
            abase4[idx] = v;
        }
    }
}

// ---------------------------------------------------------------------------
extern "C" void kernel_launch(void* const* d_in, const int* in_sizes, int n_in,
                              void* d_out, int out_size)
{
    const float* q    = (const float*)d_in[0];
    const float* k    = (const float*)d_in[1];
    const float* v    = (const float*)d_in[2];
    const int*   mask = (const int*)  d_in[3];
    const float* wq_w = (const float*)d_in[4];
    const float* wq_b = (const float*)d_in[5];
    const float* wk_w = (const float*)d_in[6];
    const float* wk_b = (const float*)d_in[7];
    const float* wv_w = (const float*)d_in[8];
    const float* wv_b = (const float*)d_in[9];
    const float* wo_w = (const float*)d_in[10];
    const float* wo_b = (const float*)d_in[11];

    float *qh_p, *kh_p, *vh_p, *o_p;
    cudaGetSymbolAddress((void**)&qh_p, g_qh);
    cudaGetSymbolAddress((void**)&kh_p, g_kh);
    cudaGetSymbolAddress((void**)&vh_p, g_vh);
    cudaGetSymbolAddress((void**)&o_p,  g_o);

    const long OUT_E  = (long)BB*SS*DD;              // 4,194,304
    const long ATTN_E = (long)BB*HH*SS*(long)SS;     // 134,217,728
    float* out_ptr  = nullptr;
    float* attn_ptr = nullptr;
    if ((long)out_size >= OUT_E + ATTN_E) {
        out_ptr  = (float*)d_out;
        attn_ptr = (float*)d_out + OUT_E;
    } else if ((long)out_size >= ATTN_E) {
        attn_ptr = (float*)d_out;
    } else {
        out_ptr  = (float*)d_out;
    }

    cudaFuncSetAttribute(proj_qkv, cudaFuncAttributeMaxDynamicSharedMemorySize, PROJ_SMEM3);
    cudaFuncSetAttribute(proj_out, cudaFuncAttributeMaxDynamicSharedMemorySize, PROJ_SMEM3);

    // fused Q/K/V projection: one launch, grid.z selects the projection
    proj_qkv<<<dim3(DD/64, MM/128, 3), 256, PROJ_SMEM3>>>(
        q, k, v, wq_w, wk_w, wv_w, wq_b, wk_b, wv_b, qh_p, kh_p, vh_p);

    cudaFuncSetAttribute(attn_fused,
                         cudaFuncAttributeMaxDynamicSharedMemorySize, ATTN_SMEM);
    attn_fused<<<dim3(SS/32, HH, BB), 256, ATTN_SMEM>>>(
        qh_p, kh_p, vh_p, mask, attn_ptr, o_p,
        attn_ptr != nullptr ? 1 : 0);

    if (out_ptr)
        proj_out<<<dim3(DD/64, MM/128), 256, PROJ_SMEM3>>>(o_p, wo_w, wo_b, out_ptr);
}